// round 1
// baseline (speedup 1.0000x reference)
#include <cuda_runtime.h>
#include <math.h>

// ---------------- constants ----------------
#define GHh 45
#define GWw 90
#define NP 4050          // tokens
#define EE 768
#define KM 23            // kept W-frequencies
#define NFREQ (GHh*KM)   // 1035
#define HID 3072
#define PKK 5120         // patch K  (20*16*16)
#define HDD 5120         // head out (16*16*20)
#define NBB 8
#define BSS 96
#define DHT_SIZE 3110400.0  // 45*90*768

// ---------------- scratch (device globals; no allocation allowed) ----------------
__device__ float g_px[(size_t)NP*PKK];     // im2col / head tokens
__device__ float g_A [NP*EE];
__device__ float g_t [NP*EE];
__device__ float g_Pr[NP*EE];
__device__ float g_Pi[NP*EE];
__device__ float g_Vr[NP*EE];
__device__ float g_Vi[NP*EE];
__device__ float g_Qr[NFREQ*EE];
__device__ float g_Qi[NFREQ*EE];
__device__ float g_a [NFREQ*EE];
__device__ float g_n [NFREQ*EE];
__device__ float g_o1k[NFREQ*EE];
__device__ float g_o1n[NFREQ*EE];
__device__ float g_s [NFREQ*EE];
__device__ float g_hbuf[(size_t)NP*HID];
// DFT tables
__device__ float g_CcosT [EE*EE];   // [kc][c] cos
__device__ float g_CnsinT[EE*EE];   // [kc][c] -sin
__device__ float g_MrT[EE*EE];      // (cos-sin)/SIZE
__device__ float g_MiT[EE*EE];      // (cos+sin)/SIZE
__device__ float g_WC[GWw*GWw];
__device__ float g_WS[GWw*GWw];
__device__ float g_HC[GHh*GHh];
__device__ float g_HS[GHh*GHh];
// per-layer prepped block weights
__device__ float g_W1p[NBB*BSS*BSS], g_W1m[NBB*BSS*BSS];
__device__ float g_W2p[NBB*BSS*BSS], g_W2m[NBB*BSS*BSS];
__device__ float g_W2a[NBB*BSS*BSS], g_W2b[NBB*BSS*BSS];
__device__ float g_bs [NBB*BSS];

// ---------------- table init ----------------
__global__ void tab768() {
    int idx = blockIdx.x*256 + threadIdx.x;
    if (idx >= EE*EE) return;
    int kc = idx / EE, c = idx % EE;
    long long m = ((long long)kc * c) % EE;
    double a = 2.0 * (double)m / (double)EE;  // angle / pi
    double cs = cospi(a), sn = sinpi(a);
    g_CcosT[idx]  = (float)cs;
    g_CnsinT[idx] = (float)(-sn);
    g_MrT[idx] = (float)((cs - sn) / DHT_SIZE);
    g_MiT[idx] = (float)((cs + sn) / DHT_SIZE);
}
__global__ void tab90() {
    int idx = blockIdx.x*256 + threadIdx.x;
    if (idx >= GWw*GWw) return;
    int a = idx / GWw, b = idx % GWw;
    long long m = ((long long)a * b) % GWw;
    double ang = 2.0 * (double)m / (double)GWw;
    g_WC[idx] = (float)cospi(ang);
    g_WS[idx] = (float)sinpi(ang);
}
__global__ void tab45() {
    int idx = blockIdx.x*256 + threadIdx.x;
    if (idx >= GHh*GHh) return;
    int a = idx / GHh, b = idx % GHh;
    long long m = ((long long)a * b) % GHh;
    double ang = 2.0 * (double)m / (double)GHh;
    g_HC[idx] = (float)cospi(ang);
    g_HS[idx] = (float)sinpi(ang);
}

// ---------------- generic SGEMM:  C[m,n] = sum_k A[m,k] * B[n,k]  ----------------
// MODE: 0 = store, 1 = store+bias[n], 2 = store+bias[n]+GELU(exact), 3 = accumulate (C += ...)
template<int MODE>
__global__ void __launch_bounds__(256)
sgemm_nt(const float* __restrict__ A, const float* __restrict__ B,
         float* __restrict__ C, int M, int N, int K,
         const float* __restrict__ bias)
{
    __shared__ float As[8][128];
    __shared__ float Bs[8][128];
    int t  = threadIdx.x;
    int bm = blockIdx.y * 128;
    int bn = blockIdx.x * 128;
    int lrow = t >> 1;
    int lcol = (t & 1) * 4;
    int tx = t & 15, ty = t >> 4;

    float acc[8][8];
    #pragma unroll
    for (int i = 0; i < 8; i++)
        #pragma unroll
        for (int j = 0; j < 8; j++) acc[i][j] = 0.f;

    const float* Aptr = A + (size_t)(bm + lrow) * K + lcol;
    const float* Bptr = B + (size_t)(bn + lrow) * K + lcol;
    bool arow_ok = (bm + lrow) < M;

    for (int k0 = 0; k0 < K; k0 += 8) {
        float4 av = arow_ok ? *(const float4*)(Aptr + k0) : make_float4(0.f,0.f,0.f,0.f);
        float4 bv = *(const float4*)(Bptr + k0);
        As[lcol+0][lrow] = av.x; As[lcol+1][lrow] = av.y;
        As[lcol+2][lrow] = av.z; As[lcol+3][lrow] = av.w;
        Bs[lcol+0][lrow] = bv.x; Bs[lcol+1][lrow] = bv.y;
        Bs[lcol+2][lrow] = bv.z; Bs[lcol+3][lrow] = bv.w;
        __syncthreads();
        #pragma unroll
        for (int kk = 0; kk < 8; kk++) {
            float af[8], bf[8];
            #pragma unroll
            for (int i = 0; i < 8; i++) af[i] = As[kk][ty*8+i];
            #pragma unroll
            for (int j = 0; j < 8; j++) bf[j] = Bs[kk][tx*8+j];
            #pragma unroll
            for (int i = 0; i < 8; i++)
                #pragma unroll
                for (int j = 0; j < 8; j++) acc[i][j] += af[i]*bf[j];
        }
        __syncthreads();
    }

    #pragma unroll
    for (int i = 0; i < 8; i++) {
        int m = bm + ty*8 + i;
        if (m >= M) continue;
        #pragma unroll
        for (int j = 0; j < 8; j++) {
            int n = bn + tx*8 + j;
            float v = acc[i][j];
            if (MODE == 1 || MODE == 2) v += bias[n];
            if (MODE == 2) v = 0.5f*v*(1.0f + erff(v*0.7071067811865475f));
            if (MODE == 3) C[(size_t)m*N + n] += v;
            else           C[(size_t)m*N + n]  = v;
        }
    }
}

// ---------------- LayerNorm (per token over E=768) ----------------
__global__ void ln_kernel(const float* __restrict__ in, float* __restrict__ out,
                          const float* __restrict__ w, const float* __restrict__ b)
{
    int tok = blockIdx.x;
    int tid = threadIdx.x;                 // 256 threads
    const float* row = in + (size_t)tok*EE;
    float x0 = row[tid], x1 = row[tid+256], x2 = row[tid+512];
    float s  = x0+x1+x2;
    float sq = x0*x0 + x1*x1 + x2*x2;
    #pragma unroll
    for (int o = 16; o > 0; o >>= 1) {
        s  += __shfl_down_sync(0xffffffffu, s,  o);
        sq += __shfl_down_sync(0xffffffffu, sq, o);
    }
    __shared__ float ss[8], ssq[8];
    int warp = tid >> 5, lane = tid & 31;
    if (lane == 0) { ss[warp] = s; ssq[warp] = sq; }
    __syncthreads();
    if (tid == 0) {
        float ts = 0.f, tq = 0.f;
        #pragma unroll
        for (int i = 0; i < 8; i++) { ts += ss[i]; tq += ssq[i]; }
        float m = ts * (1.0f/768.0f);
        float v = tq * (1.0f/768.0f) - m*m;
        ss[0] = m; ssq[0] = rsqrtf(v + 1e-5f);
    }
    __syncthreads();
    float m = ss[0], inv = ssq[0];
    float* orow = out + (size_t)tok*EE;
    orow[tid]     = (x0-m)*inv*w[tid]     + b[tid];
    orow[tid+256] = (x1-m)*inv*w[tid+256] + b[tid+256];
    orow[tid+512] = (x2-m)*inv*w[tid+512] + b[tid+512];
}

// ---------------- DHT stage kernels ----------------
// forward W-stage: P(45,90,768) complex -> Q(45,23,768) complex
__global__ void k_wfwd() {
    extern __shared__ float sm[];
    float* sr = sm; float* si = sm + 90*128;
    int c0 = blockIdx.x*128, h = blockIdx.y, tid = threadIdx.x;
    for (int w = 0; w < 90; w++) {
        sr[w*128+tid] = g_Pr[(h*90+w)*EE + c0+tid];
        si[w*128+tid] = g_Pi[(h*90+w)*EE + c0+tid];
    }
    __syncthreads();
    for (int kw = 0; kw < 23; kw++) {
        float ar = 0.f, ai = 0.f;
        #pragma unroll 6
        for (int w = 0; w < 90; w++) {
            float cw = g_WC[kw*90+w], sw = g_WS[kw*90+w];
            float pr = sr[w*128+tid], pi = si[w*128+tid];
            ar += pr*cw + pi*sw;
            ai += pi*cw - pr*sw;
        }
        g_Qr[(h*23+kw)*EE + c0+tid] = ar;
        g_Qi[(h*23+kw)*EE + c0+tid] = ai;
    }
}
// forward H-stage with fused Re+Im: Q(45,23,768) complex -> a(45,23,768) real
__global__ void k_hfwd() {
    extern __shared__ float sm[];
    float* sr = sm; float* si = sm + 45*128;
    int c0 = blockIdx.x*128, kw = blockIdx.y, tid = threadIdx.x;
    for (int h = 0; h < 45; h++) {
        sr[h*128+tid] = g_Qr[(h*23+kw)*EE + c0+tid];
        si[h*128+tid] = g_Qi[(h*23+kw)*EE + c0+tid];
    }
    __syncthreads();
    for (int kh = 0; kh < 45; kh++) {
        float acc = 0.f;
        #pragma unroll 5
        for (int h = 0; h < 45; h++) {
            float ch = g_HC[kh*45+h], sh = g_HS[kh*45+h];
            acc += sr[h*128+tid]*(ch - sh) + si[h*128+tid]*(ch + sh);
        }
        g_a[(kh*23+kw)*EE + c0+tid] = acc;
    }
}
// inverse W-stage: y(45,23,768) real -> U(45,90,768) complex (into g_Pr/g_Pi)
__global__ void k_winv() {
    extern __shared__ float sm[];
    int c0 = blockIdx.x*128, h = blockIdx.y, tid = threadIdx.x;
    for (int w = 0; w < 23; w++) sm[w*128+tid] = g_s[(h*23+w)*EE + c0+tid];
    __syncthreads();
    for (int kw = 0; kw < 90; kw++) {
        float ar = 0.f, ai = 0.f;
        #pragma unroll
        for (int w = 0; w < 23; w++) {
            float v = sm[w*128+tid];
            ar += v * g_WC[kw*90+w];
            ai -= v * g_WS[kw*90+w];
        }
        g_Pr[(h*90+kw)*EE + c0+tid] = ar;
        g_Pi[(h*90+kw)*EE + c0+tid] = ai;
    }
}
// inverse H-stage: U(45,90,768) complex -> V(45,90,768) complex
__global__ void k_hinv() {
    extern __shared__ float sm[];
    float* sr = sm; float* si = sm + 45*128;
    int c0 = blockIdx.x*128, kw = blockIdx.y, tid = threadIdx.x;
    for (int h = 0; h < 45; h++) {
        sr[h*128+tid] = g_Pr[(h*90+kw)*EE + c0+tid];
        si[h*128+tid] = g_Pi[(h*90+kw)*EE + c0+tid];
    }
    __syncthreads();
    for (int kh = 0; kh < 45; kh++) {
        float vr = 0.f, vi = 0.f;
        #pragma unroll 5
        for (int h = 0; h < 45; h++) {
            float ch = g_HC[kh*45+h], sh = g_HS[kh*45+h];
            float ur = sr[h*128+tid], ui = si[h*128+tid];
            vr += ur*ch + ui*sh;
            vi += ui*ch - ur*sh;
        }
        g_Vr[(kh*90+kw)*EE + c0+tid] = vr;
        g_Vi[(kh*90+kw)*EE + c0+tid] = vi;
    }
}

// ---------------- misc elementwise ----------------
__global__ void gather_n(const float* __restrict__ t) {
    int idx = blockIdx.x*256 + threadIdx.x;
    if (idx >= NFREQ*EE) return;
    int c = idx % EE; int p = idx / EE;
    int w = p % 23, h = p / 23;
    int sh = (45 - h) % 45;
    int sw = (90 - w) % 90;
    g_n[idx] = t[(size_t)(sh*90 + sw)*EE + c];
}
__global__ void soft_thresh() {
    int idx = blockIdx.x*256 + threadIdx.x;
    if (idx >= NFREQ*EE) return;
    float v = g_s[idx];
    float a = fabsf(v) - 0.01f;
    g_s[idx] = (a > 0.f) ? copysignf(a, v) : 0.f;
}
__global__ void add3_kernel() {   // A = z(g_Pr) + t + A
    int idx = blockIdx.x*256 + threadIdx.x;
    if (idx >= NP*EE) return;
    g_A[idx] = g_Pr[idx] + g_t[idx] + g_A[idx];
}
__global__ void add2_kernel() {   // A += g_Pr
    int idx = blockIdx.x*256 + threadIdx.x;
    if (idx >= NP*EE) return;
    g_A[idx] += g_Pr[idx];
}
__global__ void addpos_kernel(const float* __restrict__ pos) {
    int idx = blockIdx.x*256 + threadIdx.x;
    if (idx >= NP*EE) return;
    g_A[idx] += pos[idx];
}
__global__ void im2col_kernel(const float* __restrict__ x) {
    int idx = blockIdx.x*256 + threadIdx.x;
    if (idx >= NP*PKK) return;
    int p = idx / PKK, k = idx % PKK;
    int c = k >> 8, r = k & 255;
    int ph = r >> 4, pw = r & 15;
    int gh = p / 90, gw = p % 90;
    g_px[idx] = x[(size_t)c*1036800 + (size_t)(gh*16+ph)*1440 + (gw*16+pw)];
}
__global__ void scatter_out(float* __restrict__ out) {
    int idx = blockIdx.x*256 + threadIdx.x;
    if (idx >= 20736000) return;
    int oc = idx / 1036800; int r = idx % 1036800;
    int hh = r / 1440, ww = r % 1440;
    int gh = hh >> 4, ph = hh & 15, gw = ww >> 4, pw = ww & 15;
    out[idx] = g_px[(size_t)(gh*90+gw)*HDD + ph*320 + pw*20 + oc];
}

// ---------------- per-layer block-weight prep ----------------
__global__ void prep_pm(const float* __restrict__ w1l, const float* __restrict__ w2l) {
    int i = blockIdx.x*256 + threadIdx.x;
    if (i >= NBB*BSS*BSS) return;
    const int OFF = NBB*BSS*BSS;
    g_W1p[i] = 0.5f*(w1l[i] + w1l[OFF+i]);
    g_W1m[i] = 0.5f*(w1l[i] - w1l[OFF+i]);
    g_W2p[i] = 0.5f*(w2l[i] + w2l[OFF+i]);
    g_W2m[i] = 0.5f*(w2l[i] - w2l[OFF+i]);
}
__global__ void prep_ab() {
    int idx = blockIdx.x*128 + threadIdx.x;
    if (idx >= NBB*BSS*BSS) return;
    int o = idx % 96;
    int i = (idx / 96) % 96;
    int b = idx / 9216;
    const float* P = g_W2p + b*9216;
    const float* M = g_W2m + b*9216;
    float aa = g_W2p[idx];
    float bb = g_W2m[idx] + g_W2p[idx];
    #pragma unroll 8
    for (int j = 0; j < 96; j++) {
        aa += P[i*96+j] * M[j*96+o];
        bb += M[i*96+j] * M[j*96+o];
    }
    g_W2a[idx] = aa;
    g_W2b[idx] = bb;
}
__global__ void prep_bs(const float* __restrict__ b2l) {
    int idx = blockIdx.x*128 + threadIdx.x;
    if (idx >= NBB*BSS) return;
    int o = idx % 96, b = idx / 96;
    float v = b2l[idx] + b2l[NBB*BSS + idx];
    #pragma unroll 8
    for (int j = 0; j < 96; j++) v += b2l[b*96+j] * g_W2m[(b*96+j)*96+o];
    g_bs[idx] = v;
}

// ---------------- block mixing ----------------
// o1k = relu(a*W1p + n*W1m + b1[0]);  o1n = relu(n*W1p + a*W1m + b1[1])
__global__ void k_mix1(const float* __restrict__ b1l) {
    extern __shared__ float sm[];
    float* sWp = sm;
    float* sWm = sm + 9216;
    float* sX  = sm + 18432;          // 15*96
    float* sY  = sX + 1440;
    int b = blockIdx.x, tile = blockIdx.y, o = threadIdx.x;
    for (int i = o; i < 9216; i += 96) { sWp[i] = g_W1p[b*9216+i]; sWm[i] = g_W1m[b*9216+i]; }
    int p0 = tile * 15;
    for (int pp = 0; pp < 15; pp++) {
        sX[pp*96+o] = g_a[(size_t)(p0+pp)*EE + b*96 + o];
        sY[pp*96+o] = g_n[(size_t)(p0+pp)*EE + b*96 + o];
    }
    __syncthreads();
    float bk = b1l[b*96+o], bn = b1l[NBB*BSS + b*96+o];
    for (int pp = 0; pp < 15; pp++) {
        float ak = bk, an = bn;
        #pragma unroll 8
        for (int i = 0; i < 96; i++) {
            float xv = sX[pp*96+i], yv = sY[pp*96+i];
            float wp = sWp[i*96+o], wm = sWm[i*96+o];
            ak += xv*wp + yv*wm;
            an += yv*wp + xv*wm;
        }
        g_o1k[(size_t)(p0+pp)*EE + b*96 + o] = fmaxf(ak, 0.f);
        g_o1n[(size_t)(p0+pp)*EE + b*96 + o] = fmaxf(an, 0.f);
    }
}
// s = o1k*W2a + o1n*W2b + bs
__global__ void k_mix2() {
    extern __shared__ float sm[];
    float* sWa = sm;
    float* sWb = sm + 9216;
    float* sX  = sm + 18432;
    float* sY  = sX + 1440;
    int b = blockIdx.x, tile = blockIdx.y, o = threadIdx.x;
    for (int i = o; i < 9216; i += 96) { sWa[i] = g_W2a[b*9216+i]; sWb[i] = g_W2b[b*9216+i]; }
    int p0 = tile * 15;
    for (int pp = 0; pp < 15; pp++) {
        sX[pp*96+o] = g_o1k[(size_t)(p0+pp)*EE + b*96 + o];
        sY[pp*96+o] = g_o1n[(size_t)(p0+pp)*EE + b*96 + o];
    }
    __syncthreads();
    float bsv = g_bs[b*96+o];
    for (int pp = 0; pp < 15; pp++) {
        float acc = bsv;
        #pragma unroll 8
        for (int i = 0; i < 96; i++) {
            acc += sX[pp*96+i]*sWa[i*96+o] + sY[pp*96+i]*sWb[i*96+o];
        }
        g_s[(size_t)(p0+pp)*EE + b*96 + o] = acc;
    }
}

// ---------------- host orchestration ----------------
extern "C" void kernel_launch(void* const* d_in, const int* in_sizes, int n_in,
                              void* d_out, int out_size)
{
    const float* x        = (const float*)d_in[0];
    const float* patch_w  = (const float*)d_in[1];
    const float* patch_b  = (const float*)d_in[2];
    const float* pos      = (const float*)d_in[3];
    const float* norm1_w  = (const float*)d_in[4];
    const float* norm1_b  = (const float*)d_in[5];
    const float* w1       = (const float*)d_in[6];
    const float* b1       = (const float*)d_in[7];
    const float* w2       = (const float*)d_in[8];
    const float* b2       = (const float*)d_in[9];
    const float* norm2_w  = (const float*)d_in[10];
    const float* norm2_b  = (const float*)d_in[11];
    const float* fc1_w    = (const float*)d_in[12];
    const float* fc1_b    = (const float*)d_in[13];
    const float* fc2_w    = (const float*)d_in[14];
    const float* fc2_b    = (const float*)d_in[15];
    const float* head_w   = (const float*)d_in[16];
    float* out = (float*)d_out;

    float *pPX,*pA,*pT,*pPr,*pPi,*pVr,*pVi,*pH,*pCcos,*pCnsin,*pMr,*pMi;
    cudaGetSymbolAddress((void**)&pPX,   g_px);
    cudaGetSymbolAddress((void**)&pA,    g_A);
    cudaGetSymbolAddress((void**)&pT,    g_t);
    cudaGetSymbolAddress((void**)&pPr,   g_Pr);
    cudaGetSymbolAddress((void**)&pPi,   g_Pi);
    cudaGetSymbolAddress((void**)&pVr,   g_Vr);
    cudaGetSymbolAddress((void**)&pVi,   g_Vi);
    cudaGetSymbolAddress((void**)&pH,    g_hbuf);
    cudaGetSymbolAddress((void**)&pCcos, g_CcosT);
    cudaGetSymbolAddress((void**)&pCnsin,g_CnsinT);
    cudaGetSymbolAddress((void**)&pMr,   g_MrT);
    cudaGetSymbolAddress((void**)&pMi,   g_MiT);

    cudaFuncSetAttribute(k_wfwd, cudaFuncAttributeMaxDynamicSharedMemorySize, 2*90*128*4);
    cudaFuncSetAttribute(k_hfwd, cudaFuncAttributeMaxDynamicSharedMemorySize, 2*45*128*4);
    cudaFuncSetAttribute(k_hinv, cudaFuncAttributeMaxDynamicSharedMemorySize, 2*45*128*4);
    cudaFuncSetAttribute(k_mix1, cudaFuncAttributeMaxDynamicSharedMemorySize, 85248);
    cudaFuncSetAttribute(k_mix2, cudaFuncAttributeMaxDynamicSharedMemorySize, 85248);

    // DFT tables
    tab768<<<(EE*EE + 255)/256, 256>>>();
    tab90 <<<(GWw*GWw + 255)/256, 256>>>();
    tab45 <<<(GHh*GHh + 255)/256, 256>>>();

    // patch embed
    im2col_kernel<<<(NP*PKK + 255)/256, 256>>>(x);
    sgemm_nt<1><<<dim3(EE/128, (NP+127)/128), 256>>>(pPX, patch_w, pA, NP, EE, PKK, patch_b);
    addpos_kernel<<<(NP*EE + 255)/256, 256>>>(pos);

    const int EWGRID = (NP*EE + 255)/256;
    const int FGRID  = (NFREQ*EE + 255)/256;

    for (int l = 0; l < 12; l++) {
        // ---- AFNO half ----
        ln_kernel<<<NP, 256>>>(pA, pT, norm1_w + l*EE, norm1_b + l*EE);
        // forward DHT: C stage
        sgemm_nt<0><<<dim3(EE/128, (NP+127)/128), 256>>>(pT, pCcos,  pPr, NP, EE, EE, nullptr);
        sgemm_nt<0><<<dim3(EE/128, (NP+127)/128), 256>>>(pT, pCnsin, pPi, NP, EE, EE, nullptr);
        k_wfwd<<<dim3(6, 45), 128, 2*90*128*4>>>();
        k_hfwd<<<dim3(6, 23), 128, 2*45*128*4>>>();
        gather_n<<<FGRID, 256>>>(pT);
        // prep mixed block weights
        prep_pm<<<(NBB*BSS*BSS + 255)/256, 256>>>(w1 + (size_t)l*2*NBB*BSS*BSS, w2 + (size_t)l*2*NBB*BSS*BSS);
        prep_ab<<<(NBB*BSS*BSS + 127)/128, 128>>>();
        prep_bs<<<(NBB*BSS + 127)/128, 128>>>(b2 + (size_t)l*2*NBB*BSS);
        // mixing
        k_mix1<<<dim3(8, 69), 96, 85248>>>(b1 + (size_t)l*2*NBB*BSS);
        k_mix2<<<dim3(8, 69), 96, 85248>>>();
        soft_thresh<<<FGRID, 256>>>();
        // inverse DHT
        k_winv<<<dim3(6, 45), 128, 23*128*4>>>();
        k_hinv<<<dim3(6, 90), 128, 2*45*128*4>>>();
        sgemm_nt<0><<<dim3(EE/128, (NP+127)/128), 256>>>(pVr, pMr, pPr, NP, EE, EE, nullptr);
        sgemm_nt<3><<<dim3(EE/128, (NP+127)/128), 256>>>(pVi, pMi, pPr, NP, EE, EE, nullptr);
        add3_kernel<<<EWGRID, 256>>>();   // A = dht + ln_out + A

        // ---- MLP half ----
        ln_kernel<<<NP, 256>>>(pA, pT, norm2_w + l*EE, norm2_b + l*EE);
        sgemm_nt<2><<<dim3(HID/128, (NP+127)/128), 256>>>(pT, fc1_w + (size_t)l*HID*EE, pH, NP, HID, EE,  fc1_b + l*HID);
        sgemm_nt<1><<<dim3(EE/128,  (NP+127)/128), 256>>>(pH, fc2_w + (size_t)l*EE*HID, pPr, NP, EE, HID, fc2_b + l*EE);
        add2_kernel<<<EWGRID, 256>>>();
    }

    // head
    sgemm_nt<0><<<dim3(HDD/128, (NP+127)/128), 256>>>(pA, head_w, pPX, NP, HDD, EE, nullptr);
    scatter_out<<<(20736000 + 255)/256, 256>>>(out);
}

// round 3
// speedup vs baseline: 1.2815x; 1.2815x over previous
#include <cuda_runtime.h>
#include <math.h>

// ---------------- constants ----------------
#define GHh 45
#define GWw 90
#define NP 4050          // tokens
#define EE 768
#define KM 23            // kept W-frequencies
#define NFREQ (GHh*KM)   // 1035
#define HID 3072
#define PKK 5120         // patch K  (20*16*16)
#define HDD 5120         // head out (16*16*20)
#define NBB 8
#define BSS 96
#define DHT_SIZE 3110400.0  // 45*90*768

// ---------------- scratch (device globals; no allocation allowed) ----------------
__device__ float g_px[(size_t)NP*PKK];     // im2col / head tokens
__device__ float g_A [NP*EE];
__device__ float g_t [NP*EE];
__device__ float g_Pr[NP*EE];
__device__ float g_Pi[NP*EE];
__device__ float g_Vr[NP*EE];
__device__ float g_Vi[NP*EE];
__device__ float g_Qr[NFREQ*EE];
__device__ float g_Qi[NFREQ*EE];
__device__ float g_a [NFREQ*EE];
__device__ float g_n [NFREQ*EE];
__device__ float g_o1k[NFREQ*EE];
__device__ float g_o1n[NFREQ*EE];
__device__ float g_s [NFREQ*EE];
__device__ float g_hbuf[(size_t)NP*HID];
// DFT tables
__device__ float g_CcosT [EE*EE];   // [kc][c] cos
__device__ float g_CnsinT[EE*EE];   // [kc][c] -sin
__device__ float g_MrT[EE*EE];      // (cos-sin)/SIZE
__device__ float g_MiT[EE*EE];      // (cos+sin)/SIZE
__device__ float g_WC[GWw*GWw];
__device__ float g_WS[GWw*GWw];
__device__ float g_HC[GHh*GHh];
__device__ float g_HS[GHh*GHh];
// per-layer prepped block weights
__device__ float g_W1p[NBB*BSS*BSS], g_W1m[NBB*BSS*BSS];
__device__ float g_W2p[NBB*BSS*BSS], g_W2m[NBB*BSS*BSS];
__device__ float g_W2a[NBB*BSS*BSS], g_W2b[NBB*BSS*BSS];
__device__ float g_bs [NBB*BSS];

// ---------------- table init ----------------
__global__ void tab768() {
    int idx = blockIdx.x*256 + threadIdx.x;
    if (idx >= EE*EE) return;
    int kc = idx / EE, c = idx % EE;
    long long m = ((long long)kc * c) % EE;
    double a = 2.0 * (double)m / (double)EE;  // angle / pi
    double cs = cospi(a), sn = sinpi(a);
    g_CcosT[idx]  = (float)cs;
    g_CnsinT[idx] = (float)(-sn);
    g_MrT[idx] = (float)((cs - sn) / DHT_SIZE);
    g_MiT[idx] = (float)((cs + sn) / DHT_SIZE);
}
__global__ void tab90() {
    int idx = blockIdx.x*256 + threadIdx.x;
    if (idx >= GWw*GWw) return;
    int a = idx / GWw, b = idx % GWw;
    long long m = ((long long)a * b) % GWw;
    double ang = 2.0 * (double)m / (double)GWw;
    g_WC[idx] = (float)cospi(ang);
    g_WS[idx] = (float)sinpi(ang);
}
__global__ void tab45() {
    int idx = blockIdx.x*256 + threadIdx.x;
    if (idx >= GHh*GHh) return;
    int a = idx / GHh, b = idx % GHh;
    long long m = ((long long)a * b) % GHh;
    double ang = 2.0 * (double)m / (double)GHh;
    g_HC[idx] = (float)cospi(ang);
    g_HS[idx] = (float)sinpi(ang);
}

// ---------------- TF32x3 tensor-core GEMM:  C[m,n] = sum_k A[m,k] * B[n,k] --------
// MODE: 0 = store, 1 = store+bias[n], 2 = store+bias[n]+GELU(exact), 3 = accumulate
__device__ __forceinline__ unsigned f2tf32(float x) {
    unsigned r;
    asm("cvt.rna.tf32.f32 %0, %1;" : "=r"(r) : "f"(x));
    return r;
}
__device__ __forceinline__ void mma_tf32(float* c, const unsigned* a, const unsigned* b) {
    asm volatile("mma.sync.aligned.m16n8k8.row.col.f32.tf32.tf32.f32 "
        "{%0,%1,%2,%3}, {%4,%5,%6,%7}, {%8,%9}, {%0,%1,%2,%3};"
        : "+f"(c[0]), "+f"(c[1]), "+f"(c[2]), "+f"(c[3])
        : "r"(a[0]), "r"(a[1]), "r"(a[2]), "r"(a[3]), "r"(b[0]), "r"(b[1]));
}

#define SMP 20   // smem row stride in floats (80B: float4-aligned, bank-conflict-free)

template<int MODE>
__global__ void __launch_bounds__(256)
tgemm_nt(const float* __restrict__ A, const float* __restrict__ B,
         float* __restrict__ C, int M, int N, int K,
         const float* __restrict__ bias)
{
    // block tile 128x128, K-chunk 16, double-buffered smem, 8 warps (2M x 4N), warp 64x32
    __shared__ float As[2][128][SMP];
    __shared__ float Bs[2][128][SMP];

    const int t    = threadIdx.x;
    const int warp = t >> 5, lane = t & 31;
    const int wm   = warp & 1;    // 0..1
    const int wn   = warp >> 1;   // 0..3
    const int bm   = blockIdx.y * 128;
    const int bn   = blockIdx.x * 128;

    const int grp = lane >> 2;    // 0..7
    const int tig = lane & 3;     // 0..3

    float acc[4][4][4];
    #pragma unroll
    for (int i = 0; i < 4; i++)
        #pragma unroll
        for (int j = 0; j < 4; j++)
            #pragma unroll
            for (int q = 0; q < 4; q++) acc[i][j][q] = 0.f;

    // loader mapping: 256 threads, 128 rows x 16 cols of floats, float4 per thread, 2 row-halves
    const int lr = t >> 2;          // 0..63
    const int lc = (t & 3) * 4;     // 0,4,8,12
    const bool a_ok0 = (bm + lr)      < M;
    const bool a_ok1 = (bm + lr + 64) < M;
    const float* Ag0 = A + (size_t)(bm + lr)      * K + lc;
    const float* Ag1 = A + (size_t)(bm + lr + 64) * K + lc;
    const float* Bg0 = B + (size_t)(bn + lr)      * K + lc;
    const float* Bg1 = B + (size_t)(bn + lr + 64) * K + lc;

    const float4 Z4 = make_float4(0.f, 0.f, 0.f, 0.f);

    // prime buffer 0
    {
        float4 a0 = a_ok0 ? *(const float4*)(Ag0) : Z4;
        float4 a1 = a_ok1 ? *(const float4*)(Ag1) : Z4;
        float4 b0v = *(const float4*)(Bg0);
        float4 b1v = *(const float4*)(Bg1);
        *(float4*)&As[0][lr][lc]      = a0;
        *(float4*)&As[0][lr + 64][lc] = a1;
        *(float4*)&Bs[0][lr][lc]      = b0v;
        *(float4*)&Bs[0][lr + 64][lc] = b1v;
    }
    __syncthreads();

    const int nch = K / 16;
    for (int ch = 0; ch < nch; ch++) {
        const int buf = ch & 1;
        const bool more = (ch + 1) < nch;
        float4 pa0, pa1, pb0, pb1;
        if (more) {
            int ko = (ch + 1) * 16;
            pa0 = a_ok0 ? *(const float4*)(Ag0 + ko) : Z4;
            pa1 = a_ok1 ? *(const float4*)(Ag1 + ko) : Z4;
            pb0 = *(const float4*)(Bg0 + ko);
            pb1 = *(const float4*)(Bg1 + ko);
        }

        #pragma unroll
        for (int slice = 0; slice < 2; slice++) {
            const int ks = slice * 8;
            unsigned ah[4][4], al[4][4], bh[4][2], bl[4][2];
            #pragma unroll
            for (int mt = 0; mt < 4; mt++) {
                int ar = wm * 64 + mt * 16 + grp;
                int ac = ks + tig;
                float v0 = As[buf][ar][ac];
                float v1 = As[buf][ar + 8][ac];
                float v2 = As[buf][ar][ac + 4];
                float v3 = As[buf][ar + 8][ac + 4];
                ah[mt][0] = f2tf32(v0); al[mt][0] = f2tf32(v0 - __uint_as_float(ah[mt][0]));
                ah[mt][1] = f2tf32(v1); al[mt][1] = f2tf32(v1 - __uint_as_float(ah[mt][1]));
                ah[mt][2] = f2tf32(v2); al[mt][2] = f2tf32(v2 - __uint_as_float(ah[mt][2]));
                ah[mt][3] = f2tf32(v3); al[mt][3] = f2tf32(v3 - __uint_as_float(ah[mt][3]));
            }
            #pragma unroll
            for (int nt = 0; nt < 4; nt++) {
                int br = wn * 32 + nt * 8 + grp;
                int bc = ks + tig;
                float u0 = Bs[buf][br][bc];
                float u1 = Bs[buf][br][bc + 4];
                bh[nt][0] = f2tf32(u0); bl[nt][0] = f2tf32(u0 - __uint_as_float(bh[nt][0]));
                bh[nt][1] = f2tf32(u1); bl[nt][1] = f2tf32(u1 - __uint_as_float(bh[nt][1]));
            }
            #pragma unroll
            for (int mt = 0; mt < 4; mt++)
                #pragma unroll
                for (int nt = 0; nt < 4; nt++)
                    mma_tf32(acc[mt][nt], ah[mt], bh[nt]);
            #pragma unroll
            for (int mt = 0; mt < 4; mt++)
                #pragma unroll
                for (int nt = 0; nt < 4; nt++)
                    mma_tf32(acc[mt][nt], ah[mt], bl[nt]);
            #pragma unroll
            for (int mt = 0; mt < 4; mt++)
                #pragma unroll
                for (int nt = 0; nt < 4; nt++)
                    mma_tf32(acc[mt][nt], al[mt], bh[nt]);
        }

        if (more) {
            const int nb = buf ^ 1;
            *(float4*)&As[nb][lr][lc]      = pa0;
            *(float4*)&As[nb][lr + 64][lc] = pa1;
            *(float4*)&Bs[nb][lr][lc]      = pb0;
            *(float4*)&Bs[nb][lr + 64][lc] = pb1;
        }
        __syncthreads();
    }

    // epilogue
    #pragma unroll
    for (int mt = 0; mt < 4; mt++) {
        int r0 = bm + wm * 64 + mt * 16 + grp;
        #pragma unroll
        for (int nt = 0; nt < 4; nt++) {
            int cn = bn + wn * 32 + nt * 8 + 2 * tig;
            #pragma unroll
            for (int q = 0; q < 4; q++) {
                int r = r0 + (q >> 1) * 8;
                int n = cn + (q & 1);
                if (r >= M) continue;
                float v = acc[mt][nt][q];
                if (MODE == 1 || MODE == 2) v += bias[n];
                if (MODE == 2) v = 0.5f * v * (1.0f + erff(v * 0.7071067811865475f));
                if (MODE == 3) C[(size_t)r * N + n] += v;
                else           C[(size_t)r * N + n]  = v;
            }
        }
    }
}

// ---------------- LayerNorm (per token over E=768) ----------------
__global__ void ln_kernel(const float* __restrict__ in, float* __restrict__ out,
                          const float* __restrict__ w, const float* __restrict__ b)
{
    int tok = blockIdx.x;
    int tid = threadIdx.x;                 // 256 threads
    const float* row = in + (size_t)tok*EE;
    float x0 = row[tid], x1 = row[tid+256], x2 = row[tid+512];
    float s  = x0+x1+x2;
    float sq = x0*x0 + x1*x1 + x2*x2;
    #pragma unroll
    for (int o = 16; o > 0; o >>= 1) {
        s  += __shfl_down_sync(0xffffffffu, s,  o);
        sq += __shfl_down_sync(0xffffffffu, sq, o);
    }
    __shared__ float ss[8], ssq[8];
    int warp = tid >> 5, lane = tid & 31;
    if (lane == 0) { ss[warp] = s; ssq[warp] = sq; }
    __syncthreads();
    if (tid == 0) {
        float ts = 0.f, tq = 0.f;
        #pragma unroll
        for (int i = 0; i < 8; i++) { ts += ss[i]; tq += ssq[i]; }
        float m = ts * (1.0f/768.0f);
        float v = tq * (1.0f/768.0f) - m*m;
        ss[0] = m; ssq[0] = rsqrtf(v + 1e-5f);
    }
    __syncthreads();
    float m = ss[0], inv = ssq[0];
    float* orow = out + (size_t)tok*EE;
    orow[tid]     = (x0-m)*inv*w[tid]     + b[tid];
    orow[tid+256] = (x1-m)*inv*w[tid+256] + b[tid+256];
    orow[tid+512] = (x2-m)*inv*w[tid+512] + b[tid+512];
}

// ---------------- DHT stage kernels ----------------
// forward W-stage: P(45,90,768) complex -> Q(45,23,768) complex
__global__ void k_wfwd() {
    extern __shared__ float sm[];
    float* sr = sm; float* si = sm + 90*128;
    int c0 = blockIdx.x*128, h = blockIdx.y, tid = threadIdx.x;
    for (int w = 0; w < 90; w++) {
        sr[w*128+tid] = g_Pr[(h*90+w)*EE + c0+tid];
        si[w*128+tid] = g_Pi[(h*90+w)*EE + c0+tid];
    }
    __syncthreads();
    for (int kw = 0; kw < 23; kw++) {
        float ar = 0.f, ai = 0.f;
        #pragma unroll 6
        for (int w = 0; w < 90; w++) {
            float cw = g_WC[kw*90+w], sw = g_WS[kw*90+w];
            float pr = sr[w*128+tid], pi = si[w*128+tid];
            ar += pr*cw + pi*sw;
            ai += pi*cw - pr*sw;
        }
        g_Qr[(h*23+kw)*EE + c0+tid] = ar;
        g_Qi[(h*23+kw)*EE + c0+tid] = ai;
    }
}
// forward H-stage with fused Re+Im: Q(45,23,768) complex -> a(45,23,768) real
__global__ void k_hfwd() {
    extern __shared__ float sm[];
    float* sr = sm; float* si = sm + 45*128;
    int c0 = blockIdx.x*128, kw = blockIdx.y, tid = threadIdx.x;
    for (int h = 0; h < 45; h++) {
        sr[h*128+tid] = g_Qr[(h*23+kw)*EE + c0+tid];
        si[h*128+tid] = g_Qi[(h*23+kw)*EE + c0+tid];
    }
    __syncthreads();
    for (int kh = 0; kh < 45; kh++) {
        float acc = 0.f;
        #pragma unroll 5
        for (int h = 0; h < 45; h++) {
            float ch = g_HC[kh*45+h], sh = g_HS[kh*45+h];
            acc += sr[h*128+tid]*(ch - sh) + si[h*128+tid]*(ch + sh);
        }
        g_a[(kh*23+kw)*EE + c0+tid] = acc;
    }
}
// inverse W-stage: y(45,23,768) real -> U(45,90,768) complex (into g_Pr/g_Pi)
__global__ void k_winv() {
    extern __shared__ float sm[];
    int c0 = blockIdx.x*128, h = blockIdx.y, tid = threadIdx.x;
    for (int w = 0; w < 23; w++) sm[w*128+tid] = g_s[(h*23+w)*EE + c0+tid];
    __syncthreads();
    for (int kw = 0; kw < 90; kw++) {
        float ar = 0.f, ai = 0.f;
        #pragma unroll
        for (int w = 0; w < 23; w++) {
            float v = sm[w*128+tid];
            ar += v * g_WC[kw*90+w];
            ai -= v * g_WS[kw*90+w];
        }
        g_Pr[(h*90+kw)*EE + c0+tid] = ar;
        g_Pi[(h*90+kw)*EE + c0+tid] = ai;
    }
}
// inverse H-stage: U(45,90,768) complex -> V(45,90,768) complex
__global__ void k_hinv() {
    extern __shared__ float sm[];
    float* sr = sm; float* si = sm + 45*128;
    int c0 = blockIdx.x*128, kw = blockIdx.y, tid = threadIdx.x;
    for (int h = 0; h < 45; h++) {
        sr[h*128+tid] = g_Pr[(h*90+kw)*EE + c0+tid];
        si[h*128+tid] = g_Pi[(h*90+kw)*EE + c0+tid];
    }
    __syncthreads();
    for (int kh = 0; kh < 45; kh++) {
        float vr = 0.f, vi = 0.f;
        #pragma unroll 5
        for (int h = 0; h < 45; h++) {
            float ch = g_HC[kh*45+h], sh = g_HS[kh*45+h];
            float ur = sr[h*128+tid], ui = si[h*128+tid];
            vr += ur*ch + ui*sh;
            vi += ui*ch - ur*sh;
        }
        g_Vr[(kh*90+kw)*EE + c0+tid] = vr;
        g_Vi[(kh*90+kw)*EE + c0+tid] = vi;
    }
}

// ---------------- misc elementwise ----------------
__global__ void gather_n(const float* __restrict__ t) {
    int idx = blockIdx.x*256 + threadIdx.x;
    if (idx >= NFREQ*EE) return;
    int c = idx % EE; int p = idx / EE;
    int w = p % 23, h = p / 23;
    int sh = (45 - h) % 45;
    int sw = (90 - w) % 90;
    g_n[idx] = t[(size_t)(sh*90 + sw)*EE + c];
}
__global__ void soft_thresh() {
    int idx = blockIdx.x*256 + threadIdx.x;
    if (idx >= NFREQ*EE) return;
    float v = g_s[idx];
    float a = fabsf(v) - 0.01f;
    g_s[idx] = (a > 0.f) ? copysignf(a, v) : 0.f;
}
__global__ void add3_kernel() {   // A = z(g_Pr) + t + A
    int idx = blockIdx.x*256 + threadIdx.x;
    if (idx >= NP*EE) return;
    g_A[idx] = g_Pr[idx] + g_t[idx] + g_A[idx];
}
__global__ void add2_kernel() {   // A += g_Pr
    int idx = blockIdx.x*256 + threadIdx.x;
    if (idx >= NP*EE) return;
    g_A[idx] += g_Pr[idx];
}
__global__ void addpos_kernel(const float* __restrict__ pos) {
    int idx = blockIdx.x*256 + threadIdx.x;
    if (idx >= NP*EE) return;
    g_A[idx] += pos[idx];
}
__global__ void im2col_kernel(const float* __restrict__ x) {
    int idx = blockIdx.x*256 + threadIdx.x;
    if (idx >= NP*PKK) return;
    int p = idx / PKK, k = idx % PKK;
    int c = k >> 8, r = k & 255;
    int ph = r >> 4, pw = r & 15;
    int gh = p / 90, gw = p % 90;
    g_px[idx] = x[(size_t)c*1036800 + (size_t)(gh*16+ph)*1440 + (gw*16+pw)];
}
__global__ void scatter_out(float* __restrict__ out) {
    int idx = blockIdx.x*256 + threadIdx.x;
    if (idx >= 20736000) return;
    int oc = idx / 1036800; int r = idx % 1036800;
    int hh = r / 1440, ww = r % 1440;
    int gh = hh >> 4, ph = hh & 15, gw = ww >> 4, pw = ww & 15;
    out[idx] = g_px[(size_t)(gh*90+gw)*HDD + ph*320 + pw*20 + oc];
}

// ---------------- per-layer block-weight prep ----------------
__global__ void prep_pm(const float* __restrict__ w1l, const float* __restrict__ w2l) {
    int i = blockIdx.x*256 + threadIdx.x;
    if (i >= NBB*BSS*BSS) return;
    const int OFF = NBB*BSS*BSS;
    g_W1p[i] = 0.5f*(w1l[i] + w1l[OFF+i]);
    g_W1m[i] = 0.5f*(w1l[i] - w1l[OFF+i]);
    g_W2p[i] = 0.5f*(w2l[i] + w2l[OFF+i]);
    g_W2m[i] = 0.5f*(w2l[i] - w2l[OFF+i]);
}
__global__ void prep_ab() {
    int idx = blockIdx.x*128 + threadIdx.x;
    if (idx >= NBB*BSS*BSS) return;
    int o = idx % 96;
    int i = (idx / 96) % 96;
    int b = idx / 9216;
    const float* P = g_W2p + b*9216;
    const float* M = g_W2m + b*9216;
    float aa = g_W2p[idx];
    float bb = g_W2m[idx] + g_W2p[idx];
    #pragma unroll 8
    for (int j = 0; j < 96; j++) {
        aa += P[i*96+j] * M[j*96+o];
        bb += M[i*96+j] * M[j*96+o];
    }
    g_W2a[idx] = aa;
    g_W2b[idx] = bb;
}
__global__ void prep_bs(const float* __restrict__ b2l) {
    int idx = blockIdx.x*128 + threadIdx.x;
    if (idx >= NBB*BSS) return;
    int o = idx % 96, b = idx / 96;
    float v = b2l[idx] + b2l[NBB*BSS + idx];
    #pragma unroll 8
    for (int j = 0; j < 96; j++) v += b2l[b*96+j] * g_W2m[(b*96+j)*96+o];
    g_bs[idx] = v;
}

// ---------------- block mixing ----------------
// o1k = relu(a*W1p + n*W1m + b1[0]);  o1n = relu(n*W1p + a*W1m + b1[1])
__global__ void k_mix1(const float* __restrict__ b1l) {
    extern __shared__ float sm[];
    float* sWp = sm;
    float* sWm = sm + 9216;
    float* sX  = sm + 18432;          // 15*96
    float* sY  = sX + 1440;
    int b = blockIdx.x, tile = blockIdx.y, o = threadIdx.x;
    for (int i = o; i < 9216; i += 96) { sWp[i] = g_W1p[b*9216+i]; sWm[i] = g_W1m[b*9216+i]; }
    int p0 = tile * 15;
    for (int pp = 0; pp < 15; pp++) {
        sX[pp*96+o] = g_a[(size_t)(p0+pp)*EE + b*96 + o];
        sY[pp*96+o] = g_n[(size_t)(p0+pp)*EE + b*96 + o];
    }
    __syncthreads();
    float bk = b1l[b*96+o], bn = b1l[NBB*BSS + b*96+o];
    for (int pp = 0; pp < 15; pp++) {
        float ak = bk, an = bn;
        #pragma unroll 8
        for (int i = 0; i < 96; i++) {
            float xv = sX[pp*96+i], yv = sY[pp*96+i];
            float wp = sWp[i*96+o], wm = sWm[i*96+o];
            ak += xv*wp + yv*wm;
            an += yv*wp + xv*wm;
        }
        g_o1k[(size_t)(p0+pp)*EE + b*96 + o] = fmaxf(ak, 0.f);
        g_o1n[(size_t)(p0+pp)*EE + b*96 + o] = fmaxf(an, 0.f);
    }
}
// s = o1k*W2a + o1n*W2b + bs
__global__ void k_mix2() {
    extern __shared__ float sm[];
    float* sWa = sm;
    float* sWb = sm + 9216;
    float* sX  = sm + 18432;
    float* sY  = sX + 1440;
    int b = blockIdx.x, tile = blockIdx.y, o = threadIdx.x;
    for (int i = o; i < 9216; i += 96) { sWa[i] = g_W2a[b*9216+i]; sWb[i] = g_W2b[b*9216+i]; }
    int p0 = tile * 15;
    for (int pp = 0; pp < 15; pp++) {
        sX[pp*96+o] = g_o1k[(size_t)(p0+pp)*EE + b*96 + o];
        sY[pp*96+o] = g_o1n[(size_t)(p0+pp)*EE + b*96 + o];
    }
    __syncthreads();
    float bsv = g_bs[b*96+o];
    for (int pp = 0; pp < 15; pp++) {
        float acc = bsv;
        #pragma unroll 8
        for (int i = 0; i < 96; i++) {
            acc += sX[pp*96+i]*sWa[i*96+o] + sY[pp*96+i]*sWb[i*96+o];
        }
        g_s[(size_t)(p0+pp)*EE + b*96 + o] = acc;
    }
}

// ---------------- host orchestration ----------------
extern "C" void kernel_launch(void* const* d_in, const int* in_sizes, int n_in,
                              void* d_out, int out_size)
{
    const float* x        = (const float*)d_in[0];
    const float* patch_w  = (const float*)d_in[1];
    const float* patch_b  = (const float*)d_in[2];
    const float* pos      = (const float*)d_in[3];
    const float* norm1_w  = (const float*)d_in[4];
    const float* norm1_b  = (const float*)d_in[5];
    const float* w1       = (const float*)d_in[6];
    const float* b1       = (const float*)d_in[7];
    const float* w2       = (const float*)d_in[8];
    const float* b2       = (const float*)d_in[9];
    const float* norm2_w  = (const float*)d_in[10];
    const float* norm2_b  = (const float*)d_in[11];
    const float* fc1_w    = (const float*)d_in[12];
    const float* fc1_b    = (const float*)d_in[13];
    const float* fc2_w    = (const float*)d_in[14];
    const float* fc2_b    = (const float*)d_in[15];
    const float* head_w   = (const float*)d_in[16];
    float* out = (float*)d_out;

    float *pPX,*pA,*pT,*pPr,*pPi,*pVr,*pVi,*pH,*pCcos,*pCnsin,*pMr,*pMi;
    cudaGetSymbolAddress((void**)&pPX,   g_px);
    cudaGetSymbolAddress((void**)&pA,    g_A);
    cudaGetSymbolAddress((void**)&pT,    g_t);
    cudaGetSymbolAddress((void**)&pPr,   g_Pr);
    cudaGetSymbolAddress((void**)&pPi,   g_Pi);
    cudaGetSymbolAddress((void**)&pVr,   g_Vr);
    cudaGetSymbolAddress((void**)&pVi,   g_Vi);
    cudaGetSymbolAddress((void**)&pH,    g_hbuf);
    cudaGetSymbolAddress((void**)&pCcos, g_CcosT);
    cudaGetSymbolAddress((void**)&pCnsin,g_CnsinT);
    cudaGetSymbolAddress((void**)&pMr,   g_MrT);
    cudaGetSymbolAddress((void**)&pMi,   g_MiT);

    cudaFuncSetAttribute(k_wfwd, cudaFuncAttributeMaxDynamicSharedMemorySize, 2*90*128*4);
    cudaFuncSetAttribute(k_hfwd, cudaFuncAttributeMaxDynamicSharedMemorySize, 2*45*128*4);
    cudaFuncSetAttribute(k_hinv, cudaFuncAttributeMaxDynamicSharedMemorySize, 2*45*128*4);
    cudaFuncSetAttribute(k_mix1, cudaFuncAttributeMaxDynamicSharedMemorySize, 85248);
    cudaFuncSetAttribute(k_mix2, cudaFuncAttributeMaxDynamicSharedMemorySize, 85248);

    // DFT tables
    tab768<<<(EE*EE + 255)/256, 256>>>();
    tab90 <<<(GWw*GWw + 255)/256, 256>>>();
    tab45 <<<(GHh*GHh + 255)/256, 256>>>();

    // patch embed
    im2col_kernel<<<(NP*PKK + 255)/256, 256>>>(x);
    tgemm_nt<1><<<dim3(EE/128, (NP+127)/128), 256>>>(pPX, patch_w, pA, NP, EE, PKK, patch_b);
    addpos_kernel<<<(NP*EE + 255)/256, 256>>>(pos);

    const int EWGRID = (NP*EE + 255)/256;
    const int FGRID  = (NFREQ*EE + 255)/256;

    for (int l = 0; l < 12; l++) {
        // ---- AFNO half ----
        ln_kernel<<<NP, 256>>>(pA, pT, norm1_w + l*EE, norm1_b + l*EE);
        // forward DHT: C stage
        tgemm_nt<0><<<dim3(EE/128, (NP+127)/128), 256>>>(pT, pCcos,  pPr, NP, EE, EE, nullptr);
        tgemm_nt<0><<<dim3(EE/128, (NP+127)/128), 256>>>(pT, pCnsin, pPi, NP, EE, EE, nullptr);
        k_wfwd<<<dim3(6, 45), 128, 2*90*128*4>>>();
        k_hfwd<<<dim3(6, 23), 128, 2*45*128*4>>>();
        gather_n<<<FGRID, 256>>>(pT);
        // prep mixed block weights
        prep_pm<<<(NBB*BSS*BSS + 255)/256, 256>>>(w1 + (size_t)l*2*NBB*BSS*BSS, w2 + (size_t)l*2*NBB*BSS*BSS);
        prep_ab<<<(NBB*BSS*BSS + 127)/128, 128>>>();
        prep_bs<<<(NBB*BSS + 127)/128, 128>>>(b2 + (size_t)l*2*NBB*BSS);
        // mixing
        k_mix1<<<dim3(8, 69), 96, 85248>>>(b1 + (size_t)l*2*NBB*BSS);
        k_mix2<<<dim3(8, 69), 96, 85248>>>();
        soft_thresh<<<FGRID, 256>>>();
        // inverse DHT
        k_winv<<<dim3(6, 45), 128, 23*128*4>>>();
        k_hinv<<<dim3(6, 90), 128, 2*45*128*4>>>();
        tgemm_nt<0><<<dim3(EE/128, (NP+127)/128), 256>>>(pVr, pMr, pPr, NP, EE, EE, nullptr);
        tgemm_nt<3><<<dim3(EE/128, (NP+127)/128), 256>>>(pVi, pMi, pPr, NP, EE, EE, nullptr);
        add3_kernel<<<EWGRID, 256>>>();   // A = dht + ln_out + A

        // ---- MLP half ----
        ln_kernel<<<NP, 256>>>(pA, pT, norm2_w + l*EE, norm2_b + l*EE);
        tgemm_nt<2><<<dim3(HID/128, (NP+127)/128), 256>>>(pT, fc1_w + (size_t)l*HID*EE, pH, NP, HID, EE,  fc1_b + l*HID);
        tgemm_nt<1><<<dim3(EE/128,  (NP+127)/128), 256>>>(pH, fc2_w + (size_t)l*EE*HID, pPr, NP, EE, HID, fc2_b + l*EE);
        add2_kernel<<<EWGRID, 256>>>();
    }

    // head
    tgemm_nt<0><<<dim3(HDD/128, (NP+127)/128), 256>>>(pA, head_w, pPX, NP, HDD, EE, nullptr);
    scatter_out<<<(20736000 + 255)/256, 256>>>(out);
}

// round 5
// speedup vs baseline: 1.8038x; 1.4076x over previous
#include <cuda_runtime.h>
#include <cuda_bf16.h>
#include <math.h>
#include <stdint.h>

// ---------------- constants ----------------
#define GHh 45
#define GWw 90
#define NP 4050          // tokens
#define MPAD 4096        // padded token rows for GEMM A operands
#define EE 768
#define KM 23
#define NFREQ (GHh*KM)   // 1035
#define HID 3072
#define PKK 5120
#define HDD 5120
#define NBB 8
#define BSS 96
#define DHT_SIZE 3110400.0

// ---------------- fp32 scratch ----------------
__device__ __align__(128) float g_px[(size_t)NP*PKK];   // head output tokens
__device__ __align__(128) float g_A [NP*EE];
__device__ __align__(128) float g_t [NP*EE];
__device__ __align__(128) float g_Pr[NP*EE];
__device__ __align__(128) float g_Pi[NP*EE];
__device__ __align__(128) float g_Qr[NFREQ*EE];
__device__ __align__(128) float g_Qi[NFREQ*EE];
__device__ __align__(128) float g_a [NFREQ*EE];
__device__ __align__(128) float g_n [NFREQ*EE];
__device__ __align__(128) float g_o1k[NFREQ*EE];
__device__ __align__(128) float g_o1n[NFREQ*EE];
__device__ __align__(128) float g_s [NFREQ*EE];
// small DFT tables
__device__ __align__(128) float g_WC[GWw*GWw];
__device__ __align__(128) float g_WS[GWw*GWw];
__device__ __align__(128) float g_HC[GHh*GHh];
__device__ __align__(128) float g_HS[GHh*GHh];
// per-layer prepped block weights (fp32 mixing path)
__device__ __align__(128) float g_W1p[NBB*BSS*BSS], g_W1m[NBB*BSS*BSS];
__device__ __align__(128) float g_W2p[NBB*BSS*BSS], g_W2m[NBB*BSS*BSS];
__device__ __align__(128) float g_W2a[NBB*BSS*BSS], g_W2b[NBB*BSS*BSS];
__device__ __align__(128) float g_bs [NBB*BSS];

// ---------------- bf16 split buffers (hi/lo) ----------------
__device__ __align__(128) __nv_bfloat16 g_pxh[(size_t)MPAD*PKK], g_pxl[(size_t)MPAD*PKK];
__device__ __align__(128) __nv_bfloat16 g_th [(size_t)MPAD*EE],  g_tl [(size_t)MPAD*EE];
__device__ __align__(128) __nv_bfloat16 g_Vrh[(size_t)MPAD*EE],  g_Vrl[(size_t)MPAD*EE];
__device__ __align__(128) __nv_bfloat16 g_Vih[(size_t)MPAD*EE],  g_Vil[(size_t)MPAD*EE];
__device__ __align__(128) __nv_bfloat16 g_hbh[(size_t)MPAD*HID], g_hbl[(size_t)MPAD*HID];
__device__ __align__(128) __nv_bfloat16 g_Ah2[(size_t)MPAD*EE],  g_Al2[(size_t)MPAD*EE];
// weights / tables
__device__ __align__(128) __nv_bfloat16 g_pwh[EE*PKK],  g_pwl[EE*PKK];
__device__ __align__(128) __nv_bfloat16 g_cch[EE*EE],   g_ccl[EE*EE];   // cos
__device__ __align__(128) __nv_bfloat16 g_csh[EE*EE],   g_csl[EE*EE];   // -sin
__device__ __align__(128) __nv_bfloat16 g_mrh[EE*EE],   g_mrl[EE*EE];   // (cos-sin)/S
__device__ __align__(128) __nv_bfloat16 g_mih[EE*EE],   g_mil[EE*EE];   // (cos+sin)/S
__device__ __align__(128) __nv_bfloat16 g_f1h[(size_t)12*HID*EE], g_f1l[(size_t)12*HID*EE];
__device__ __align__(128) __nv_bfloat16 g_f2h[(size_t)12*EE*HID], g_f2l[(size_t)12*EE*HID];
__device__ __align__(128) __nv_bfloat16 g_hwh[HDD*EE],  g_hwl[HDD*EE];

// ---------------- helpers ----------------
__device__ __forceinline__ void bsplit(float x, __nv_bfloat16& h, __nv_bfloat16& l) {
    h = __float2bfloat16(x);
    l = __float2bfloat16(x - __bfloat162float(h));
}
__device__ __forceinline__ uint32_t s2u32(const void* p) {
    uint32_t a;
    asm("{ .reg .u64 t; cvta.to.shared.u64 t, %1; cvt.u32.u64 %0, t; }" : "=r"(a) : "l"(p));
    return a;
}
__device__ __forceinline__ void mma_bf16(float* c, const uint32_t* a, const uint32_t* b) {
    asm volatile("mma.sync.aligned.m16n8k16.row.col.f32.bf16.bf16.f32 "
        "{%0,%1,%2,%3}, {%4,%5,%6,%7}, {%8,%9}, {%0,%1,%2,%3};"
        : "+f"(c[0]), "+f"(c[1]), "+f"(c[2]), "+f"(c[3])
        : "r"(a[0]), "r"(a[1]), "r"(a[2]), "r"(a[3]), "r"(b[0]), "r"(b[1]));
}
__device__ __forceinline__ void cpa16(uint32_t dst, const void* src) {
    asm volatile("cp.async.cg.shared.global [%0], [%1], 16;" :: "r"(dst), "l"(src));
}

// ---------------- table init ----------------
__global__ void tab768() {
    int idx = blockIdx.x*256 + threadIdx.x;
    if (idx >= EE*EE) return;
    int kc = idx / EE, c = idx % EE;
    long long m = ((long long)kc * c) % EE;
    double a = 2.0 * (double)m / (double)EE;
    double cs = cospi(a), sn = sinpi(a);
    __nv_bfloat16 h, l;
    bsplit((float)cs, h, l);                 g_cch[idx]=h; g_ccl[idx]=l;
    bsplit((float)(-sn), h, l);              g_csh[idx]=h; g_csl[idx]=l;
    bsplit((float)((cs-sn)/DHT_SIZE), h, l); g_mrh[idx]=h; g_mrl[idx]=l;
    bsplit((float)((cs+sn)/DHT_SIZE), h, l); g_mih[idx]=h; g_mil[idx]=l;
}
__global__ void tab90() {
    int idx = blockIdx.x*256 + threadIdx.x;
    if (idx >= GWw*GWw) return;
    int a = idx / GWw, b = idx % GWw;
    long long m = ((long long)a * b) % GWw;
    double ang = 2.0 * (double)m / (double)GWw;
    g_WC[idx] = (float)cospi(ang);
    g_WS[idx] = (float)sinpi(ang);
}
__global__ void tab45() {
    int idx = blockIdx.x*256 + threadIdx.x;
    if (idx >= GHh*GHh) return;
    int a = idx / GHh, b = idx % GHh;
    long long m = ((long long)a * b) % GHh;
    double ang = 2.0 * (double)m / (double)GHh;
    g_HC[idx] = (float)cospi(ang);
    g_HS[idx] = (float)sinpi(ang);
}

// ---------------- generic fp32 -> bf16 hi/lo splitter ----------------
__global__ void split_kernel(const float* __restrict__ in,
                             __nv_bfloat16* __restrict__ oh,
                             __nv_bfloat16* __restrict__ ol, int n) {
    int i = blockIdx.x*256 + threadIdx.x;
    if (i >= n) return;
    __nv_bfloat16 h, l;
    bsplit(in[i], h, l);
    oh[i] = h; ol[i] = l;
}

// ---------------- bf16x3 mma.sync GEMM: C[m,n] = sum_k A[m,k]*B[n,k] ----------------
// block 128x128, k-chunk 32, 8 warps (2m x 4n), warp tile 64x32, cp.async double buffer
// smem tile layout: rows of 40 bf16 (80B stride -> conflict-free ldmatrix)
// MODE: 0=store fp32, 1=store+bias, 2=bias+GELU -> bf16 split, 3=accumulate fp32
#define TSE 5120                 // tile elems (128*40)
#define TSB 10240                // tile bytes
#define BUFB 40960               // 4 tiles per buffer, bytes

template<int MODE>
__global__ void __launch_bounds__(256, 2)
hgemm(const __nv_bfloat16* __restrict__ Ah, const __nv_bfloat16* __restrict__ Al,
      const __nv_bfloat16* __restrict__ Bh, const __nv_bfloat16* __restrict__ Bl,
      float* __restrict__ C,
      __nv_bfloat16* __restrict__ Csh, __nv_bfloat16* __restrict__ Csl,
      int Mtrue, int N, int K, const float* __restrict__ bias)
{
    extern __shared__ __align__(128) char smem[];   // 81920 B
    const int t = threadIdx.x, warp = t >> 5, lane = t & 31;
    const int wm = warp & 1, wn = warp >> 1;
    const int bm = blockIdx.y * 128, bn = blockIdx.x * 128;
    const uint32_t sb = s2u32(smem);

    float acc[4][4][4];
    #pragma unroll
    for (int i = 0; i < 4; i++)
        #pragma unroll
        for (int j = 0; j < 4; j++)
            #pragma unroll
            for (int q = 0; q < 4; q++) acc[i][j][q] = 0.f;

    // loader mapping: 256 threads -> 128 rows x 2 col-halves (16 bf16 = 32B each)
    const int lrow = t & 127, lhalf = t >> 7;
    const __nv_bfloat16* pAh = Ah + (size_t)(bm + lrow) * K + lhalf * 16;
    const __nv_bfloat16* pAl = Al + (size_t)(bm + lrow) * K + lhalf * 16;
    const __nv_bfloat16* pBh = Bh + (size_t)(bn + lrow) * K + lhalf * 16;
    const __nv_bfloat16* pBl = Bl + (size_t)(bn + lrow) * K + lhalf * 16;
    const uint32_t soff = (uint32_t)(lrow * 40 + lhalf * 16) * 2;  // bytes

    const int nch = K >> 5;

    // issue chunk loads
    auto issue = [&](int ch) {
        const int koff = ch << 5;
        const uint32_t dst = sb + (uint32_t)(ch & 1) * BUFB + soff;
        cpa16(dst,              pAh + koff); cpa16(dst + 16,              (const char*)(pAh + koff) + 16);
        cpa16(dst + TSB,        pAl + koff); cpa16(dst + TSB + 16,        (const char*)(pAl + koff) + 16);
        cpa16(dst + 2*TSB,      pBh + koff); cpa16(dst + 2*TSB + 16,      (const char*)(pBh + koff) + 16);
        cpa16(dst + 3*TSB,      pBl + koff); cpa16(dst + 3*TSB + 16,      (const char*)(pBl + koff) + 16);
        asm volatile("cp.async.commit_group;" ::: "memory");
    };

    issue(0);
    for (int ch = 0; ch < nch; ch++) {
        const bool more = (ch + 1) < nch;
        if (more) issue(ch + 1);
        if (more) asm volatile("cp.async.wait_group 1;" ::: "memory");
        else      asm volatile("cp.async.wait_group 0;" ::: "memory");
        __syncthreads();

        const uint32_t bufb = sb + (uint32_t)(ch & 1) * BUFB;
        const uint32_t tAh = bufb, tAl = bufb + TSB, tBh = bufb + 2*TSB, tBl = bufb + 3*TSB;

        #pragma unroll
        for (int step = 0; step < 2; step++) {
            const int ks = step * 16;
            uint32_t af[4][4], bf[4][2];
            const int g = lane >> 3, r = lane & 7;
            // A fragment addresses: row = rA + (g&1)*8 + r, col = ks + (g>>1)*8
            const uint32_t a_off = (uint32_t)(((g & 1) * 8 + r) * 40 + ks + (g >> 1) * 8) * 2;
            // B fragment addresses (2 n-tiles per ldmatrix.x4): row = rB + (g>>1)*8 + r, col = ks + (g&1)*8
            const uint32_t b_off = (uint32_t)(((g >> 1) * 8 + r) * 40 + ks + (g & 1) * 8) * 2;

            #pragma unroll
            for (int mt = 0; mt < 4; mt++) {
                uint32_t ad = tAh + (uint32_t)((wm*64 + mt*16) * 40) * 2 + a_off;
                asm volatile("ldmatrix.sync.aligned.m8n8.x4.shared.b16 {%0,%1,%2,%3}, [%4];"
                    : "=r"(af[mt][0]), "=r"(af[mt][1]), "=r"(af[mt][2]), "=r"(af[mt][3]) : "r"(ad));
            }
            #pragma unroll
            for (int j = 0; j < 4; j += 2) {
                uint32_t bd = tBh + (uint32_t)((wn*32 + j*8) * 40) * 2 + b_off;
                asm volatile("ldmatrix.sync.aligned.m8n8.x4.shared.b16 {%0,%1,%2,%3}, [%4];"
                    : "=r"(bf[j][0]), "=r"(bf[j][1]), "=r"(bf[j+1][0]), "=r"(bf[j+1][1]) : "r"(bd));
            }
            #pragma unroll
            for (int mt = 0; mt < 4; mt++)
                #pragma unroll
                for (int nt = 0; nt < 4; nt++) mma_bf16(acc[mt][nt], af[mt], bf[nt]);

            // Ah * Bl
            #pragma unroll
            for (int j = 0; j < 4; j += 2) {
                uint32_t bd = tBl + (uint32_t)((wn*32 + j*8) * 40) * 2 + b_off;
                asm volatile("ldmatrix.sync.aligned.m8n8.x4.shared.b16 {%0,%1,%2,%3}, [%4];"
                    : "=r"(bf[j][0]), "=r"(bf[j][1]), "=r"(bf[j+1][0]), "=r"(bf[j+1][1]) : "r"(bd));
            }
            #pragma unroll
            for (int mt = 0; mt < 4; mt++)
                #pragma unroll
                for (int nt = 0; nt < 4; nt++) mma_bf16(acc[mt][nt], af[mt], bf[nt]);

            // Al * Bh (reload Al into af, Bh into bf)
            #pragma unroll
            for (int mt = 0; mt < 4; mt++) {
                uint32_t ad = tAl + (uint32_t)((wm*64 + mt*16) * 40) * 2 + a_off;
                asm volatile("ldmatrix.sync.aligned.m8n8.x4.shared.b16 {%0,%1,%2,%3}, [%4];"
                    : "=r"(af[mt][0]), "=r"(af[mt][1]), "=r"(af[mt][2]), "=r"(af[mt][3]) : "r"(ad));
            }
            #pragma unroll
            for (int j = 0; j < 4; j += 2) {
                uint32_t bd = tBh + (uint32_t)((wn*32 + j*8) * 40) * 2 + b_off;
                asm volatile("ldmatrix.sync.aligned.m8n8.x4.shared.b16 {%0,%1,%2,%3}, [%4];"
                    : "=r"(bf[j][0]), "=r"(bf[j][1]), "=r"(bf[j+1][0]), "=r"(bf[j+1][1]) : "r"(bd));
            }
            #pragma unroll
            for (int mt = 0; mt < 4; mt++)
                #pragma unroll
                for (int nt = 0; nt < 4; nt++) mma_bf16(acc[mt][nt], af[mt], bf[nt]);
        }
        __syncthreads();
    }

    // epilogue: direct register -> gmem
    #pragma unroll
    for (int mt = 0; mt < 4; mt++) {
        const int r0 = bm + wm*64 + mt*16 + (lane >> 2);
        #pragma unroll
        for (int nt = 0; nt < 4; nt++) {
            const int c0 = bn + wn*32 + nt*8 + (lane & 3)*2;
            float b0 = 0.f, b1 = 0.f;
            if (MODE == 1 || MODE == 2) { b0 = bias[c0]; b1 = bias[c0+1]; }
            #pragma unroll
            for (int h = 0; h < 2; h++) {
                const int row = r0 + h*8;
                if (row >= Mtrue) continue;
                float v0 = acc[mt][nt][h*2+0] + b0;
                float v1 = acc[mt][nt][h*2+1] + b1;
                if (MODE == 2) {
                    v0 = 0.5f*v0*(1.0f + erff(v0*0.7071067811865475f));
                    v1 = 0.5f*v1*(1.0f + erff(v1*0.7071067811865475f));
                    __nv_bfloat16 h0, l0, h1, l1;
                    bsplit(v0, h0, l0); bsplit(v1, h1, l1);
                    __nv_bfloat162 hv; hv.x = h0; hv.y = h1;
                    __nv_bfloat162 lv; lv.x = l0; lv.y = l1;
                    *(__nv_bfloat162*)&Csh[(size_t)row*N + c0] = hv;
                    *(__nv_bfloat162*)&Csl[(size_t)row*N + c0] = lv;
                } else if (MODE == 3) {
                    float2* cp = (float2*)&C[(size_t)row*N + c0];
                    float2 old = *cp;
                    old.x += v0; old.y += v1;
                    *cp = old;
                } else {
                    float2 fv; fv.x = v0; fv.y = v1;
                    *(float2*)&C[(size_t)row*N + c0] = fv;
                }
            }
        }
    }
}

// ---------------- LayerNorm (fp32 out + bf16 split out) ----------------
__global__ void ln_kernel(const float* __restrict__ in, float* __restrict__ out,
                          __nv_bfloat16* __restrict__ oh, __nv_bfloat16* __restrict__ ol,
                          const float* __restrict__ w, const float* __restrict__ b)
{
    int tok = blockIdx.x;
    int tid = threadIdx.x;                 // 256 threads
    const float* row = in + (size_t)tok*EE;
    float x0 = row[tid], x1 = row[tid+256], x2 = row[tid+512];
    float s  = x0+x1+x2;
    float sq = x0*x0 + x1*x1 + x2*x2;
    #pragma unroll
    for (int o = 16; o > 0; o >>= 1) {
        s  += __shfl_down_sync(0xffffffffu, s,  o);
        sq += __shfl_down_sync(0xffffffffu, sq, o);
    }
    __shared__ float ss[8], ssq[8];
    int warp = tid >> 5, lane = tid & 31;
    if (lane == 0) { ss[warp] = s; ssq[warp] = sq; }
    __syncthreads();
    if (tid == 0) {
        float ts = 0.f, tq = 0.f;
        #pragma unroll
        for (int i = 0; i < 8; i++) { ts += ss[i]; tq += ssq[i]; }
        float m = ts * (1.0f/768.0f);
        float v = tq * (1.0f/768.0f) - m*m;
        ss[0] = m; ssq[0] = rsqrtf(v + 1e-5f);
    }
    __syncthreads();
    float m = ss[0], inv = ssq[0];
    size_t base = (size_t)tok*EE;
    #pragma unroll
    for (int j = 0; j < 3; j++) {
        int o = tid + j*256;
        float y = (j==0?x0:(j==1?x1:x2));
        y = (y - m)*inv*w[o] + b[o];
        out[base + o] = y;
        __nv_bfloat16 h, l; bsplit(y, h, l);
        oh[base + o] = h; ol[base + o] = l;
    }
}

// ---------------- DHT stage kernels ----------------
__global__ void k_wfwd() {
    extern __shared__ float sm[];
    float* sr = sm; float* si = sm + 90*128;
    int c0 = blockIdx.x*128, h = blockIdx.y, tid = threadIdx.x;
    for (int w = 0; w < 90; w++) {
        sr[w*128+tid] = g_Pr[(h*90+w)*EE + c0+tid];
        si[w*128+tid] = g_Pi[(h*90+w)*EE + c0+tid];
    }
    __syncthreads();
    for (int kw = 0; kw < 23; kw++) {
        float ar = 0.f, ai = 0.f;
        #pragma unroll 6
        for (int w = 0; w < 90; w++) {
            float cw = g_WC[kw*90+w], sw = g_WS[kw*90+w];
            float pr = sr[w*128+tid], pi = si[w*128+tid];
            ar += pr*cw + pi*sw;
            ai += pi*cw - pr*sw;
        }
        g_Qr[(h*23+kw)*EE + c0+tid] = ar;
        g_Qi[(h*23+kw)*EE + c0+tid] = ai;
    }
}
__global__ void k_hfwd() {
    extern __shared__ float sm[];
    float* sr = sm; float* si = sm + 45*128;
    int c0 = blockIdx.x*128, kw = blockIdx.y, tid = threadIdx.x;
    for (int h = 0; h < 45; h++) {
        sr[h*128+tid] = g_Qr[(h*23+kw)*EE + c0+tid];
        si[h*128+tid] = g_Qi[(h*23+kw)*EE + c0+tid];
    }
    __syncthreads();
    for (int kh = 0; kh < 45; kh++) {
        float acc = 0.f;
        #pragma unroll 5
        for (int h = 0; h < 45; h++) {
            float ch = g_HC[kh*45+h], sh = g_HS[kh*45+h];
            acc += sr[h*128+tid]*(ch - sh) + si[h*128+tid]*(ch + sh);
        }
        g_a[(kh*23+kw)*EE + c0+tid] = acc;
    }
}
__global__ void k_winv() {
    extern __shared__ float sm[];
    int c0 = blockIdx.x*128, h = blockIdx.y, tid = threadIdx.x;
    for (int w = 0; w < 23; w++) sm[w*128+tid] = g_s[(h*23+w)*EE + c0+tid];
    __syncthreads();
    for (int kw = 0; kw < 90; kw++) {
        float ar = 0.f, ai = 0.f;
        #pragma unroll
        for (int w = 0; w < 23; w++) {
            float v = sm[w*128+tid];
            ar += v * g_WC[kw*90+w];
            ai -= v * g_WS[kw*90+w];
        }
        g_Pr[(h*90+kw)*EE + c0+tid] = ar;
        g_Pi[(h*90+kw)*EE + c0+tid] = ai;
    }
}
// inverse H-stage: writes V as bf16 splits (GEMM A operand)
__global__ void k_hinv() {
    extern __shared__ float sm[];
    float* sr = sm; float* si = sm + 45*128;
    int c0 = blockIdx.x*128, kw = blockIdx.y, tid = threadIdx.x;
    for (int h = 0; h < 45; h++) {
        sr[h*128+tid] = g_Pr[(h*90+kw)*EE + c0+tid];
        si[h*128+tid] = g_Pi[(h*90+kw)*EE + c0+tid];
    }
    __syncthreads();
    for (int kh = 0; kh < 45; kh++) {
        float vr = 0.f, vi = 0.f;
        #pragma unroll 5
        for (int h = 0; h < 45; h++) {
            float ch = g_HC[kh*45+h], sh = g_HS[kh*45+h];
            float ur = sr[h*128+tid], ui = si[h*128+tid];
            vr += ur*ch + ui*sh;
            vi += ui*ch - ur*sh;
        }
        size_t o = (size_t)(kh*90+kw)*EE + c0+tid;
        __nv_bfloat16 h2, l2;
        bsplit(vr, h2, l2); g_Vrh[o]=h2; g_Vrl[o]=l2;
        bsplit(vi, h2, l2); g_Vih[o]=h2; g_Vil[o]=l2;
    }
}

// ---------------- misc elementwise ----------------
__global__ void gather_n(const float* __restrict__ t) {
    int idx = blockIdx.x*256 + threadIdx.x;
    if (idx >= NFREQ*EE) return;
    int c = idx % EE; int p = idx / EE;
    int w = p % 23, h = p / 23;
    int sh = (45 - h) % 45;
    int sw = (90 - w) % 90;
    g_n[idx] = t[(size_t)(sh*90 + sw)*EE + c];
}
__global__ void soft_thresh() {
    int idx = blockIdx.x*256 + threadIdx.x;
    if (idx >= NFREQ*EE) return;
    float v = g_s[idx];
    float a = fabsf(v) - 0.01f;
    g_s[idx] = (a > 0.f) ? copysignf(a, v) : 0.f;
}
__global__ void add3_kernel() {   // A = dht(g_Pr) + t + A
    int idx = blockIdx.x*256 + threadIdx.x;
    if (idx >= NP*EE) return;
    g_A[idx] = g_Pr[idx] + g_t[idx] + g_A[idx];
}
__global__ void add2_kernel() {   // A += g_Pr
    int idx = blockIdx.x*256 + threadIdx.x;
    if (idx >= NP*EE) return;
    g_A[idx] += g_Pr[idx];
}
__global__ void addpos_kernel(const float* __restrict__ pos) {
    int idx = blockIdx.x*256 + threadIdx.x;
    if (idx >= NP*EE) return;
    g_A[idx] += pos[idx];
}
__global__ void im2col_kernel(const float* __restrict__ x) {
    int idx = blockIdx.x*256 + threadIdx.x;
    if (idx >= NP*PKK) return;
    int p = idx / PKK, k = idx % PKK;
    int c = k >> 8, r = k & 255;
    int ph = r >> 4, pw = r & 15;
    int gh = p / 90, gw = p % 90;
    float v = x[(size_t)c*1036800 + (size_t)(gh*16+ph)*1440 + (gw*16+pw)];
    __nv_bfloat16 h, l; bsplit(v, h, l);
    size_t o = (size_t)p*PKK + k;
    g_pxh[o] = h; g_pxl[o] = l;
}
__global__ void scatter_out(float* __restrict__ out) {
    int idx = blockIdx.x*256 + threadIdx.x;
    if (idx >= 20736000) return;
    int oc = idx / 1036800; int r = idx % 1036800;
    int hh = r / 1440, ww = r % 1440;
    int gh = hh >> 4, ph = hh & 15, gw = ww >> 4, pw = ww & 15;
    out[idx] = g_px[(size_t)(gh*90+gw)*HDD + ph*320 + pw*20 + oc];
}

// ---------------- per-layer block-weight prep ----------------
__global__ void prep_pm(const float* __restrict__ w1l, const float* __restrict__ w2l) {
    int i = blockIdx.x*256 + threadIdx.x;
    if (i >= NBB*BSS*BSS) return;
    const int OFF = NBB*BSS*BSS;
    g_W1p[i] = 0.5f*(w1l[i] + w1l[OFF+i]);
    g_W1m[i] = 0.5f*(w1l[i] - w1l[OFF+i]);
    g_W2p[i] = 0.5f*(w2l[i] + w2l[OFF+i]);
    g_W2m[i] = 0.5f*(w2l[i] - w2l[OFF+i]);
}
__global__ void prep_ab() {
    int idx = blockIdx.x*128 + threadIdx.x;
    if (idx >= NBB*BSS*BSS) return;
    int o = idx % 96;
    int i = (idx / 96) % 96;
    int b = idx / 9216;
    const float* P = g_W2p + b*9216;
    const float* M = g_W2m + b*9216;
    float aa = g_W2p[idx];
    float bb = g_W2m[idx] + g_W2p[idx];
    #pragma unroll 8
    for (int j = 0; j < 96; j++) {
        aa += P[i*96+j] * M[j*96+o];
        bb += M[i*96+j] * M[j*96+o];
    }
    g_W2a[idx] = aa;
    g_W2b[idx] = bb;
}
__global__ void prep_bs(const float* __restrict__ b2l) {
    int idx = blockIdx.x*128 + threadIdx.x;
    if (idx >= NBB*BSS) return;
    int o = idx % 96, b = idx / 96;
    float v = b2l[idx] + b2l[NBB*BSS + idx];
    #pragma unroll 8
    for (int j = 0; j < 96; j++) v += b2l[b*96+j] * g_W2m[(b*96+j)*96+o];
    g_bs[idx] = v;
}

// ---------------- block mixing ----------------
__global__ void k_mix1(const float* __restrict__ b1l) {
    extern __shared__ float sm[];
    float* sWp = sm;
    float* sWm = sm + 9216;
    float* sX  = sm + 18432;
    float* sY  = sX + 1440;
    int b = blockIdx.x, tile = blockIdx.y, o = threadIdx.x;
    for (int i = o; i < 9216; i += 96) { sWp[i] = g_W1p[b*9216+i]; sWm[i] = g_W1m[b*9216+i]; }
    int p0 = tile * 15;
    for (int pp = 0; pp < 15; pp++) {
        sX[pp*96+o] = g_a[(size_t)(p0+pp)*EE + b*96 + o];
        sY[pp*96+o] = g_n[(size_t)(p0+pp)*EE + b*96 + o];
    }
    __syncthreads();
    float bk = b1l[b*96+o], bn = b1l[NBB*BSS + b*96+o];
    for (int pp = 0; pp < 15; pp++) {
        float ak = bk, an = bn;
        #pragma unroll 8
        for (int i = 0; i < 96; i++) {
            float xv = sX[pp*96+i], yv = sY[pp*96+i];
            float wp = sWp[i*96+o], wm = sWm[i*96+o];
            ak += xv*wp + yv*wm;
            an += yv*wp + xv*wm;
        }
        g_o1k[(size_t)(p0+pp)*EE + b*96 + o] = fmaxf(ak, 0.f);
        g_o1n[(size_t)(p0+pp)*EE + b*96 + o] = fmaxf(an, 0.f);
    }
}
__global__ void k_mix2() {
    extern __shared__ float sm[];
    float* sWa = sm;
    float* sWb = sm + 9216;
    float* sX  = sm + 18432;
    float* sY  = sX + 1440;
    int b = blockIdx.x, tile = blockIdx.y, o = threadIdx.x;
    for (int i = o; i < 9216; i += 96) { sWa[i] = g_W2a[b*9216+i]; sWb[i] = g_W2b[b*9216+i]; }
    int p0 = tile * 15;
    for (int pp = 0; pp < 15; pp++) {
        sX[pp*96+o] = g_o1k[(size_t)(p0+pp)*EE + b*96 + o];
        sY[pp*96+o] = g_o1n[(size_t)(p0+pp)*EE + b*96 + o];
    }
    __syncthreads();
    float bsv = g_bs[b*96+o];
    for (int pp = 0; pp < 15; pp++) {
        float acc = bsv;
        #pragma unroll 8
        for (int i = 0; i < 96; i++) {
            acc += sX[pp*96+i]*sWa[i*96+o] + sY[pp*96+i]*sWb[i*96+o];
        }
        g_s[(size_t)(p0+pp)*EE + b*96 + o] = acc;
    }
}

// ---------------- host orchestration ----------------
extern "C" void kernel_launch(void* const* d_in, const int* in_sizes, int n_in,
                              void* d_out, int out_size)
{
    const float* x        = (const float*)d_in[0];
    const float* patch_w  = (const float*)d_in[1];
    const float* patch_b  = (const float*)d_in[2];
    const float* pos      = (const float*)d_in[3];
    const float* norm1_w  = (const float*)d_in[4];
    const float* norm1_b  = (const float*)d_in[5];
    const float* w1       = (const float*)d_in[6];
    const float* b1       = (const float*)d_in[7];
    const float* w2       = (const float*)d_in[8];
    const float* b2       = (const float*)d_in[9];
    const float* norm2_w  = (const float*)d_in[10];
    const float* norm2_b  = (const float*)d_in[11];
    const float* fc1_w    = (const float*)d_in[12];
    const float* fc1_b    = (const float*)d_in[13];
    const float* fc2_w    = (const float*)d_in[14];
    const float* fc2_b    = (const float*)d_in[15];
    const float* head_w   = (const float*)d_in[16];
    float* out = (float*)d_out;

    float *pPX,*pA,*pT,*pPr,*pPi;
    cudaGetSymbolAddress((void**)&pPX, g_px);
    cudaGetSymbolAddress((void**)&pA,  g_A);
    cudaGetSymbolAddress((void**)&pT,  g_t);
    cudaGetSymbolAddress((void**)&pPr, g_Pr);
    cudaGetSymbolAddress((void**)&pPi, g_Pi);

    __nv_bfloat16 *pxh,*pxl,*th,*tl,*vrh,*vrl,*vih,*vil,*hbh,*hbl,*ah2,*al2;
    __nv_bfloat16 *pwh,*pwl,*cch,*ccl,*csh,*csl,*mrh,*mrl,*mih,*mil,*f1h,*f1l,*f2h,*f2l,*hwh,*hwl;
    cudaGetSymbolAddress((void**)&pxh, g_pxh);  cudaGetSymbolAddress((void**)&pxl, g_pxl);
    cudaGetSymbolAddress((void**)&th,  g_th);   cudaGetSymbolAddress((void**)&tl,  g_tl);
    cudaGetSymbolAddress((void**)&vrh, g_Vrh);  cudaGetSymbolAddress((void**)&vrl, g_Vrl);
    cudaGetSymbolAddress((void**)&vih, g_Vih);  cudaGetSymbolAddress((void**)&vil, g_Vil);
    cudaGetSymbolAddress((void**)&hbh, g_hbh);  cudaGetSymbolAddress((void**)&hbl, g_hbl);
    cudaGetSymbolAddress((void**)&ah2, g_Ah2);  cudaGetSymbolAddress((void**)&al2, g_Al2);
    cudaGetSymbolAddress((void**)&pwh, g_pwh);  cudaGetSymbolAddress((void**)&pwl, g_pwl);
    cudaGetSymbolAddress((void**)&cch, g_cch);  cudaGetSymbolAddress((void**)&ccl, g_ccl);
    cudaGetSymbolAddress((void**)&csh, g_csh);  cudaGetSymbolAddress((void**)&csl, g_csl);
    cudaGetSymbolAddress((void**)&mrh, g_mrh);  cudaGetSymbolAddress((void**)&mrl, g_mrl);
    cudaGetSymbolAddress((void**)&mih, g_mih);  cudaGetSymbolAddress((void**)&mil, g_mil);
    cudaGetSymbolAddress((void**)&f1h, g_f1h);  cudaGetSymbolAddress((void**)&f1l, g_f1l);
    cudaGetSymbolAddress((void**)&f2h, g_f2h);  cudaGetSymbolAddress((void**)&f2l, g_f2l);
    cudaGetSymbolAddress((void**)&hwh, g_hwh);  cudaGetSymbolAddress((void**)&hwl, g_hwl);

    cudaFuncSetAttribute(k_wfwd, cudaFuncAttributeMaxDynamicSharedMemorySize, 2*90*128*4);
    cudaFuncSetAttribute(k_hfwd, cudaFuncAttributeMaxDynamicSharedMemorySize, 2*45*128*4);
    cudaFuncSetAttribute(k_hinv, cudaFuncAttributeMaxDynamicSharedMemorySize, 2*45*128*4);
    cudaFuncSetAttribute(k_mix1, cudaFuncAttributeMaxDynamicSharedMemorySize, 85248);
    cudaFuncSetAttribute(k_mix2, cudaFuncAttributeMaxDynamicSharedMemorySize, 85248);
    cudaFuncSetAttribute(hgemm<0>, cudaFuncAttributeMaxDynamicSharedMemorySize, 2*BUFB);
    cudaFuncSetAttribute(hgemm<1>, cudaFuncAttributeMaxDynamicSharedMemorySize, 2*BUFB);
    cudaFuncSetAttribute(hgemm<2>, cudaFuncAttributeMaxDynamicSharedMemorySize, 2*BUFB);
    cudaFuncSetAttribute(hgemm<3>, cudaFuncAttributeMaxDynamicSharedMemorySize, 2*BUFB);

    // tables + weight splits (once per launch)
    tab768<<<(EE*EE + 255)/256, 256>>>();
    tab90 <<<(GWw*GWw + 255)/256, 256>>>();
    tab45 <<<(GHh*GHh + 255)/256, 256>>>();
    split_kernel<<<(EE*PKK + 255)/256, 256>>>(patch_w, pwh, pwl, EE*PKK);
    split_kernel<<<(HDD*EE + 255)/256, 256>>>(head_w, hwh, hwl, HDD*EE);
    split_kernel<<<(12*HID*EE + 255)/256, 256>>>(fc1_w, f1h, f1l, 12*HID*EE);
    split_kernel<<<(12*EE*HID + 255)/256, 256>>>(fc2_w, f2h, f2l, 12*EE*HID);

    const dim3 GB(256);
    const int MT = MPAD/128;   // 32 row tiles
    const int SMB = 2*BUFB;

    // patch embed
    im2col_kernel<<<(NP*PKK + 255)/256, 256>>>(x);
    hgemm<1><<<dim3(EE/128, MT), GB, SMB>>>(pxh, pxl, pwh, pwl, pA, nullptr, nullptr, NP, EE, PKK, patch_b);
    addpos_kernel<<<(NP*EE + 255)/256, 256>>>(pos);

    const int EWGRID = (NP*EE + 255)/256;
    const int FGRID  = (NFREQ*EE + 255)/256;

    for (int l = 0; l < 12; l++) {
        // ---- AFNO half ----
        ln_kernel<<<NP, 256>>>(pA, pT, th, tl, norm1_w + l*EE, norm1_b + l*EE);
        hgemm<0><<<dim3(EE/128, MT), GB, SMB>>>(th, tl, cch, ccl, pPr, nullptr, nullptr, NP, EE, EE, nullptr);
        hgemm<0><<<dim3(EE/128, MT), GB, SMB>>>(th, tl, csh, csl, pPi, nullptr, nullptr, NP, EE, EE, nullptr);
        k_wfwd<<<dim3(6, 45), 128, 2*90*128*4>>>();
        k_hfwd<<<dim3(6, 23), 128, 2*45*128*4>>>();
        gather_n<<<FGRID, 256>>>(pT);
        prep_pm<<<(NBB*BSS*BSS + 255)/256, 256>>>(w1 + (size_t)l*2*NBB*BSS*BSS, w2 + (size_t)l*2*NBB*BSS*BSS);
        prep_ab<<<(NBB*BSS*BSS + 127)/128, 128>>>();
        prep_bs<<<(NBB*BSS + 127)/128, 128>>>(b2 + (size_t)l*2*NBB*BSS);
        k_mix1<<<dim3(8, 69), 96, 85248>>>(b1 + (size_t)l*2*NBB*BSS);
        k_mix2<<<dim3(8, 69), 96, 85248>>>();
        soft_thresh<<<FGRID, 256>>>();
        k_winv<<<dim3(6, 45), 128, 23*128*4>>>();
        k_hinv<<<dim3(6, 90), 128, 2*45*128*4>>>();
        hgemm<0><<<dim3(EE/128, MT), GB, SMB>>>(vrh, vrl, mrh, mrl, pPr, nullptr, nullptr, NP, EE, EE, nullptr);
        hgemm<3><<<dim3(EE/128, MT), GB, SMB>>>(vih, vil, mih, mil, pPr, nullptr, nullptr, NP, EE, EE, nullptr);
        add3_kernel<<<EWGRID, 256>>>();

        // ---- MLP half ----
        ln_kernel<<<NP, 256>>>(pA, pT, th, tl, norm2_w + l*EE, norm2_b + l*EE);
        hgemm<2><<<dim3(HID/128, MT), GB, SMB>>>(th, tl, f1h + (size_t)l*HID*EE, f1l + (size_t)l*HID*EE,
                                                 pPr, hbh, hbl, NP, HID, EE, fc1_b + l*HID);
        hgemm<1><<<dim3(EE/128, MT), GB, SMB>>>(hbh, hbl, f2h + (size_t)l*EE*HID, f2l + (size_t)l*EE*HID,
                                                pPr, nullptr, nullptr, NP, EE, HID, fc2_b + l*EE);
        add2_kernel<<<EWGRID, 256>>>();
    }

    // head
    split_kernel<<<(NP*EE + 255)/256, 256>>>(pA, ah2, al2, NP*EE);
    hgemm<0><<<dim3(HDD/128, MT), GB, SMB>>>(ah2, al2, hwh, hwl, pPX, nullptr, nullptr, NP, HDD, EE, nullptr);
    scatter_out<<<(20736000 + 255)/256, 256>>>(out);
}

// round 7
// speedup vs baseline: 2.2386x; 1.2411x over previous
#include <cuda_runtime.h>
#include <cuda_bf16.h>
#include <math.h>
#include <stdint.h>

// ---------------- constants ----------------
#define GHh 45
#define GWw 90
#define NP 4050          // tokens
#define MPAD 4096        // padded token rows
#define EE 768
#define KM 23
#define NFREQ (GHh*KM)   // 1035
#define FPAD 1152        // padded freq rows (9*128)
#define HID 3072
#define PKK 5120
#define HDD 5120
#define NBB 8
#define BSS 96
#define DHT_SIZE 3110400.0

// ---------------- fp32 scratch ----------------
__device__ __align__(128) float g_px[(size_t)NP*HDD];
__device__ __align__(128) float g_A [NP*EE];
__device__ __align__(128) float g_t [NP*EE];
__device__ __align__(128) float g_T [NP*EE];        // inverse C-stage out (1035 x 1536 view)
__device__ __align__(128) float g_Qr[NFREQ*EE];
__device__ __align__(128) float g_Qi[NFREQ*EE];
__device__ __align__(128) float g_Ur[NP*EE];
__device__ __align__(128) float g_Ui[NP*EE];
__device__ __align__(128) float g_a [NFREQ*EE];
__device__ __align__(128) float g_n [NFREQ*EE];
__device__ __align__(128) float g_o1k[NFREQ*EE];
__device__ __align__(128) float g_o1n[NFREQ*EE];
// small DFT tables
__device__ __align__(128) float g_WC[GWw*GWw];
__device__ __align__(128) float g_WS[GWw*GWw];
__device__ __align__(128) float g_HC[GHh*GHh];
__device__ __align__(128) float g_HS[GHh*GHh];
__device__ __align__(128) float g_HCm[GHh*GHh];
__device__ __align__(128) float g_HCp[GHh*GHh];
// per-layer prepped block weights
__device__ __align__(128) float g_W1p[NBB*BSS*BSS], g_W1m[NBB*BSS*BSS];
__device__ __align__(128) float g_W2p[NBB*BSS*BSS], g_W2m[NBB*BSS*BSS];
__device__ __align__(128) float g_W2a[NBB*BSS*BSS], g_W2b[NBB*BSS*BSS];
__device__ __align__(128) float g_bs [NBB*BSS];

// ---------------- bf16 split buffers (hi/lo) ----------------
__device__ __align__(128) __nv_bfloat16 g_pxh[(size_t)MPAD*PKK], g_pxl[(size_t)MPAD*PKK];
__device__ __align__(128) __nv_bfloat16 g_th [(size_t)MPAD*EE],  g_tl [(size_t)MPAD*EE];
__device__ __align__(128) __nv_bfloat16 g_hbh[(size_t)MPAD*HID], g_hbl[(size_t)MPAD*HID];
__device__ __align__(128) __nv_bfloat16 g_Ah2[(size_t)MPAD*EE],  g_Al2[(size_t)MPAD*EE];
__device__ __align__(128) __nv_bfloat16 g_q2h[(size_t)FPAD*2*EE], g_q2l[(size_t)FPAD*2*EE];
__device__ __align__(128) __nv_bfloat16 g_sh [(size_t)FPAD*EE],  g_sl [(size_t)FPAD*EE];
// weights / tables
__device__ __align__(128) __nv_bfloat16 g_pwh[EE*PKK],  g_pwl[EE*PKK];
__device__ __align__(128) __nv_bfloat16 g_fBh[EE*2*EE], g_fBl[EE*2*EE];   // fwd C B: [kc][c]=cos-sin, [kc][768+c]=cos+sin
__device__ __align__(128) __nv_bfloat16 g_iBh[2*EE*EE], g_iBl[2*EE*EE];   // inv C B: rows<768 cos, rows>=768 -sin
__device__ __align__(128) __nv_bfloat16 g_f1h[(size_t)12*HID*EE], g_f1l[(size_t)12*HID*EE];
__device__ __align__(128) __nv_bfloat16 g_f2h[(size_t)12*EE*HID], g_f2l[(size_t)12*EE*HID];
__device__ __align__(128) __nv_bfloat16 g_hwh[HDD*EE],  g_hwl[HDD*EE];

// ---------------- helpers ----------------
__device__ __forceinline__ void bsplit(float x, __nv_bfloat16& h, __nv_bfloat16& l) {
    h = __float2bfloat16(x);
    l = __float2bfloat16(x - __bfloat162float(h));
}
__device__ __forceinline__ uint32_t s2u32(const void* p) {
    uint32_t a;
    asm("{ .reg .u64 t; cvta.to.shared.u64 t, %1; cvt.u32.u64 %0, t; }" : "=r"(a) : "l"(p));
    return a;
}
__device__ __forceinline__ void mma_bf16(float* c, const uint32_t* a, const uint32_t* b) {
    asm volatile("mma.sync.aligned.m16n8k16.row.col.f32.bf16.bf16.f32 "
        "{%0,%1,%2,%3}, {%4,%5,%6,%7}, {%8,%9}, {%0,%1,%2,%3};"
        : "+f"(c[0]), "+f"(c[1]), "+f"(c[2]), "+f"(c[3])
        : "r"(a[0]), "r"(a[1]), "r"(a[2]), "r"(a[3]), "r"(b[0]), "r"(b[1]));
}
__device__ __forceinline__ void cpa16(uint32_t dst, const void* src) {
    asm volatile("cp.async.cg.shared.global [%0], [%1], 16;" :: "r"(dst), "l"(src));
}

// ---------------- table init ----------------
__global__ void tabC() {
    int idx = blockIdx.x*256 + threadIdx.x;
    if (idx >= EE*EE) return;
    int kc = idx / EE, c = idx % EE;
    long long m = ((long long)kc * c) % EE;
    double a = 2.0 * (double)m / (double)EE;
    double cs = cospi(a), sn = sinpi(a);
    __nv_bfloat16 h, l;
    bsplit((float)(cs - sn), h, l); g_fBh[kc*2*EE + c]      = h; g_fBl[kc*2*EE + c]      = l;
    bsplit((float)(cs + sn), h, l); g_fBh[kc*2*EE + EE + c] = h; g_fBl[kc*2*EE + EE + c] = l;
    bsplit((float)cs, h, l);        g_iBh[kc*EE + c]        = h; g_iBl[kc*EE + c]        = l;
    bsplit((float)(-sn), h, l);     g_iBh[(EE+kc)*EE + c]   = h; g_iBl[(EE+kc)*EE + c]   = l;
}
__global__ void tab90() {
    int idx = blockIdx.x*256 + threadIdx.x;
    if (idx >= GWw*GWw) return;
    int a = idx / GWw, b = idx % GWw;
    long long m = ((long long)a * b) % GWw;
    double ang = 2.0 * (double)m / (double)GWw;
    g_WC[idx] = (float)cospi(ang);
    g_WS[idx] = (float)sinpi(ang);
}
__global__ void tab45() {
    int idx = blockIdx.x*256 + threadIdx.x;
    if (idx >= GHh*GHh) return;
    int a = idx / GHh, b = idx % GHh;
    long long m = ((long long)a * b) % GHh;
    double ang = 2.0 * (double)m / (double)GHh;
    double cs = cospi(ang), sn = sinpi(ang);
    g_HC[idx]  = (float)cs;
    g_HS[idx]  = (float)sn;
    g_HCm[idx] = (float)((cs - sn) / DHT_SIZE);
    g_HCp[idx] = (float)((cs + sn) / DHT_SIZE);
}

__global__ void split_kernel(const float* __restrict__ in,
                             __nv_bfloat16* __restrict__ oh,
                             __nv_bfloat16* __restrict__ ol, int n) {
    int i = blockIdx.x*256 + threadIdx.x;
    if (i >= n) return;
    __nv_bfloat16 h, l;
    bsplit(in[i], h, l);
    oh[i] = h; ol[i] = l;
}

// ---------------- bf16x3 mma.sync GEMM, tile 128Mx64N, k-chunk 32 ----------------
// MODE: 0=store fp32, 2=bias+GELU->bf16 split, 3=accumulate(+bias) fp32, 4=store+bias+addmat
#define SMSTR 40
#define A_TB (128*SMSTR*2)
#define B_TB (64*SMSTR*2)
#define BUF_B (2*A_TB + 2*B_TB)

template<int MODE>
__global__ void __launch_bounds__(256, 3)
hgemm(const __nv_bfloat16* __restrict__ Ah, const __nv_bfloat16* __restrict__ Al,
      const __nv_bfloat16* __restrict__ Bh, const __nv_bfloat16* __restrict__ Bl,
      float* __restrict__ C,
      __nv_bfloat16* __restrict__ Csh, __nv_bfloat16* __restrict__ Csl,
      int Mtrue, int N, int K, const float* __restrict__ bias,
      const float* __restrict__ addm)
{
    extern __shared__ __align__(128) char smem[];
    const int t = threadIdx.x, warp = t >> 5, lane = t & 31;
    const int wm = warp >> 1, wn = warp & 1;
    const int bm = blockIdx.y * 128, bn = blockIdx.x * 64;
    const uint32_t sb = s2u32(smem);

    float acc[2][4][4];
    #pragma unroll
    for (int i = 0; i < 2; i++)
        #pragma unroll
        for (int j = 0; j < 4; j++)
            #pragma unroll
            for (int q = 0; q < 4; q++) acc[i][j][q] = 0.f;

    const int arow = t & 127, ahalf = t >> 7;
    const __nv_bfloat16* pAh = Ah + (size_t)(bm + arow) * K + ahalf * 16;
    const __nv_bfloat16* pAl = Al + (size_t)(bm + arow) * K + ahalf * 16;
    const uint32_t aoff = (uint32_t)(arow * SMSTR + ahalf * 16) * 2;
    const int brow = t >> 2, bseg = t & 3;
    const __nv_bfloat16* pBh = Bh + (size_t)(bn + brow) * K + bseg * 8;
    const __nv_bfloat16* pBl = Bl + (size_t)(bn + brow) * K + bseg * 8;
    const uint32_t boff = (uint32_t)(brow * SMSTR + bseg * 8) * 2;

    const int nch = K >> 5;
    auto issue = [&](int ch) {
        const int k0 = ch << 5;
        const uint32_t dst = sb + (uint32_t)(ch & 1) * BUF_B;
        cpa16(dst + aoff,        pAh + k0); cpa16(dst + aoff + 16,        pAh + k0 + 8);
        cpa16(dst + A_TB + aoff, pAl + k0); cpa16(dst + A_TB + aoff + 16, pAl + k0 + 8);
        cpa16(dst + 2*A_TB + boff,        pBh + k0);
        cpa16(dst + 2*A_TB + B_TB + boff, pBl + k0);
        asm volatile("cp.async.commit_group;" ::: "memory");
    };

    issue(0);
    for (int ch = 0; ch < nch; ch++) {
        const bool more = (ch + 1) < nch;
        if (more) { issue(ch + 1); asm volatile("cp.async.wait_group 1;" ::: "memory"); }
        else      { asm volatile("cp.async.wait_group 0;" ::: "memory"); }
        __syncthreads();

        const uint32_t bufb = sb + (uint32_t)(ch & 1) * BUF_B;
        const uint32_t tAh = bufb, tAl = bufb + A_TB;
        const uint32_t tBh = bufb + 2*A_TB, tBl = bufb + 2*A_TB + B_TB;

        #pragma unroll
        for (int step = 0; step < 2; step++) {
            const int ks = step * 16;
            const int g = lane >> 3, r = lane & 7;
            const uint32_t a_off = (uint32_t)(((g & 1) * 8 + r) * SMSTR + ks + (g >> 1) * 8) * 2;
            const uint32_t b_off = (uint32_t)(((g >> 1) * 8 + r) * SMSTR + ks + (g & 1) * 8) * 2;

            uint32_t af[2][4], bf[4][2];
            #pragma unroll
            for (int mt = 0; mt < 2; mt++) {
                uint32_t ad = tAh + (uint32_t)((wm*32 + mt*16) * SMSTR) * 2 + a_off;
                asm volatile("ldmatrix.sync.aligned.m8n8.x4.shared.b16 {%0,%1,%2,%3}, [%4];"
                    : "=r"(af[mt][0]), "=r"(af[mt][1]), "=r"(af[mt][2]), "=r"(af[mt][3]) : "r"(ad));
            }
            #pragma unroll
            for (int j = 0; j < 4; j += 2) {
                uint32_t bd = tBh + (uint32_t)((wn*32 + j*8) * SMSTR) * 2 + b_off;
                asm volatile("ldmatrix.sync.aligned.m8n8.x4.shared.b16 {%0,%1,%2,%3}, [%4];"
                    : "=r"(bf[j][0]), "=r"(bf[j][1]), "=r"(bf[j+1][0]), "=r"(bf[j+1][1]) : "r"(bd));
            }
            #pragma unroll
            for (int mt = 0; mt < 2; mt++)
                #pragma unroll
                for (int nt = 0; nt < 4; nt++) mma_bf16(acc[mt][nt], af[mt], bf[nt]);
            #pragma unroll
            for (int j = 0; j < 4; j += 2) {
                uint32_t bd = tBl + (uint32_t)((wn*32 + j*8) * SMSTR) * 2 + b_off;
                asm volatile("ldmatrix.sync.aligned.m8n8.x4.shared.b16 {%0,%1,%2,%3}, [%4];"
                    : "=r"(bf[j][0]), "=r"(bf[j][1]), "=r"(bf[j+1][0]), "=r"(bf[j+1][1]) : "r"(bd));
            }
            #pragma unroll
            for (int mt = 0; mt < 2; mt++)
                #pragma unroll
                for (int nt = 0; nt < 4; nt++) mma_bf16(acc[mt][nt], af[mt], bf[nt]);
            #pragma unroll
            for (int mt = 0; mt < 2; mt++) {
                uint32_t ad = tAl + (uint32_t)((wm*32 + mt*16) * SMSTR) * 2 + a_off;
                asm volatile("ldmatrix.sync.aligned.m8n8.x4.shared.b16 {%0,%1,%2,%3}, [%4];"
                    : "=r"(af[mt][0]), "=r"(af[mt][1]), "=r"(af[mt][2]), "=r"(af[mt][3]) : "r"(ad));
            }
            #pragma unroll
            for (int j = 0; j < 4; j += 2) {
                uint32_t bd = tBh + (uint32_t)((wn*32 + j*8) * SMSTR) * 2 + b_off;
                asm volatile("ldmatrix.sync.aligned.m8n8.x4.shared.b16 {%0,%1,%2,%3}, [%4];"
                    : "=r"(bf[j][0]), "=r"(bf[j][1]), "=r"(bf[j+1][0]), "=r"(bf[j+1][1]) : "r"(bd));
            }
            #pragma unroll
            for (int mt = 0; mt < 2; mt++)
                #pragma unroll
                for (int nt = 0; nt < 4; nt++) mma_bf16(acc[mt][nt], af[mt], bf[nt]);
        }
        __syncthreads();
    }

    #pragma unroll
    for (int mt = 0; mt < 2; mt++) {
        const int r0 = bm + wm*32 + mt*16 + (lane >> 2);
        #pragma unroll
        for (int nt = 0; nt < 4; nt++) {
            const int c0 = bn + wn*32 + nt*8 + (lane & 3)*2;
            float b0 = 0.f, b1 = 0.f;
            if (MODE == 2 || MODE == 3 || MODE == 4) { b0 = bias[c0]; b1 = bias[c0+1]; }
            #pragma unroll
            for (int h = 0; h < 2; h++) {
                const int row = r0 + h*8;
                if (row >= Mtrue) continue;
                float v0 = acc[mt][nt][h*2+0] + b0;
                float v1 = acc[mt][nt][h*2+1] + b1;
                if (MODE == 2) {
                    v0 = 0.5f*v0*(1.0f + erff(v0*0.7071067811865475f));
                    v1 = 0.5f*v1*(1.0f + erff(v1*0.7071067811865475f));
                    __nv_bfloat16 h0, l0, h1, l1;
                    bsplit(v0, h0, l0); bsplit(v1, h1, l1);
                    __nv_bfloat162 hv; hv.x = h0; hv.y = h1;
                    __nv_bfloat162 lv; lv.x = l0; lv.y = l1;
                    *(__nv_bfloat162*)&Csh[(size_t)row*N + c0] = hv;
                    *(__nv_bfloat162*)&Csl[(size_t)row*N + c0] = lv;
                } else if (MODE == 3) {
                    float2* cp = (float2*)&C[(size_t)row*N + c0];
                    float2 old = *cp;
                    old.x += v0; old.y += v1;
                    *cp = old;
                } else if (MODE == 4) {
                    const float2 am = *(const float2*)&addm[(size_t)row*N + c0];
                    float2 fv; fv.x = v0 + am.x; fv.y = v1 + am.y;
                    *(float2*)&C[(size_t)row*N + c0] = fv;
                } else {
                    float2 fv; fv.x = v0; fv.y = v1;
                    *(float2*)&C[(size_t)row*N + c0] = fv;
                }
            }
        }
    }
}

// ---------------- LayerNorm (fp32 out + bf16 split out) ----------------
__global__ void ln_kernel(const float* __restrict__ in, float* __restrict__ out,
                          __nv_bfloat16* __restrict__ oh, __nv_bfloat16* __restrict__ ol,
                          const float* __restrict__ w, const float* __restrict__ b)
{
    int tok = blockIdx.x;
    int tid = threadIdx.x;
    const float* row = in + (size_t)tok*EE;
    float x0 = row[tid], x1 = row[tid+256], x2 = row[tid+512];
    float s  = x0+x1+x2;
    float sq = x0*x0 + x1*x1 + x2*x2;
    #pragma unroll
    for (int o = 16; o > 0; o >>= 1) {
        s  += __shfl_down_sync(0xffffffffu, s,  o);
        sq += __shfl_down_sync(0xffffffffu, sq, o);
    }
    __shared__ float ss[8], ssq[8];
    int warp = tid >> 5, lane = tid & 31;
    if (lane == 0) { ss[warp] = s; ssq[warp] = sq; }
    __syncthreads();
    if (tid == 0) {
        float ts = 0.f, tq = 0.f;
        #pragma unroll
        for (int i = 0; i < 8; i++) { ts += ss[i]; tq += ssq[i]; }
        float m = ts * (1.0f/768.0f);
        float v = tq * (1.0f/768.0f) - m*m;
        ss[0] = m; ssq[0] = rsqrtf(v + 1e-5f);
    }
    __syncthreads();
    float m = ss[0], inv = ssq[0];
    size_t base = (size_t)tok*EE;
    #pragma unroll
    for (int j = 0; j < 3; j++) {
        int o = tid + j*256;
        float y = (j==0?x0:(j==1?x1:x2));
        y = (y - m)*inv*w[o] + b[o];
        out[base + o] = y;
        __nv_bfloat16 h, l; bsplit(y, h, l);
        oh[base + o] = h; ol[base + o] = l;
    }
}

// ---------------- DHT stage kernels ----------------
__global__ void k_wfwd() {
    extern __shared__ float sm[];
    int c0 = blockIdx.x*128, h = blockIdx.y, tid = threadIdx.x;
    for (int w = 0; w < 90; w++) sm[w*128+tid] = g_t[(h*90+w)*EE + c0+tid];
    __syncthreads();
    for (int kw = 0; kw < 23; kw++) {
        float ar = 0.f, ai = 0.f;
        #pragma unroll 6
        for (int w = 0; w < 90; w++) {
            float v = sm[w*128+tid];
            ar += v * g_WC[kw*90+w];
            ai -= v * g_WS[kw*90+w];
        }
        g_Qr[(h*23+kw)*EE + c0+tid] = ar;
        g_Qi[(h*23+kw)*EE + c0+tid] = ai;
    }
}
__global__ void k_hfwd() {
    extern __shared__ float sm[];
    float* sr = sm; float* si = sm + 45*128;
    int c0 = blockIdx.x*128, kw = blockIdx.y, tid = threadIdx.x;
    for (int h = 0; h < 45; h++) {
        sr[h*128+tid] = g_Qr[(h*23+kw)*EE + c0+tid];
        si[h*128+tid] = g_Qi[(h*23+kw)*EE + c0+tid];
    }
    __syncthreads();
    for (int kh = 0; kh < 45; kh++) {
        float qr = 0.f, qi = 0.f;
        #pragma unroll 5
        for (int h = 0; h < 45; h++) {
            float ch = g_HC[kh*45+h], sh = g_HS[kh*45+h];
            float ur = sr[h*128+tid], ui = si[h*128+tid];
            qr += ur*ch + ui*sh;
            qi += ui*ch - ur*sh;
        }
        size_t row = (size_t)(kh*23+kw) * (2*EE);
        __nv_bfloat16 h2, l2;
        bsplit(qr, h2, l2); g_q2h[row + c0+tid] = h2;      g_q2l[row + c0+tid] = l2;
        bsplit(qi, h2, l2); g_q2h[row + EE + c0+tid] = h2; g_q2l[row + EE + c0+tid] = l2;
    }
}
__global__ void k_winv() {
    extern __shared__ float sm[];
    float* tr = sm; float* ti = sm + 23*128;
    int c0 = blockIdx.x*128, hp = blockIdx.y, tid = threadIdx.x;
    for (int wp = 0; wp < 23; wp++) {
        size_t row = (size_t)(hp*23+wp) * (2*EE);
        tr[wp*128+tid] = g_T[row + c0+tid];
        ti[wp*128+tid] = g_T[row + EE + c0+tid];
    }
    __syncthreads();
    for (int b = 0; b < 90; b++) {
        float ur = 0.f, ui = 0.f;
        #pragma unroll
        for (int wp = 0; wp < 23; wp++) {
            float cw = g_WC[b*90+wp], sw = g_WS[b*90+wp];
            float xr = tr[wp*128+tid], xi = ti[wp*128+tid];
            ur += xr*cw + xi*sw;
            ui += xi*cw - xr*sw;
        }
        g_Ur[(hp*90+b)*EE + c0+tid] = ur;
        g_Ui[(hp*90+b)*EE + c0+tid] = ui;
    }
}
__global__ void k_hinv() {
    extern __shared__ float sm[];
    float* sr = sm; float* si = sm + 45*128;
    int c0 = blockIdx.x*128, b = blockIdx.y, tid = threadIdx.x;
    for (int hp = 0; hp < 45; hp++) {
        sr[hp*128+tid] = g_Ur[(hp*90+b)*EE + c0+tid];
        si[hp*128+tid] = g_Ui[(hp*90+b)*EE + c0+tid];
    }
    __syncthreads();
    for (int a = 0; a < 45; a++) {
        float y = 0.f;
        #pragma unroll 5
        for (int hp = 0; hp < 45; hp++) {
            y += sr[hp*128+tid]*g_HCm[a*45+hp] + si[hp*128+tid]*g_HCp[a*45+hp];
        }
        size_t idx = (size_t)(a*90+b)*EE + c0+tid;
        g_A[idx] += y + g_t[idx];
    }
}

// ---------------- misc elementwise ----------------
__global__ void gather_n(const float* __restrict__ t) {
    int idx = blockIdx.x*256 + threadIdx.x;
    if (idx >= NFREQ*EE) return;
    int c = idx % EE; int p = idx / EE;
    int w = p % 23, h = p / 23;
    int sh = (45 - h) % 45;
    int sw = (90 - w) % 90;
    g_n[idx] = t[(size_t)(sh*90 + sw)*EE + c];
}
__global__ void im2col_kernel(const float* __restrict__ x) {
    int idx = blockIdx.x*256 + threadIdx.x;
    if (idx >= NP*PKK) return;
    int p = idx / PKK, k = idx % PKK;
    int c = k >> 8, r = k & 255;
    int ph = r >> 4, pw = r & 15;
    int gh = p / 90, gw = p % 90;
    float v = x[(size_t)c*1036800 + (size_t)(gh*16+ph)*1440 + (gw*16+pw)];
    __nv_bfloat16 h, l; bsplit(v, h, l);
    size_t o = (size_t)p*PKK + k;
    g_pxh[o] = h; g_pxl[o] = l;
}
__global__ void scatter_out(float* __restrict__ out) {
    int idx = blockIdx.x*256 + threadIdx.x;
    if (idx >= 20736000) return;
    int oc = idx / 1036800; int r = idx % 1036800;
    int hh = r / 1440, ww = r % 1440;
    int gh = hh >> 4, ph = hh & 15, gw = ww >> 4, pw = ww & 15;
    out[idx] = g_px[(size_t)(gh*90+gw)*HDD + ph*320 + pw*20 + oc];
}

// ---------------- per-layer block-weight prep ----------------
__global__ void prep_pm(const float* __restrict__ w1l, const float* __restrict__ w2l) {
    int i = blockIdx.x*256 + threadIdx.x;
    if (i >= NBB*BSS*BSS) return;
    const int OFF = NBB*BSS*BSS;
    g_W1p[i] = 0.5f*(w1l[i] + w1l[OFF+i]);
    g_W1m[i] = 0.5f*(w1l[i] - w1l[OFF+i]);
    g_W2p[i] = 0.5f*(w2l[i] + w2l[OFF+i]);
    g_W2m[i] = 0.5f*(w2l[i] - w2l[OFF+i]);
}
__global__ void prep_ab() {
    int idx = blockIdx.x*128 + threadIdx.x;
    if (idx >= NBB*BSS*BSS) return;
    int o = idx % 96;
    int i = (idx / 96) % 96;
    int b = idx / 9216;
    const float* P = g_W2p + b*9216;
    const float* M = g_W2m + b*9216;
    float aa = g_W2p[idx];
    float bb = g_W2m[idx] + g_W2p[idx];
    #pragma unroll 8
    for (int j = 0; j < 96; j++) {
        aa += P[i*96+j] * M[j*96+o];
        bb += M[i*96+j] * M[j*96+o];
    }
    g_W2a[idx] = aa;
    g_W2b[idx] = bb;
}
__global__ void prep_bs(const float* __restrict__ b2l) {
    int idx = blockIdx.x*128 + threadIdx.x;
    if (idx >= NBB*BSS) return;
    int o = idx % 96, b = idx / 96;
    float v = b2l[idx] + b2l[NBB*BSS + idx];
    #pragma unroll 8
    for (int j = 0; j < 96; j++) v += b2l[b*96+j] * g_W2m[(b*96+j)*96+o];
    g_bs[idx] = v;
}

// ---------------- block mixing ----------------
__global__ void k_mix1(const float* __restrict__ b1l) {
    extern __shared__ float sm[];
    float* sWp = sm;
    float* sWm = sm + 9216;
    float* sX  = sm + 18432;
    float* sY  = sX + 1440;
    int b = blockIdx.x, tile = blockIdx.y, o = threadIdx.x;
    for (int i = o; i < 9216; i += 96) { sWp[i] = g_W1p[b*9216+i]; sWm[i] = g_W1m[b*9216+i]; }
    int p0 = tile * 15;
    for (int pp = 0; pp < 15; pp++) {
        sX[pp*96+o] = g_a[(size_t)(p0+pp)*EE + b*96 + o];
        sY[pp*96+o] = g_n[(size_t)(p0+pp)*EE + b*96 + o];
    }
    __syncthreads();
    float bk = b1l[b*96+o], bn = b1l[NBB*BSS + b*96+o];
    for (int pp = 0; pp < 15; pp++) {
        float ak = bk, an = bn;
        #pragma unroll 8
        for (int i = 0; i < 96; i++) {
            float xv = sX[pp*96+i], yv = sY[pp*96+i];
            float wp = sWp[i*96+o], wm = sWm[i*96+o];
            ak += xv*wp + yv*wm;
            an += yv*wp + xv*wm;
        }
        g_o1k[(size_t)(p0+pp)*EE + b*96 + o] = fmaxf(ak, 0.f);
        g_o1n[(size_t)(p0+pp)*EE + b*96 + o] = fmaxf(an, 0.f);
    }
}
__global__ void k_mix2() {
    extern __shared__ float sm[];
    float* sWa = sm;
    float* sWb = sm + 9216;
    float* sX  = sm + 18432;
    float* sY  = sX + 1440;
    int b = blockIdx.x, tile = blockIdx.y, o = threadIdx.x;
    for (int i = o; i < 9216; i += 96) { sWa[i] = g_W2a[b*9216+i]; sWb[i] = g_W2b[b*9216+i]; }
    int p0 = tile * 15;
    for (int pp = 0; pp < 15; pp++) {
        sX[pp*96+o] = g_o1k[(size_t)(p0+pp)*EE + b*96 + o];
        sY[pp*96+o] = g_o1n[(size_t)(p0+pp)*EE + b*96 + o];
    }
    __syncthreads();
    float bsv = g_bs[b*96+o];
    for (int pp = 0; pp < 15; pp++) {
        float acc = bsv;
        #pragma unroll 8
        for (int i = 0; i < 96; i++) {
            acc += sX[pp*96+i]*sWa[i*96+o] + sY[pp*96+i]*sWb[i*96+o];
        }
        float aab = fabsf(acc) - 0.01f;
        float v = (aab > 0.f) ? copysignf(aab, acc) : 0.f;
        __nv_bfloat16 h, l; bsplit(v, h, l);
        size_t idx = (size_t)(p0+pp)*EE + b*96 + o;
        g_sh[idx] = h; g_sl[idx] = l;
    }
}

// ---------------- host orchestration ----------------
extern "C" void kernel_launch(void* const* d_in, const int* in_sizes, int n_in,
                              void* d_out, int out_size)
{
    const float* x        = (const float*)d_in[0];
    const float* patch_w  = (const float*)d_in[1];
    const float* patch_b  = (const float*)d_in[2];
    const float* pos      = (const float*)d_in[3];
    const float* norm1_w  = (const float*)d_in[4];
    const float* norm1_b  = (const float*)d_in[5];
    const float* w1       = (const float*)d_in[6];
    const float* b1       = (const float*)d_in[7];
    const float* w2       = (const float*)d_in[8];
    const float* b2       = (const float*)d_in[9];
    const float* norm2_w  = (const float*)d_in[10];
    const float* norm2_b  = (const float*)d_in[11];
    const float* fc1_w    = (const float*)d_in[12];
    const float* fc1_b    = (const float*)d_in[13];
    const float* fc2_w    = (const float*)d_in[14];
    const float* fc2_b    = (const float*)d_in[15];
    const float* head_w   = (const float*)d_in[16];
    float* out = (float*)d_out;

    float *pPX,*pA,*pT,*pTT,*pa;
    cudaGetSymbolAddress((void**)&pPX, g_px);
    cudaGetSymbolAddress((void**)&pA,  g_A);
    cudaGetSymbolAddress((void**)&pT,  g_t);
    cudaGetSymbolAddress((void**)&pTT, g_T);
    cudaGetSymbolAddress((void**)&pa,  g_a);

    __nv_bfloat16 *pxh,*pxl,*th,*tl,*hbh,*hbl,*ah2,*al2,*q2h,*q2l,*sh,*sl;
    __nv_bfloat16 *pwh,*pwl,*fBh,*fBl,*iBh,*iBl,*f1h,*f1l,*f2h,*f2l,*hwh,*hwl;
    cudaGetSymbolAddress((void**)&pxh, g_pxh);  cudaGetSymbolAddress((void**)&pxl, g_pxl);
    cudaGetSymbolAddress((void**)&th,  g_th);   cudaGetSymbolAddress((void**)&tl,  g_tl);
    cudaGetSymbolAddress((void**)&hbh, g_hbh);  cudaGetSymbolAddress((void**)&hbl, g_hbl);
    cudaGetSymbolAddress((void**)&ah2, g_Ah2);  cudaGetSymbolAddress((void**)&al2, g_Al2);
    cudaGetSymbolAddress((void**)&q2h, g_q2h);  cudaGetSymbolAddress((void**)&q2l, g_q2l);
    cudaGetSymbolAddress((void**)&sh,  g_sh);   cudaGetSymbolAddress((void**)&sl,  g_sl);
    cudaGetSymbolAddress((void**)&pwh, g_pwh);  cudaGetSymbolAddress((void**)&pwl, g_pwl);
    cudaGetSymbolAddress((void**)&fBh, g_fBh);  cudaGetSymbolAddress((void**)&fBl, g_fBl);
    cudaGetSymbolAddress((void**)&iBh, g_iBh);  cudaGetSymbolAddress((void**)&iBl, g_iBl);
    cudaGetSymbolAddress((void**)&f1h, g_f1h);  cudaGetSymbolAddress((void**)&f1l, g_f1l);
    cudaGetSymbolAddress((void**)&f2h, g_f2h);  cudaGetSymbolAddress((void**)&f2l, g_f2l);
    cudaGetSymbolAddress((void**)&hwh, g_hwh);  cudaGetSymbolAddress((void**)&hwl, g_hwl);

    cudaFuncSetAttribute(k_wfwd, cudaFuncAttributeMaxDynamicSharedMemorySize, 90*128*4);
    cudaFuncSetAttribute(k_hfwd, cudaFuncAttributeMaxDynamicSharedMemorySize, 2*45*128*4);
    cudaFuncSetAttribute(k_winv, cudaFuncAttributeMaxDynamicSharedMemorySize, 2*23*128*4);
    cudaFuncSetAttribute(k_hinv, cudaFuncAttributeMaxDynamicSharedMemorySize, 2*45*128*4);
    cudaFuncSetAttribute(k_mix1, cudaFuncAttributeMaxDynamicSharedMemorySize, 85248);
    cudaFuncSetAttribute(k_mix2, cudaFuncAttributeMaxDynamicSharedMemorySize, 85248);
    cudaFuncSetAttribute(hgemm<0>, cudaFuncAttributeMaxDynamicSharedMemorySize, 2*BUF_B);
    cudaFuncSetAttribute(hgemm<2>, cudaFuncAttributeMaxDynamicSharedMemorySize, 2*BUF_B);
    cudaFuncSetAttribute(hgemm<3>, cudaFuncAttributeMaxDynamicSharedMemorySize, 2*BUF_B);
    cudaFuncSetAttribute(hgemm<4>, cudaFuncAttributeMaxDynamicSharedMemorySize, 2*BUF_B);

    // tables + weight splits
    tabC <<<(EE*EE + 255)/256, 256>>>();
    tab90<<<(GWw*GWw + 255)/256, 256>>>();
    tab45<<<(GHh*GHh + 255)/256, 256>>>();
    split_kernel<<<(EE*PKK + 255)/256, 256>>>(patch_w, pwh, pwl, EE*PKK);
    split_kernel<<<(HDD*EE + 255)/256, 256>>>(head_w, hwh, hwl, HDD*EE);
    split_kernel<<<(12*HID*EE + 255)/256, 256>>>(fc1_w, f1h, f1l, 12*HID*EE);
    split_kernel<<<(12*EE*HID + 255)/256, 256>>>(fc2_w, f2h, f2l, 12*EE*HID);

    const dim3 GB(256);
    const int SMB = 2*BUF_B;

    // patch embed (bias + pos fused)
    im2col_kernel<<<(NP*PKK + 255)/256, 256>>>(x);
    hgemm<4><<<dim3(EE/64, MPAD/128), GB, SMB>>>(pxh, pxl, pwh, pwl, pA, nullptr, nullptr,
                                                 NP, EE, PKK, patch_b, pos);

    const int FGRID = (NFREQ*EE + 255)/256;

    for (int l = 0; l < 12; l++) {
        // ---- AFNO half ----
        ln_kernel<<<NP, 256>>>(pA, pT, th, tl, norm1_w + l*EE, norm1_b + l*EE);
        k_wfwd<<<dim3(6, 45), 128, 90*128*4>>>();
        k_hfwd<<<dim3(6, 23), 128, 2*45*128*4>>>();
        // a = [Q2r|Q2i] x fwdB   (M=1035, N=768, K=1536)
        hgemm<0><<<dim3(EE/64, FPAD/128), GB, SMB>>>(q2h, q2l, fBh, fBl, pa, nullptr, nullptr,
                                                     NFREQ, EE, 2*EE, nullptr, nullptr);
        gather_n<<<FGRID, 256>>>(pT);
        prep_pm<<<(NBB*BSS*BSS + 255)/256, 256>>>(w1 + (size_t)l*2*NBB*BSS*BSS, w2 + (size_t)l*2*NBB*BSS*BSS);
        prep_ab<<<(NBB*BSS*BSS + 127)/128, 128>>>();
        prep_bs<<<(NBB*BSS + 127)/128, 128>>>(b2 + (size_t)l*2*NBB*BSS);
        k_mix1<<<dim3(8, 69), 96, 85248>>>(b1 + (size_t)l*2*NBB*BSS);
        k_mix2<<<dim3(8, 69), 96, 85248>>>();
        // T = s x invB  (M=1035, N=1536, K=768)
        hgemm<0><<<dim3((2*EE)/64, FPAD/128), GB, SMB>>>(sh, sl, iBh, iBl, pTT, nullptr, nullptr,
                                                         NFREQ, 2*EE, EE, nullptr, nullptr);
        k_winv<<<dim3(6, 45), 128, 2*23*128*4>>>();
        k_hinv<<<dim3(6, 90), 128, 2*45*128*4>>>();   // fused: A += y + t

        // ---- MLP half ----
        ln_kernel<<<NP, 256>>>(pA, pT, th, tl, norm2_w + l*EE, norm2_b + l*EE);
        hgemm<2><<<dim3(HID/64, MPAD/128), GB, SMB>>>(th, tl, f1h + (size_t)l*HID*EE, f1l + (size_t)l*HID*EE,
                                                      nullptr, hbh, hbl, NP, HID, EE, fc1_b + l*HID, nullptr);
        hgemm<3><<<dim3(EE/64, MPAD/128), GB, SMB>>>(hbh, hbl, f2h + (size_t)l*EE*HID, f2l + (size_t)l*EE*HID,
                                                     pA, nullptr, nullptr, NP, EE, HID, fc2_b + l*EE, nullptr);
    }

    // head
    split_kernel<<<(NP*EE + 255)/256, 256>>>(pA, ah2, al2, NP*EE);
    hgemm<0><<<dim3(HDD/64, MPAD/128), GB, SMB>>>(ah2, al2, hwh, hwl, pPX, nullptr, nullptr,
                                                  NP, HDD, EE, nullptr, nullptr);
    scatter_out<<<(20736000 + 255)/256, 256>>>(out);
}

// round 8
// speedup vs baseline: 2.3112x; 1.0325x over previous
#include <cuda_runtime.h>
#include <cuda_bf16.h>
#include <math.h>
#include <stdint.h>

// ---------------- constants ----------------
#define GHh 45
#define GWw 90
#define NP 4050          // tokens
#define MPAD 4096        // padded token rows
#define EE 768
#define KM 23
#define NFREQ (GHh*KM)   // 1035
#define FPAD 1152        // padded freq rows (9*128)
#define HID 3072
#define PKK 5120
#define HDD 5120
#define NBB 8
#define BSS 96
#define DHT_SIZE 3110400.0

// ---------------- fp32 scratch ----------------
__device__ __align__(128) float g_px[(size_t)NP*HDD];
__device__ __align__(128) float g_A [NP*EE];
__device__ __align__(128) float g_t [NP*EE];
__device__ __align__(128) float g_T [NP*EE];        // inverse C-stage out (1035 x 1536 view)
__device__ __align__(128) float g_Qr[NFREQ*EE];
__device__ __align__(128) float g_Qi[NFREQ*EE];
__device__ __align__(128) float g_Zr[NFREQ*EE];     // inverse H-stage out (small!)
__device__ __align__(128) float g_Zi[NFREQ*EE];
__device__ __align__(128) float g_a [NFREQ*EE];
__device__ __align__(128) float g_o1k[NFREQ*EE];
__device__ __align__(128) float g_o1n[NFREQ*EE];
// small DFT tables
__device__ __align__(128) float g_WC[GWw*GWw];
__device__ __align__(128) float g_WS[GWw*GWw];
__device__ __align__(128) float g_WCm[GWw*GWw];   // (cos-sin)/SIZE
__device__ __align__(128) float g_WCp[GWw*GWw];   // (cos+sin)/SIZE
__device__ __align__(128) float g_HC[GHh*GHh];
__device__ __align__(128) float g_HS[GHh*GHh];
// per-layer prepped block weights
__device__ __align__(128) float g_W1p[NBB*BSS*BSS], g_W1m[NBB*BSS*BSS];
__device__ __align__(128) float g_W2p[NBB*BSS*BSS], g_W2m[NBB*BSS*BSS];
__device__ __align__(128) float g_W2a[NBB*BSS*BSS], g_W2b[NBB*BSS*BSS];
__device__ __align__(128) float g_bs [NBB*BSS];

// ---------------- bf16 split buffers (hi/lo) ----------------
__device__ __align__(128) __nv_bfloat16 g_pxh[(size_t)MPAD*PKK], g_pxl[(size_t)MPAD*PKK];
__device__ __align__(128) __nv_bfloat16 g_th [(size_t)MPAD*EE],  g_tl [(size_t)MPAD*EE];
__device__ __align__(128) __nv_bfloat16 g_hbh[(size_t)MPAD*HID], g_hbl[(size_t)MPAD*HID];
__device__ __align__(128) __nv_bfloat16 g_Ah2[(size_t)MPAD*EE],  g_Al2[(size_t)MPAD*EE];
__device__ __align__(128) __nv_bfloat16 g_q2h[(size_t)FPAD*2*EE], g_q2l[(size_t)FPAD*2*EE];
__device__ __align__(128) __nv_bfloat16 g_sh [(size_t)FPAD*EE],  g_sl [(size_t)FPAD*EE];
// weights / tables
__device__ __align__(128) __nv_bfloat16 g_pwh[EE*PKK],  g_pwl[EE*PKK];
__device__ __align__(128) __nv_bfloat16 g_fBh[EE*2*EE], g_fBl[EE*2*EE];   // fwd C B
__device__ __align__(128) __nv_bfloat16 g_iBh[2*EE*EE], g_iBl[2*EE*EE];   // inv C B
__device__ __align__(128) __nv_bfloat16 g_f1h[(size_t)12*HID*EE], g_f1l[(size_t)12*HID*EE];
__device__ __align__(128) __nv_bfloat16 g_f2h[(size_t)12*EE*HID], g_f2l[(size_t)12*EE*HID];
__device__ __align__(128) __nv_bfloat16 g_hwh[HDD*EE],  g_hwl[HDD*EE];

// ---------------- helpers ----------------
__device__ __forceinline__ void bsplit(float x, __nv_bfloat16& h, __nv_bfloat16& l) {
    h = __float2bfloat16(x);
    l = __float2bfloat16(x - __bfloat162float(h));
}
__device__ __forceinline__ uint32_t s2u32(const void* p) {
    uint32_t a;
    asm("{ .reg .u64 t; cvta.to.shared.u64 t, %1; cvt.u32.u64 %0, t; }" : "=r"(a) : "l"(p));
    return a;
}
__device__ __forceinline__ void mma_bf16(float* c, const uint32_t* a, const uint32_t* b) {
    asm volatile("mma.sync.aligned.m16n8k16.row.col.f32.bf16.bf16.f32 "
        "{%0,%1,%2,%3}, {%4,%5,%6,%7}, {%8,%9}, {%0,%1,%2,%3};"
        : "+f"(c[0]), "+f"(c[1]), "+f"(c[2]), "+f"(c[3])
        : "r"(a[0]), "r"(a[1]), "r"(a[2]), "r"(a[3]), "r"(b[0]), "r"(b[1]));
}
__device__ __forceinline__ void cpa16(uint32_t dst, const void* src) {
    asm volatile("cp.async.cg.shared.global [%0], [%1], 16;" :: "r"(dst), "l"(src));
}
__device__ __forceinline__ void ldsm4(uint32_t* r, uint32_t addr) {
    asm volatile("ldmatrix.sync.aligned.m8n8.x4.shared.b16 {%0,%1,%2,%3}, [%4];"
        : "=r"(r[0]), "=r"(r[1]), "=r"(r[2]), "=r"(r[3]) : "r"(addr));
}

// ---------------- table init ----------------
__global__ void tabC() {
    int idx = blockIdx.x*256 + threadIdx.x;
    if (idx >= EE*EE) return;
    int kc = idx / EE, c = idx % EE;
    long long m = ((long long)kc * c) % EE;
    double a = 2.0 * (double)m / (double)EE;
    double cs = cospi(a), sn = sinpi(a);
    __nv_bfloat16 h, l;
    bsplit((float)(cs - sn), h, l); g_fBh[kc*2*EE + c]      = h; g_fBl[kc*2*EE + c]      = l;
    bsplit((float)(cs + sn), h, l); g_fBh[kc*2*EE + EE + c] = h; g_fBl[kc*2*EE + EE + c] = l;
    bsplit((float)cs, h, l);        g_iBh[kc*EE + c]        = h; g_iBl[kc*EE + c]        = l;
    bsplit((float)(-sn), h, l);     g_iBh[(EE+kc)*EE + c]   = h; g_iBl[(EE+kc)*EE + c]   = l;
}
__global__ void tab90() {
    int idx = blockIdx.x*256 + threadIdx.x;
    if (idx >= GWw*GWw) return;
    int a = idx / GWw, b = idx % GWw;
    long long m = ((long long)a * b) % GWw;
    double ang = 2.0 * (double)m / (double)GWw;
    double cs = cospi(ang), sn = sinpi(ang);
    g_WC[idx]  = (float)cs;
    g_WS[idx]  = (float)sn;
    g_WCm[idx] = (float)((cs - sn) / DHT_SIZE);
    g_WCp[idx] = (float)((cs + sn) / DHT_SIZE);
}
__global__ void tab45() {
    int idx = blockIdx.x*256 + threadIdx.x;
    if (idx >= GHh*GHh) return;
    int a = idx / GHh, b = idx % GHh;
    long long m = ((long long)a * b) % GHh;
    double ang = 2.0 * (double)m / (double)GHh;
    g_HC[idx] = (float)cospi(ang);
    g_HS[idx] = (float)sinpi(ang);
}

__global__ void split_kernel(const float* __restrict__ in,
                             __nv_bfloat16* __restrict__ oh,
                             __nv_bfloat16* __restrict__ ol, int n) {
    int i = blockIdx.x*256 + threadIdx.x;
    if (i >= n) return;
    __nv_bfloat16 h, l;
    bsplit(in[i], h, l);
    oh[i] = h; ol[i] = l;
}

// ---------------- bf16x3 mma.sync GEMM, tile 128Mx64N, k-chunk 32 ----------------
// MODE: 0=store fp32, 2=bias+GELU->bf16 split, 3=accumulate(+bias) fp32,
//       4=store+bias+addmat, 5=accumulate(+bias) fp32 AND emit bf16 split of result
#define SMSTR 40
#define A_TB (128*SMSTR*2)
#define B_TB (64*SMSTR*2)
#define BUF_B (2*A_TB + 2*B_TB)

template<int MODE>
__global__ void __launch_bounds__(256, 3)
hgemm(const __nv_bfloat16* __restrict__ Ah, const __nv_bfloat16* __restrict__ Al,
      const __nv_bfloat16* __restrict__ Bh, const __nv_bfloat16* __restrict__ Bl,
      float* __restrict__ C,
      __nv_bfloat16* __restrict__ Csh, __nv_bfloat16* __restrict__ Csl,
      int Mtrue, int N, int K, const float* __restrict__ bias,
      const float* __restrict__ addm)
{
    extern __shared__ __align__(128) char smem[];
    const int t = threadIdx.x, warp = t >> 5, lane = t & 31;
    const int wm = warp >> 1, wn = warp & 1;
    const int bm = blockIdx.y * 128, bn = blockIdx.x * 64;
    const uint32_t sb = s2u32(smem);

    float acc[2][4][4];
    #pragma unroll
    for (int i = 0; i < 2; i++)
        #pragma unroll
        for (int j = 0; j < 4; j++)
            #pragma unroll
            for (int q = 0; q < 4; q++) acc[i][j][q] = 0.f;

    const int arow = t & 127, ahalf = t >> 7;
    const __nv_bfloat16* pAh = Ah + (size_t)(bm + arow) * K + ahalf * 16;
    const __nv_bfloat16* pAl = Al + (size_t)(bm + arow) * K + ahalf * 16;
    const uint32_t aoff = (uint32_t)(arow * SMSTR + ahalf * 16) * 2;
    const int brow = t >> 2, bseg = t & 3;
    const __nv_bfloat16* pBh = Bh + (size_t)(bn + brow) * K + bseg * 8;
    const __nv_bfloat16* pBl = Bl + (size_t)(bn + brow) * K + bseg * 8;
    const uint32_t boff = (uint32_t)(brow * SMSTR + bseg * 8) * 2;

    const int nch = K >> 5;
    auto issue = [&](int ch) {
        const int k0 = ch << 5;
        const uint32_t dst = sb + (uint32_t)(ch & 1) * BUF_B;
        cpa16(dst + aoff,        pAh + k0); cpa16(dst + aoff + 16,        pAh + k0 + 8);
        cpa16(dst + A_TB + aoff, pAl + k0); cpa16(dst + A_TB + aoff + 16, pAl + k0 + 8);
        cpa16(dst + 2*A_TB + boff,        pBh + k0);
        cpa16(dst + 2*A_TB + B_TB + boff, pBl + k0);
        asm volatile("cp.async.commit_group;" ::: "memory");
    };

    issue(0);
    for (int ch = 0; ch < nch; ch++) {
        const bool more = (ch + 1) < nch;
        if (more) { issue(ch + 1); asm volatile("cp.async.wait_group 1;" ::: "memory"); }
        else      { asm volatile("cp.async.wait_group 0;" ::: "memory"); }
        __syncthreads();

        const uint32_t bufb = sb + (uint32_t)(ch & 1) * BUF_B;
        const uint32_t tAh = bufb, tAl = bufb + A_TB;
        const uint32_t tBh = bufb + 2*A_TB, tBl = bufb + 2*A_TB + B_TB;

        #pragma unroll
        for (int step = 0; step < 2; step++) {
            const int ks = step * 16;
            const int g = lane >> 3, r = lane & 7;
            const uint32_t a_off = (uint32_t)(((g & 1) * 8 + r) * SMSTR + ks + (g >> 1) * 8) * 2;
            const uint32_t b_off = (uint32_t)(((g >> 1) * 8 + r) * SMSTR + ks + (g & 1) * 8) * 2;

            uint32_t ah_[2][4], al_[2][4], bh_[4][2], bl_[4][2];
            #pragma unroll
            for (int mt = 0; mt < 2; mt++) {
                const uint32_t rowb = (uint32_t)((wm*32 + mt*16) * SMSTR) * 2 + a_off;
                ldsm4(ah_[mt], tAh + rowb);
                ldsm4(al_[mt], tAl + rowb);
            }
            #pragma unroll
            for (int j = 0; j < 4; j += 2) {
                const uint32_t rowb = (uint32_t)((wn*32 + j*8) * SMSTR) * 2 + b_off;
                uint32_t tmp[4];
                ldsm4(tmp, tBh + rowb);
                bh_[j][0]=tmp[0]; bh_[j][1]=tmp[1]; bh_[j+1][0]=tmp[2]; bh_[j+1][1]=tmp[3];
                ldsm4(tmp, tBl + rowb);
                bl_[j][0]=tmp[0]; bl_[j][1]=tmp[1]; bl_[j+1][0]=tmp[2]; bl_[j+1][1]=tmp[3];
            }
            #pragma unroll
            for (int mt = 0; mt < 2; mt++)
                #pragma unroll
                for (int nt = 0; nt < 4; nt++) mma_bf16(acc[mt][nt], ah_[mt], bh_[nt]);
            #pragma unroll
            for (int mt = 0; mt < 2; mt++)
                #pragma unroll
                for (int nt = 0; nt < 4; nt++) mma_bf16(acc[mt][nt], al_[mt], bh_[nt]);
            #pragma unroll
            for (int mt = 0; mt < 2; mt++)
                #pragma unroll
                for (int nt = 0; nt < 4; nt++) mma_bf16(acc[mt][nt], ah_[mt], bl_[nt]);
        }
        __syncthreads();
    }

    #pragma unroll
    for (int mt = 0; mt < 2; mt++) {
        const int r0 = bm + wm*32 + mt*16 + (lane >> 2);
        #pragma unroll
        for (int nt = 0; nt < 4; nt++) {
            const int c0 = bn + wn*32 + nt*8 + (lane & 3)*2;
            float b0 = 0.f, b1 = 0.f;
            if (MODE == 2 || MODE == 3 || MODE == 4 || MODE == 5) { b0 = bias[c0]; b1 = bias[c0+1]; }
            #pragma unroll
            for (int h = 0; h < 2; h++) {
                const int row = r0 + h*8;
                if (row >= Mtrue) continue;
                float v0 = acc[mt][nt][h*2+0] + b0;
                float v1 = acc[mt][nt][h*2+1] + b1;
                if (MODE == 2) {
                    v0 = 0.5f*v0*(1.0f + erff(v0*0.7071067811865475f));
                    v1 = 0.5f*v1*(1.0f + erff(v1*0.7071067811865475f));
                    __nv_bfloat16 h0, l0, h1, l1;
                    bsplit(v0, h0, l0); bsplit(v1, h1, l1);
                    __nv_bfloat162 hv; hv.x = h0; hv.y = h1;
                    __nv_bfloat162 lv; lv.x = l0; lv.y = l1;
                    *(__nv_bfloat162*)&Csh[(size_t)row*N + c0] = hv;
                    *(__nv_bfloat162*)&Csl[(size_t)row*N + c0] = lv;
                } else if (MODE == 3) {
                    float2* cp = (float2*)&C[(size_t)row*N + c0];
                    float2 old = *cp;
                    old.x += v0; old.y += v1;
                    *cp = old;
                } else if (MODE == 5) {
                    float2* cp = (float2*)&C[(size_t)row*N + c0];
                    float2 old = *cp;
                    old.x += v0; old.y += v1;
                    *cp = old;
                    __nv_bfloat16 h0, l0, h1, l1;
                    bsplit(old.x, h0, l0); bsplit(old.y, h1, l1);
                    __nv_bfloat162 hv; hv.x = h0; hv.y = h1;
                    __nv_bfloat162 lv; lv.x = l0; lv.y = l1;
                    *(__nv_bfloat162*)&Csh[(size_t)row*N + c0] = hv;
                    *(__nv_bfloat162*)&Csl[(size_t)row*N + c0] = lv;
                } else if (MODE == 4) {
                    const float2 am = *(const float2*)&addm[(size_t)row*N + c0];
                    float2 fv; fv.x = v0 + am.x; fv.y = v1 + am.y;
                    *(float2*)&C[(size_t)row*N + c0] = fv;
                } else {
                    float2 fv; fv.x = v0; fv.y = v1;
                    *(float2*)&C[(size_t)row*N + c0] = fv;
                }
            }
        }
    }
}

// ---------------- LayerNorm variants ----------------
// common reduction; WRITE: 0 = fp32 only, 1 = bf16 splits only
template<int WRITE>
__global__ void ln_kernel(const float* __restrict__ in, float* __restrict__ out,
                          __nv_bfloat16* __restrict__ oh, __nv_bfloat16* __restrict__ ol,
                          const float* __restrict__ w, const float* __restrict__ b)
{
    int tok = blockIdx.x;
    int tid = threadIdx.x;
    const float* row = in + (size_t)tok*EE;
    float x0 = row[tid], x1 = row[tid+256], x2 = row[tid+512];
    float s  = x0+x1+x2;
    float sq = x0*x0 + x1*x1 + x2*x2;
    #pragma unroll
    for (int o = 16; o > 0; o >>= 1) {
        s  += __shfl_down_sync(0xffffffffu, s,  o);
        sq += __shfl_down_sync(0xffffffffu, sq, o);
    }
    __shared__ float ss[8], ssq[8];
    int warp = tid >> 5, lane = tid & 31;
    if (lane == 0) { ss[warp] = s; ssq[warp] = sq; }
    __syncthreads();
    if (tid == 0) {
        float ts = 0.f, tq = 0.f;
        #pragma unroll
        for (int i = 0; i < 8; i++) { ts += ss[i]; tq += ssq[i]; }
        float m = ts * (1.0f/768.0f);
        float v = tq * (1.0f/768.0f) - m*m;
        ss[0] = m; ssq[0] = rsqrtf(v + 1e-5f);
    }
    __syncthreads();
    float m = ss[0], inv = ssq[0];
    size_t base = (size_t)tok*EE;
    #pragma unroll
    for (int j = 0; j < 3; j++) {
        int o = tid + j*256;
        float y = (j==0?x0:(j==1?x1:x2));
        y = (y - m)*inv*w[o] + b[o];
        if (WRITE == 0) {
            out[base + o] = y;
        } else {
            __nv_bfloat16 h, l; bsplit(y, h, l);
            oh[base + o] = h; ol[base + o] = l;
        }
    }
}

// ---------------- DHT stage kernels ----------------
__global__ void k_wfwd() {
    extern __shared__ float sm[];
    int c0 = blockIdx.x*128, h = blockIdx.y, tid = threadIdx.x;
    for (int w = 0; w < 90; w++) sm[w*128+tid] = g_t[(h*90+w)*EE + c0+tid];
    __syncthreads();
    for (int kw = 0; kw < 23; kw++) {
        float ar = 0.f, ai = 0.f;
        #pragma unroll 6
        for (int w = 0; w < 90; w++) {
            float v = sm[w*128+tid];
            ar += v * g_WC[kw*90+w];
            ai -= v * g_WS[kw*90+w];
        }
        g_Qr[(h*23+kw)*EE + c0+tid] = ar;
        g_Qi[(h*23+kw)*EE + c0+tid] = ai;
    }
}
__global__ void k_hfwd() {
    extern __shared__ float sm[];
    float* sr = sm; float* si = sm + 45*128;
    int c0 = blockIdx.x*128, kw = blockIdx.y, tid = threadIdx.x;
    for (int h = 0; h < 45; h++) {
        sr[h*128+tid] = g_Qr[(h*23+kw)*EE + c0+tid];
        si[h*128+tid] = g_Qi[(h*23+kw)*EE + c0+tid];
    }
    __syncthreads();
    for (int kh = 0; kh < 45; kh++) {
        float qr = 0.f, qi = 0.f;
        #pragma unroll 5
        for (int h = 0; h < 45; h++) {
            float ch = g_HC[kh*45+h], sh = g_HS[kh*45+h];
            float ur = sr[h*128+tid], ui = si[h*128+tid];
            qr += ur*ch + ui*sh;
            qi += ui*ch - ur*sh;
        }
        size_t row = (size_t)(kh*23+kw) * (2*EE);
        __nv_bfloat16 h2, l2;
        bsplit(qr, h2, l2); g_q2h[row + c0+tid] = h2;      g_q2l[row + c0+tid] = l2;
        bsplit(qi, h2, l2); g_q2h[row + EE + c0+tid] = h2; g_q2l[row + EE + c0+tid] = l2;
    }
}
// inverse H-stage FIRST: T(hp,wp complex) -> Z(a,wp complex), still 1035 rows
__global__ void k_hinv2() {
    extern __shared__ float sm[];
    float* tr = sm; float* ti = sm + 45*128;
    int c0 = blockIdx.x*128, wp = blockIdx.y, tid = threadIdx.x;
    for (int hp = 0; hp < 45; hp++) {
        size_t row = (size_t)(hp*23+wp) * (2*EE);
        tr[hp*128+tid] = g_T[row + c0+tid];
        ti[hp*128+tid] = g_T[row + EE + c0+tid];
    }
    __syncthreads();
    for (int a = 0; a < 45; a++) {
        float zr = 0.f, zi = 0.f;
        #pragma unroll 5
        for (int hp = 0; hp < 45; hp++) {
            float ch = g_HC[a*45+hp], sh = g_HS[a*45+hp];
            float xr = tr[hp*128+tid], xi = ti[hp*128+tid];
            zr += xr*ch + xi*sh;
            zi += xi*ch - xr*sh;
        }
        g_Zr[(a*23+wp)*EE + c0+tid] = zr;
        g_Zi[(a*23+wp)*EE + c0+tid] = zi;
    }
}
// inverse W-stage LAST with Re+Im combine, /size, fused residual: A += y + t
__global__ void k_winv2() {
    extern __shared__ float sm[];
    float* zr = sm; float* zi = sm + 23*128;
    int c0 = blockIdx.x*128, a = blockIdx.y, tid = threadIdx.x;
    for (int wp = 0; wp < 23; wp++) {
        zr[wp*128+tid] = g_Zr[(a*23+wp)*EE + c0+tid];
        zi[wp*128+tid] = g_Zi[(a*23+wp)*EE + c0+tid];
    }
    __syncthreads();
    for (int b = 0; b < 90; b++) {
        float y = 0.f;
        #pragma unroll
        for (int wp = 0; wp < 23; wp++) {
            y += zr[wp*128+tid]*g_WCm[b*90+wp] + zi[wp*128+tid]*g_WCp[b*90+wp];
        }
        size_t idx = (size_t)(a*90+b)*EE + c0+tid;
        g_A[idx] += y + g_t[idx];
    }
}

// ---------------- misc elementwise ----------------
__global__ void im2col_kernel(const float* __restrict__ x) {
    int idx = blockIdx.x*256 + threadIdx.x;
    if (idx >= NP*PKK) return;
    int p = idx / PKK, k = idx % PKK;
    int c = k >> 8, r = k & 255;
    int ph = r >> 4, pw = r & 15;
    int gh = p / 90, gw = p % 90;
    float v = x[(size_t)c*1036800 + (size_t)(gh*16+ph)*1440 + (gw*16+pw)];
    __nv_bfloat16 h, l; bsplit(v, h, l);
    size_t o = (size_t)p*PKK + k;
    g_pxh[o] = h; g_pxl[o] = l;
}
__global__ void scatter_out(float* __restrict__ out) {
    int idx = blockIdx.x*256 + threadIdx.x;
    if (idx >= 20736000) return;
    int oc = idx / 1036800; int r = idx % 1036800;
    int hh = r / 1440, ww = r % 1440;
    int gh = hh >> 4, ph = hh & 15, gw = ww >> 4, pw = ww & 15;
    out[idx] = g_px[(size_t)(gh*90+gw)*HDD + ph*320 + pw*20 + oc];
}

// ---------------- per-layer block-weight prep ----------------
__global__ void prep_pm(const float* __restrict__ w1l, const float* __restrict__ w2l) {
    int i = blockIdx.x*256 + threadIdx.x;
    if (i >= NBB*BSS*BSS) return;
    const int OFF = NBB*BSS*BSS;
    g_W1p[i] = 0.5f*(w1l[i] + w1l[OFF+i]);
    g_W1m[i] = 0.5f*(w1l[i] - w1l[OFF+i]);
    g_W2p[i] = 0.5f*(w2l[i] + w2l[OFF+i]);
    g_W2m[i] = 0.5f*(w2l[i] - w2l[OFF+i]);
}
__global__ void prep_ab() {
    int idx = blockIdx.x*128 + threadIdx.x;
    if (idx >= NBB*BSS*BSS) return;
    int o = idx % 96;
    int i = (idx / 96) % 96;
    int b = idx / 9216;
    const float* P = g_W2p + b*9216;
    const float* M = g_W2m + b*9216;
    float aa = g_W2p[idx];
    float bb = g_W2m[idx] + g_W2p[idx];
    #pragma unroll 8
    for (int j = 0; j < 96; j++) {
        aa += P[i*96+j] * M[j*96+o];
        bb += M[i*96+j] * M[j*96+o];
    }
    g_W2a[idx] = aa;
    g_W2b[idx] = bb;
}
__global__ void prep_bs(const float* __restrict__ b2l) {
    int idx = blockIdx.x*128 + threadIdx.x;
    if (idx >= NBB*BSS) return;
    int o = idx % 96, b = idx / 96;
    float v = b2l[idx] + b2l[NBB*BSS + idx];
    #pragma unroll 8
    for (int j = 0; j < 96; j++) v += b2l[b*96+j] * g_W2m[(b*96+j)*96+o];
    g_bs[idx] = v;
}

// ---------------- block mixing (288 threads; gather fused into mix1) ----------------
__global__ void k_mix1(const float* __restrict__ b1l) {
    extern __shared__ float sm[];
    float* sWp = sm;
    float* sWm = sm + 9216;
    float* sX  = sm + 18432;          // 15*96
    float* sY  = sX + 1440;
    int b = blockIdx.x, tile = blockIdx.y;
    int t = threadIdx.x;              // 288
    int o = t % 96, rg = t / 96;      // rg 0..2
    for (int i = t; i < 9216; i += 288) { sWp[i] = g_W1p[b*9216+i]; sWm[i] = g_W1m[b*9216+i]; }
    int p0 = tile * 15;
    for (int pp = rg; pp < 15; pp += 3) {
        int p = p0 + pp;
        int h = p / 23, w = p % 23;
        int sh = (45 - h) % 45;
        int sw = (90 - w) % 90;
        sX[pp*96+o] = g_a[(size_t)p*EE + b*96 + o];
        sY[pp*96+o] = g_t[(size_t)(sh*90 + sw)*EE + b*96 + o];   // fused gather_n
    }
    __syncthreads();
    float bk = b1l[b*96+o], bn = b1l[NBB*BSS + b*96+o];
    for (int pp = rg; pp < 15; pp += 3) {
        float ak = bk, an = bn;
        #pragma unroll 8
        for (int i = 0; i < 96; i++) {
            float xv = sX[pp*96+i], yv = sY[pp*96+i];
            float wp = sWp[i*96+o], wm = sWm[i*96+o];
            ak += xv*wp + yv*wm;
            an += yv*wp + xv*wm;
        }
        g_o1k[(size_t)(p0+pp)*EE + b*96 + o] = fmaxf(ak, 0.f);
        g_o1n[(size_t)(p0+pp)*EE + b*96 + o] = fmaxf(an, 0.f);
    }
}
__global__ void k_mix2() {
    extern __shared__ float sm[];
    float* sWa = sm;
    float* sWb = sm + 9216;
    float* sX  = sm + 18432;
    float* sY  = sX + 1440;
    int b = blockIdx.x, tile = blockIdx.y;
    int t = threadIdx.x;
    int o = t % 96, rg = t / 96;
    for (int i = t; i < 9216; i += 288) { sWa[i] = g_W2a[b*9216+i]; sWb[i] = g_W2b[b*9216+i]; }
    int p0 = tile * 15;
    for (int pp = rg; pp < 15; pp += 3) {
        sX[pp*96+o] = g_o1k[(size_t)(p0+pp)*EE + b*96 + o];
        sY[pp*96+o] = g_o1n[(size_t)(p0+pp)*EE + b*96 + o];
    }
    __syncthreads();
    float bsv = g_bs[b*96+o];
    for (int pp = rg; pp < 15; pp += 3) {
        float acc = bsv;
        #pragma unroll 8
        for (int i = 0; i < 96; i++) {
            acc += sX[pp*96+i]*sWa[i*96+o] + sY[pp*96+i]*sWb[i*96+o];
        }
        float aab = fabsf(acc) - 0.01f;
        float v = (aab > 0.f) ? copysignf(aab, acc) : 0.f;
        __nv_bfloat16 h, l; bsplit(v, h, l);
        size_t idx = (size_t)(p0+pp)*EE + b*96 + o;
        g_sh[idx] = h; g_sl[idx] = l;
    }
}

// ---------------- host orchestration ----------------
extern "C" void kernel_launch(void* const* d_in, const int* in_sizes, int n_in,
                              void* d_out, int out_size)
{
    const float* x        = (const float*)d_in[0];
    const float* patch_w  = (const float*)d_in[1];
    const float* patch_b  = (const float*)d_in[2];
    const float* pos      = (const float*)d_in[3];
    const float* norm1_w  = (const float*)d_in[4];
    const float* norm1_b  = (const float*)d_in[5];
    const float* w1       = (const float*)d_in[6];
    const float* b1       = (const float*)d_in[7];
    const float* w2       = (const float*)d_in[8];
    const float* b2       = (const float*)d_in[9];
    const float* norm2_w  = (const float*)d_in[10];
    const float* norm2_b  = (const float*)d_in[11];
    const float* fc1_w    = (const float*)d_in[12];
    const float* fc1_b    = (const float*)d_in[13];
    const float* fc2_w    = (const float*)d_in[14];
    const float* fc2_b    = (const float*)d_in[15];
    const float* head_w   = (const float*)d_in[16];
    float* out = (float*)d_out;

    float *pPX,*pA,*pT,*pTT,*pa;
    cudaGetSymbolAddress((void**)&pPX, g_px);
    cudaGetSymbolAddress((void**)&pA,  g_A);
    cudaGetSymbolAddress((void**)&pT,  g_t);
    cudaGetSymbolAddress((void**)&pTT, g_T);
    cudaGetSymbolAddress((void**)&pa,  g_a);

    __nv_bfloat16 *pxh,*pxl,*th,*tl,*hbh,*hbl,*ah2,*al2,*q2h,*q2l,*sh,*sl;
    __nv_bfloat16 *pwh,*pwl,*fBh,*fBl,*iBh,*iBl,*f1h,*f1l,*f2h,*f2l,*hwh,*hwl;
    cudaGetSymbolAddress((void**)&pxh, g_pxh);  cudaGetSymbolAddress((void**)&pxl, g_pxl);
    cudaGetSymbolAddress((void**)&th,  g_th);   cudaGetSymbolAddress((void**)&tl,  g_tl);
    cudaGetSymbolAddress((void**)&hbh, g_hbh);  cudaGetSymbolAddress((void**)&hbl, g_hbl);
    cudaGetSymbolAddress((void**)&ah2, g_Ah2);  cudaGetSymbolAddress((void**)&al2, g_Al2);
    cudaGetSymbolAddress((void**)&q2h, g_q2h);  cudaGetSymbolAddress((void**)&q2l, g_q2l);
    cudaGetSymbolAddress((void**)&sh,  g_sh);   cudaGetSymbolAddress((void**)&sl,  g_sl);
    cudaGetSymbolAddress((void**)&pwh, g_pwh);  cudaGetSymbolAddress((void**)&pwl, g_pwl);
    cudaGetSymbolAddress((void**)&fBh, g_fBh);  cudaGetSymbolAddress((void**)&fBl, g_fBl);
    cudaGetSymbolAddress((void**)&iBh, g_iBh);  cudaGetSymbolAddress((void**)&iBl, g_iBl);
    cudaGetSymbolAddress((void**)&f1h, g_f1h);  cudaGetSymbolAddress((void**)&f1l, g_f1l);
    cudaGetSymbolAddress((void**)&f2h, g_f2h);  cudaGetSymbolAddress((void**)&f2l, g_f2l);
    cudaGetSymbolAddress((void**)&hwh, g_hwh);  cudaGetSymbolAddress((void**)&hwl, g_hwl);

    cudaFuncSetAttribute(k_wfwd,  cudaFuncAttributeMaxDynamicSharedMemorySize, 90*128*4);
    cudaFuncSetAttribute(k_hfwd,  cudaFuncAttributeMaxDynamicSharedMemorySize, 2*45*128*4);
    cudaFuncSetAttribute(k_hinv2, cudaFuncAttributeMaxDynamicSharedMemorySize, 2*45*128*4);
    cudaFuncSetAttribute(k_winv2, cudaFuncAttributeMaxDynamicSharedMemorySize, 2*23*128*4);
    cudaFuncSetAttribute(k_mix1,  cudaFuncAttributeMaxDynamicSharedMemorySize, 85248);
    cudaFuncSetAttribute(k_mix2,  cudaFuncAttributeMaxDynamicSharedMemorySize, 85248);
    cudaFuncSetAttribute(hgemm<0>, cudaFuncAttributeMaxDynamicSharedMemorySize, 2*BUF_B);
    cudaFuncSetAttribute(hgemm<2>, cudaFuncAttributeMaxDynamicSharedMemorySize, 2*BUF_B);
    cudaFuncSetAttribute(hgemm<3>, cudaFuncAttributeMaxDynamicSharedMemorySize, 2*BUF_B);
    cudaFuncSetAttribute(hgemm<4>, cudaFuncAttributeMaxDynamicSharedMemorySize, 2*BUF_B);
    cudaFuncSetAttribute(hgemm<5>, cudaFuncAttributeMaxDynamicSharedMemorySize, 2*BUF_B);

    // tables + weight splits
    tabC <<<(EE*EE + 255)/256, 256>>>();
    tab90<<<(GWw*GWw + 255)/256, 256>>>();
    tab45<<<(GHh*GHh + 255)/256, 256>>>();
    split_kernel<<<(EE*PKK + 255)/256, 256>>>(patch_w, pwh, pwl, EE*PKK);
    split_kernel<<<(HDD*EE + 255)/256, 256>>>(head_w, hwh, hwl, HDD*EE);
    split_kernel<<<(12*HID*EE + 255)/256, 256>>>(fc1_w, f1h, f1l, 12*HID*EE);
    split_kernel<<<(12*EE*HID + 255)/256, 256>>>(fc2_w, f2h, f2l, 12*EE*HID);

    const dim3 GB(256);
    const int SMB = 2*BUF_B;

    // patch embed (bias + pos fused)
    im2col_kernel<<<(NP*PKK + 255)/256, 256>>>(x);
    hgemm<4><<<dim3(EE/64, MPAD/128), GB, SMB>>>(pxh, pxl, pwh, pwl, pA, nullptr, nullptr,
                                                 NP, EE, PKK, patch_b, pos);

    for (int l = 0; l < 12; l++) {
        // ---- AFNO half ----
        ln_kernel<0><<<NP, 256>>>(pA, pT, nullptr, nullptr, norm1_w + l*EE, norm1_b + l*EE);
        k_wfwd<<<dim3(6, 45), 128, 90*128*4>>>();
        k_hfwd<<<dim3(6, 23), 128, 2*45*128*4>>>();
        hgemm<0><<<dim3(EE/64, FPAD/128), GB, SMB>>>(q2h, q2l, fBh, fBl, pa, nullptr, nullptr,
                                                     NFREQ, EE, 2*EE, nullptr, nullptr);
        prep_pm<<<(NBB*BSS*BSS + 255)/256, 256>>>(w1 + (size_t)l*2*NBB*BSS*BSS, w2 + (size_t)l*2*NBB*BSS*BSS);
        prep_ab<<<(NBB*BSS*BSS + 127)/128, 128>>>();
        prep_bs<<<(NBB*BSS + 127)/128, 128>>>(b2 + (size_t)l*2*NBB*BSS);
        k_mix1<<<dim3(8, 69), 288, 85248>>>(b1 + (size_t)l*2*NBB*BSS);
        k_mix2<<<dim3(8, 69), 288, 85248>>>();
        hgemm<0><<<dim3((2*EE)/64, FPAD/128), GB, SMB>>>(sh, sl, iBh, iBl, pTT, nullptr, nullptr,
                                                         NFREQ, 2*EE, EE, nullptr, nullptr);
        k_hinv2<<<dim3(6, 23), 128, 2*45*128*4>>>();
        k_winv2<<<dim3(6, 45), 128, 2*23*128*4>>>();   // fused: A += y + t

        // ---- MLP half ----
        ln_kernel<1><<<NP, 256>>>(pA, nullptr, th, tl, norm2_w + l*EE, norm2_b + l*EE);
        hgemm<2><<<dim3(HID/64, MPAD/128), GB, SMB>>>(th, tl, f1h + (size_t)l*HID*EE, f1l + (size_t)l*HID*EE,
                                                      nullptr, hbh, hbl, NP, HID, EE, fc1_b + l*HID, nullptr);
        if (l < 11) {
            hgemm<3><<<dim3(EE/64, MPAD/128), GB, SMB>>>(hbh, hbl, f2h + (size_t)l*EE*HID, f2l + (size_t)l*EE*HID,
                                                         pA, nullptr, nullptr, NP, EE, HID, fc2_b + l*EE, nullptr);
        } else {
            hgemm<5><<<dim3(EE/64, MPAD/128), GB, SMB>>>(hbh, hbl, f2h + (size_t)l*EE*HID, f2l + (size_t)l*EE*HID,
                                                         pA, ah2, al2, NP, EE, HID, fc2_b + l*EE, nullptr);
        }
    }

    // head (A splits already emitted by last fc2)
    hgemm<0><<<dim3(HDD/64, MPAD/128), GB, SMB>>>(ah2, al2, hwh, hwl, pPX, nullptr, nullptr,
                                                  NP, HDD, EE, nullptr, nullptr);
    scatter_out<<<(20736000 + 255)/256, 256>>>(out);
}

// round 9
// speedup vs baseline: 2.3139x; 1.0012x over previous
#include <cuda_runtime.h>
#include <cuda_bf16.h>
#include <math.h>
#include <stdint.h>

// ---------------- constants ----------------
#define GHh 45
#define GWw 90
#define NP 4050          // tokens
#define MPAD 4096        // padded token rows
#define EE 768
#define KM 23
#define NFREQ (GHh*KM)   // 1035
#define FPAD 1152        // padded freq rows (9*128)
#define HID 3072
#define PKK 5120
#define HDD 5120
#define NBB 8
#define BSS 96
#define BLK (NBB*BSS*BSS)   // 73728 per layer
#define DHT_SIZE 3110400.0

// ---------------- fp32 scratch ----------------
__device__ __align__(128) float g_px[(size_t)NP*HDD];
__device__ __align__(128) float g_A [NP*EE];
__device__ __align__(128) float g_t [NP*EE];
__device__ __align__(128) float g_T [NP*EE];        // inverse C-stage out (1035 x 1536 view)
__device__ __align__(128) float g_Qr[NFREQ*EE];
__device__ __align__(128) float g_Qi[NFREQ*EE];
__device__ __align__(128) float g_Zr[NFREQ*EE];
__device__ __align__(128) float g_Zi[NFREQ*EE];
__device__ __align__(128) float g_a [NFREQ*EE];
// small DFT tables
__device__ __align__(128) float g_WC[GWw*GWw];
__device__ __align__(128) float g_WS[GWw*GWw];
__device__ __align__(128) float g_WCm[GWw*GWw];   // (cos-sin)/SIZE
__device__ __align__(128) float g_WCp[GWw*GWw];   // (cos+sin)/SIZE
__device__ __align__(128) float g_HC[GHh*GHh];
__device__ __align__(128) float g_HS[GHh*GHh];
// per-layer prepped block weights (ALL 12 layers, hoisted)
__device__ __align__(128) float g_W1p[12*BLK], g_W1m[12*BLK];
__device__ __align__(128) float g_W2p[12*BLK], g_W2m[12*BLK];
__device__ __align__(128) float g_W2a[12*BLK], g_W2b[12*BLK];
__device__ __align__(128) float g_bs [12*NBB*BSS];

// ---------------- bf16 split buffers (hi/lo) ----------------
__device__ __align__(128) __nv_bfloat16 g_pxh[(size_t)MPAD*PKK], g_pxl[(size_t)MPAD*PKK];
__device__ __align__(128) __nv_bfloat16 g_th [(size_t)MPAD*EE],  g_tl [(size_t)MPAD*EE];
__device__ __align__(128) __nv_bfloat16 g_hbh[(size_t)MPAD*HID], g_hbl[(size_t)MPAD*HID];
__device__ __align__(128) __nv_bfloat16 g_Ah2[(size_t)MPAD*EE],  g_Al2[(size_t)MPAD*EE];
__device__ __align__(128) __nv_bfloat16 g_q2h[(size_t)FPAD*2*EE], g_q2l[(size_t)FPAD*2*EE];
__device__ __align__(128) __nv_bfloat16 g_sh [(size_t)FPAD*EE],  g_sl [(size_t)FPAD*EE];
// weights / tables
__device__ __align__(128) __nv_bfloat16 g_pwh[EE*PKK],  g_pwl[EE*PKK];
__device__ __align__(128) __nv_bfloat16 g_fBh[EE*2*EE], g_fBl[EE*2*EE];   // fwd C B
__device__ __align__(128) __nv_bfloat16 g_iBh[2*EE*EE], g_iBl[2*EE*EE];   // inv C B
__device__ __align__(128) __nv_bfloat16 g_f1h[(size_t)12*HID*EE], g_f1l[(size_t)12*HID*EE];
__device__ __align__(128) __nv_bfloat16 g_f2h[(size_t)12*EE*HID], g_f2l[(size_t)12*EE*HID];
__device__ __align__(128) __nv_bfloat16 g_hwh[HDD*EE],  g_hwl[HDD*EE];

// ---------------- helpers ----------------
__device__ __forceinline__ void bsplit(float x, __nv_bfloat16& h, __nv_bfloat16& l) {
    h = __float2bfloat16(x);
    l = __float2bfloat16(x - __bfloat162float(h));
}
__device__ __forceinline__ uint32_t s2u32(const void* p) {
    uint32_t a;
    asm("{ .reg .u64 t; cvta.to.shared.u64 t, %1; cvt.u32.u64 %0, t; }" : "=r"(a) : "l"(p));
    return a;
}
__device__ __forceinline__ void mma_bf16(float* c, const uint32_t* a, const uint32_t* b) {
    asm volatile("mma.sync.aligned.m16n8k16.row.col.f32.bf16.bf16.f32 "
        "{%0,%1,%2,%3}, {%4,%5,%6,%7}, {%8,%9}, {%0,%1,%2,%3};"
        : "+f"(c[0]), "+f"(c[1]), "+f"(c[2]), "+f"(c[3])
        : "r"(a[0]), "r"(a[1]), "r"(a[2]), "r"(a[3]), "r"(b[0]), "r"(b[1]));
}
__device__ __forceinline__ void cpa16(uint32_t dst, const void* src) {
    asm volatile("cp.async.cg.shared.global [%0], [%1], 16;" :: "r"(dst), "l"(src));
}
__device__ __forceinline__ void ldsm4(uint32_t* r, uint32_t addr) {
    asm volatile("ldmatrix.sync.aligned.m8n8.x4.shared.b16 {%0,%1,%2,%3}, [%4];"
        : "=r"(r[0]), "=r"(r[1]), "=r"(r[2]), "=r"(r[3]) : "r"(addr));
}

// ---------------- table init ----------------
__global__ void tabC() {
    int idx = blockIdx.x*256 + threadIdx.x;
    if (idx >= EE*EE) return;
    int kc = idx / EE, c = idx % EE;
    long long m = ((long long)kc * c) % EE;
    double a = 2.0 * (double)m / (double)EE;
    double cs = cospi(a), sn = sinpi(a);
    __nv_bfloat16 h, l;
    bsplit((float)(cs - sn), h, l); g_fBh[kc*2*EE + c]      = h; g_fBl[kc*2*EE + c]      = l;
    bsplit((float)(cs + sn), h, l); g_fBh[kc*2*EE + EE + c] = h; g_fBl[kc*2*EE + EE + c] = l;
    bsplit((float)cs, h, l);        g_iBh[kc*EE + c]        = h; g_iBl[kc*EE + c]        = l;
    bsplit((float)(-sn), h, l);     g_iBh[(EE+kc)*EE + c]   = h; g_iBl[(EE+kc)*EE + c]   = l;
}
__global__ void tab90() {
    int idx = blockIdx.x*256 + threadIdx.x;
    if (idx >= GWw*GWw) return;
    int a = idx / GWw, b = idx % GWw;
    long long m = ((long long)a * b) % GWw;
    double ang = 2.0 * (double)m / (double)GWw;
    double cs = cospi(ang), sn = sinpi(ang);
    g_WC[idx]  = (float)cs;
    g_WS[idx]  = (float)sn;
    g_WCm[idx] = (float)((cs - sn) / DHT_SIZE);
    g_WCp[idx] = (float)((cs + sn) / DHT_SIZE);
}
__global__ void tab45() {
    int idx = blockIdx.x*256 + threadIdx.x;
    if (idx >= GHh*GHh) return;
    int a = idx / GHh, b = idx % GHh;
    long long m = ((long long)a * b) % GHh;
    double ang = 2.0 * (double)m / (double)GHh;
    g_HC[idx] = (float)cospi(ang);
    g_HS[idx] = (float)sinpi(ang);
}

__global__ void split_kernel(const float* __restrict__ in,
                             __nv_bfloat16* __restrict__ oh,
                             __nv_bfloat16* __restrict__ ol, int n) {
    int i = blockIdx.x*256 + threadIdx.x;
    if (i >= n) return;
    __nv_bfloat16 h, l;
    bsplit(in[i], h, l);
    oh[i] = h; ol[i] = l;
}

// ---------------- bf16x3 mma.sync GEMM, tile 128Mx64N, k-chunk 32 ----------------
// MODE: 0=store fp32, 2=bias+GELU->bf16 split, 3=accumulate(+bias) fp32,
//       4=store+bias+addmat, 5=accumulate(+bias) fp32 AND emit bf16 split of result
#define SMSTR 40
#define A_TB (128*SMSTR*2)
#define B_TB (64*SMSTR*2)
#define BUF_B (2*A_TB + 2*B_TB)

template<int MODE>
__global__ void __launch_bounds__(256, 3)
hgemm(const __nv_bfloat16* __restrict__ Ah, const __nv_bfloat16* __restrict__ Al,
      const __nv_bfloat16* __restrict__ Bh, const __nv_bfloat16* __restrict__ Bl,
      float* __restrict__ C,
      __nv_bfloat16* __restrict__ Csh, __nv_bfloat16* __restrict__ Csl,
      int Mtrue, int N, int K, const float* __restrict__ bias,
      const float* __restrict__ addm)
{
    extern __shared__ __align__(128) char smem[];
    const int t = threadIdx.x, warp = t >> 5, lane = t & 31;
    const int wm = warp >> 1, wn = warp & 1;
    const int bm = blockIdx.y * 128, bn = blockIdx.x * 64;
    const uint32_t sb = s2u32(smem);

    float acc[2][4][4];
    #pragma unroll
    for (int i = 0; i < 2; i++)
        #pragma unroll
        for (int j = 0; j < 4; j++)
            #pragma unroll
            for (int q = 0; q < 4; q++) acc[i][j][q] = 0.f;

    const int arow = t & 127, ahalf = t >> 7;
    const __nv_bfloat16* pAh = Ah + (size_t)(bm + arow) * K + ahalf * 16;
    const __nv_bfloat16* pAl = Al + (size_t)(bm + arow) * K + ahalf * 16;
    const uint32_t aoff = (uint32_t)(arow * SMSTR + ahalf * 16) * 2;
    const int brow = t >> 2, bseg = t & 3;
    const __nv_bfloat16* pBh = Bh + (size_t)(bn + brow) * K + bseg * 8;
    const __nv_bfloat16* pBl = Bl + (size_t)(bn + brow) * K + bseg * 8;
    const uint32_t boff = (uint32_t)(brow * SMSTR + bseg * 8) * 2;

    const int nch = K >> 5;
    auto issue = [&](int ch) {
        const int k0 = ch << 5;
        const uint32_t dst = sb + (uint32_t)(ch & 1) * BUF_B;
        cpa16(dst + aoff,        pAh + k0); cpa16(dst + aoff + 16,        pAh + k0 + 8);
        cpa16(dst + A_TB + aoff, pAl + k0); cpa16(dst + A_TB + aoff + 16, pAl + k0 + 8);
        cpa16(dst + 2*A_TB + boff,        pBh + k0);
        cpa16(dst + 2*A_TB + B_TB + boff, pBl + k0);
        asm volatile("cp.async.commit_group;" ::: "memory");
    };

    issue(0);
    for (int ch = 0; ch < nch; ch++) {
        const bool more = (ch + 1) < nch;
        if (more) { issue(ch + 1); asm volatile("cp.async.wait_group 1;" ::: "memory"); }
        else      { asm volatile("cp.async.wait_group 0;" ::: "memory"); }
        __syncthreads();

        const uint32_t bufb = sb + (uint32_t)(ch & 1) * BUF_B;
        const uint32_t tAh = bufb, tAl = bufb + A_TB;
        const uint32_t tBh = bufb + 2*A_TB, tBl = bufb + 2*A_TB + B_TB;

        #pragma unroll
        for (int step = 0; step < 2; step++) {
            const int ks = step * 16;
            const int g = lane >> 3, r = lane & 7;
            const uint32_t a_off = (uint32_t)(((g & 1) * 8 + r) * SMSTR + ks + (g >> 1) * 8) * 2;
            const uint32_t b_off = (uint32_t)(((g >> 1) * 8 + r) * SMSTR + ks + (g & 1) * 8) * 2;

            uint32_t ah_[2][4], al_[2][4], bh_[4][2], bl_[4][2];
            #pragma unroll
            for (int mt = 0; mt < 2; mt++) {
                const uint32_t rowb = (uint32_t)((wm*32 + mt*16) * SMSTR) * 2 + a_off;
                ldsm4(ah_[mt], tAh + rowb);
                ldsm4(al_[mt], tAl + rowb);
            }
            #pragma unroll
            for (int j = 0; j < 4; j += 2) {
                const uint32_t rowb = (uint32_t)((wn*32 + j*8) * SMSTR) * 2 + b_off;
                uint32_t tmp[4];
                ldsm4(tmp, tBh + rowb);
                bh_[j][0]=tmp[0]; bh_[j][1]=tmp[1]; bh_[j+1][0]=tmp[2]; bh_[j+1][1]=tmp[3];
                ldsm4(tmp, tBl + rowb);
                bl_[j][0]=tmp[0]; bl_[j][1]=tmp[1]; bl_[j+1][0]=tmp[2]; bl_[j+1][1]=tmp[3];
            }
            #pragma unroll
            for (int mt = 0; mt < 2; mt++)
                #pragma unroll
                for (int nt = 0; nt < 4; nt++) mma_bf16(acc[mt][nt], ah_[mt], bh_[nt]);
            #pragma unroll
            for (int mt = 0; mt < 2; mt++)
                #pragma unroll
                for (int nt = 0; nt < 4; nt++) mma_bf16(acc[mt][nt], al_[mt], bh_[nt]);
            #pragma unroll
            for (int mt = 0; mt < 2; mt++)
                #pragma unroll
                for (int nt = 0; nt < 4; nt++) mma_bf16(acc[mt][nt], ah_[mt], bl_[nt]);
        }
        __syncthreads();
    }

    #pragma unroll
    for (int mt = 0; mt < 2; mt++) {
        const int r0 = bm + wm*32 + mt*16 + (lane >> 2);
        #pragma unroll
        for (int nt = 0; nt < 4; nt++) {
            const int c0 = bn + wn*32 + nt*8 + (lane & 3)*2;
            float b0 = 0.f, b1 = 0.f;
            if (MODE == 2 || MODE == 3 || MODE == 4 || MODE == 5) { b0 = bias[c0]; b1 = bias[c0+1]; }
            #pragma unroll
            for (int h = 0; h < 2; h++) {
                const int row = r0 + h*8;
                if (row >= Mtrue) continue;
                float v0 = acc[mt][nt][h*2+0] + b0;
                float v1 = acc[mt][nt][h*2+1] + b1;
                if (MODE == 2) {
                    v0 = 0.5f*v0*(1.0f + erff(v0*0.7071067811865475f));
                    v1 = 0.5f*v1*(1.0f + erff(v1*0.7071067811865475f));
                    __nv_bfloat16 h0, l0, h1, l1;
                    bsplit(v0, h0, l0); bsplit(v1, h1, l1);
                    __nv_bfloat162 hv; hv.x = h0; hv.y = h1;
                    __nv_bfloat162 lv; lv.x = l0; lv.y = l1;
                    *(__nv_bfloat162*)&Csh[(size_t)row*N + c0] = hv;
                    *(__nv_bfloat162*)&Csl[(size_t)row*N + c0] = lv;
                } else if (MODE == 3) {
                    float2* cp = (float2*)&C[(size_t)row*N + c0];
                    float2 old = *cp;
                    old.x += v0; old.y += v1;
                    *cp = old;
                } else if (MODE == 5) {
                    float2* cp = (float2*)&C[(size_t)row*N + c0];
                    float2 old = *cp;
                    old.x += v0; old.y += v1;
                    *cp = old;
                    __nv_bfloat16 h0, l0, h1, l1;
                    bsplit(old.x, h0, l0); bsplit(old.y, h1, l1);
                    __nv_bfloat162 hv; hv.x = h0; hv.y = h1;
                    __nv_bfloat162 lv; lv.x = l0; lv.y = l1;
                    *(__nv_bfloat162*)&Csh[(size_t)row*N + c0] = hv;
                    *(__nv_bfloat162*)&Csl[(size_t)row*N + c0] = lv;
                } else if (MODE == 4) {
                    const float2 am = *(const float2*)&addm[(size_t)row*N + c0];
                    float2 fv; fv.x = v0 + am.x; fv.y = v1 + am.y;
                    *(float2*)&C[(size_t)row*N + c0] = fv;
                } else {
                    float2 fv; fv.x = v0; fv.y = v1;
                    *(float2*)&C[(size_t)row*N + c0] = fv;
                }
            }
        }
    }
}

// ---------------- LayerNorm variants ----------------
template<int WRITE>
__global__ void ln_kernel(const float* __restrict__ in, float* __restrict__ out,
                          __nv_bfloat16* __restrict__ oh, __nv_bfloat16* __restrict__ ol,
                          const float* __restrict__ w, const float* __restrict__ b)
{
    int tok = blockIdx.x;
    int tid = threadIdx.x;
    const float* row = in + (size_t)tok*EE;
    float x0 = row[tid], x1 = row[tid+256], x2 = row[tid+512];
    float s  = x0+x1+x2;
    float sq = x0*x0 + x1*x1 + x2*x2;
    #pragma unroll
    for (int o = 16; o > 0; o >>= 1) {
        s  += __shfl_down_sync(0xffffffffu, s,  o);
        sq += __shfl_down_sync(0xffffffffu, sq, o);
    }
    __shared__ float ss[8], ssq[8];
    int warp = tid >> 5, lane = tid & 31;
    if (lane == 0) { ss[warp] = s; ssq[warp] = sq; }
    __syncthreads();
    if (tid == 0) {
        float ts = 0.f, tq = 0.f;
        #pragma unroll
        for (int i = 0; i < 8; i++) { ts += ss[i]; tq += ssq[i]; }
        float m = ts * (1.0f/768.0f);
        float v = tq * (1.0f/768.0f) - m*m;
        ss[0] = m; ssq[0] = rsqrtf(v + 1e-5f);
    }
    __syncthreads();
    float m = ss[0], inv = ssq[0];
    size_t base = (size_t)tok*EE;
    #pragma unroll
    for (int j = 0; j < 3; j++) {
        int o = tid + j*256;
        float y = (j==0?x0:(j==1?x1:x2));
        y = (y - m)*inv*w[o] + b[o];
        if (WRITE == 0) {
            out[base + o] = y;
        } else {
            __nv_bfloat16 h, l; bsplit(y, h, l);
            oh[base + o] = h; ol[base + o] = l;
        }
    }
}

// ---------------- DHT stage kernels ----------------
__global__ void k_wfwd() {
    extern __shared__ float sm[];
    int c0 = blockIdx.x*128, h = blockIdx.y, tid = threadIdx.x;
    for (int w = 0; w < 90; w++) sm[w*128+tid] = g_t[(h*90+w)*EE + c0+tid];
    __syncthreads();
    for (int kw = 0; kw < 23; kw++) {
        float ar = 0.f, ai = 0.f;
        #pragma unroll 6
        for (int w = 0; w < 90; w++) {
            float v = sm[w*128+tid];
            ar += v * g_WC[kw*90+w];
            ai -= v * g_WS[kw*90+w];
        }
        g_Qr[(h*23+kw)*EE + c0+tid] = ar;
        g_Qi[(h*23+kw)*EE + c0+tid] = ai;
    }
}
__global__ void k_hfwd() {
    extern __shared__ float sm[];
    float* sr = sm; float* si = sm + 45*128;
    int c0 = blockIdx.x*128, kw = blockIdx.y, tid = threadIdx.x;
    for (int h = 0; h < 45; h++) {
        sr[h*128+tid] = g_Qr[(h*23+kw)*EE + c0+tid];
        si[h*128+tid] = g_Qi[(h*23+kw)*EE + c0+tid];
    }
    __syncthreads();
    for (int kh = 0; kh < 45; kh++) {
        float qr = 0.f, qi = 0.f;
        #pragma unroll 5
        for (int h = 0; h < 45; h++) {
            float ch = g_HC[kh*45+h], sh = g_HS[kh*45+h];
            float ur = sr[h*128+tid], ui = si[h*128+tid];
            qr += ur*ch + ui*sh;
            qi += ui*ch - ur*sh;
        }
        size_t row = (size_t)(kh*23+kw) * (2*EE);
        __nv_bfloat16 h2, l2;
        bsplit(qr, h2, l2); g_q2h[row + c0+tid] = h2;      g_q2l[row + c0+tid] = l2;
        bsplit(qi, h2, l2); g_q2h[row + EE + c0+tid] = h2; g_q2l[row + EE + c0+tid] = l2;
    }
}
__global__ void k_hinv2() {
    extern __shared__ float sm[];
    float* tr = sm; float* ti = sm + 45*128;
    int c0 = blockIdx.x*128, wp = blockIdx.y, tid = threadIdx.x;
    for (int hp = 0; hp < 45; hp++) {
        size_t row = (size_t)(hp*23+wp) * (2*EE);
        tr[hp*128+tid] = g_T[row + c0+tid];
        ti[hp*128+tid] = g_T[row + EE + c0+tid];
    }
    __syncthreads();
    for (int a = 0; a < 45; a++) {
        float zr = 0.f, zi = 0.f;
        #pragma unroll 5
        for (int hp = 0; hp < 45; hp++) {
            float ch = g_HC[a*45+hp], sh = g_HS[a*45+hp];
            float xr = tr[hp*128+tid], xi = ti[hp*128+tid];
            zr += xr*ch + xi*sh;
            zi += xi*ch - xr*sh;
        }
        g_Zr[(a*23+wp)*EE + c0+tid] = zr;
        g_Zi[(a*23+wp)*EE + c0+tid] = zi;
    }
}
__global__ void k_winv2() {
    extern __shared__ float sm[];
    float* zr = sm; float* zi = sm + 23*128;
    int c0 = blockIdx.x*128, a = blockIdx.y, tid = threadIdx.x;
    for (int wp = 0; wp < 23; wp++) {
        zr[wp*128+tid] = g_Zr[(a*23+wp)*EE + c0+tid];
        zi[wp*128+tid] = g_Zi[(a*23+wp)*EE + c0+tid];
    }
    __syncthreads();
    for (int b = 0; b < 90; b++) {
        float y = 0.f;
        #pragma unroll
        for (int wp = 0; wp < 23; wp++) {
            y += zr[wp*128+tid]*g_WCm[b*90+wp] + zi[wp*128+tid]*g_WCp[b*90+wp];
        }
        size_t idx = (size_t)(a*90+b)*EE + c0+tid;
        g_A[idx] += y + g_t[idx];
    }
}

// ---------------- misc elementwise ----------------
__global__ void im2col_kernel(const float* __restrict__ x) {
    int idx = blockIdx.x*256 + threadIdx.x;
    if (idx >= NP*PKK) return;
    int p = idx / PKK, k = idx % PKK;
    int c = k >> 8, r = k & 255;
    int ph = r >> 4, pw = r & 15;
    int gh = p / 90, gw = p % 90;
    float v = x[(size_t)c*1036800 + (size_t)(gh*16+ph)*1440 + (gw*16+pw)];
    __nv_bfloat16 h, l; bsplit(v, h, l);
    size_t o = (size_t)p*PKK + k;
    g_pxh[o] = h; g_pxl[o] = l;
}
__global__ void scatter_out(float* __restrict__ out) {
    int idx = blockIdx.x*256 + threadIdx.x;
    if (idx >= 20736000) return;
    int oc = idx / 1036800; int r = idx % 1036800;
    int hh = r / 1440, ww = r % 1440;
    int gh = hh >> 4, ph = hh & 15, gw = ww >> 4, pw = ww & 15;
    out[idx] = g_px[(size_t)(gh*90+gw)*HDD + ph*320 + pw*20 + oc];
}

// ---------------- block-weight prep, ALL layers hoisted ----------------
__global__ void prep_pm_all(const float* __restrict__ w1, const float* __restrict__ w2) {
    int idx = blockIdx.x*256 + threadIdx.x;
    if (idx >= 12*BLK) return;
    int l = idx / BLK, i = idx % BLK;
    const float* w1l = w1 + (size_t)l*2*BLK;
    const float* w2l = w2 + (size_t)l*2*BLK;
    g_W1p[idx] = 0.5f*(w1l[i] + w1l[BLK+i]);
    g_W1m[idx] = 0.5f*(w1l[i] - w1l[BLK+i]);
    g_W2p[idx] = 0.5f*(w2l[i] + w2l[BLK+i]);
    g_W2m[idx] = 0.5f*(w2l[i] - w2l[BLK+i]);
}
__global__ void prep_ab_all() {
    int idx = blockIdx.x*128 + threadIdx.x;
    if (idx >= 12*BLK) return;
    int l = idx / BLK, rr = idx % BLK;
    int o = rr % 96;
    int i = (rr / 96) % 96;
    int b = rr / 9216;
    const float* P = g_W2p + (size_t)l*BLK + b*9216;
    const float* M = g_W2m + (size_t)l*BLK + b*9216;
    float aa = g_W2p[idx];
    float bb = g_W2m[idx] + g_W2p[idx];
    #pragma unroll 8
    for (int j = 0; j < 96; j++) {
        aa += P[i*96+j] * M[j*96+o];
        bb += M[i*96+j] * M[j*96+o];
    }
    g_W2a[idx] = aa;
    g_W2b[idx] = bb;
}
__global__ void prep_bs_all(const float* __restrict__ b2) {
    int idx = blockIdx.x*128 + threadIdx.x;
    if (idx >= 12*NBB*BSS) return;
    int l = idx / (NBB*BSS), rr = idx % (NBB*BSS);
    int o = rr % 96, b = rr / 96;
    const float* b2l = b2 + (size_t)l*2*NBB*BSS;
    float v = b2l[rr] + b2l[NBB*BSS + rr];
    const float* M = g_W2m + (size_t)l*BLK;
    #pragma unroll 8
    for (int j = 0; j < 96; j++) v += b2l[b*96+j] * M[(b*96+j)*96+o];
    g_bs[idx] = v;
}

// ---------------- fused block mixing (mix1 + mix2 + soft-thresh + split) ----------------
// grid (8 blocks b, 23 tiles of 45 freq-rows), 288 threads
#define MROWS 45
#define MIXSM ((9216*2 + MROWS*96*2)*4)   // 108288 bytes
__global__ void k_mixf(const float* __restrict__ b1l, int loff, int lbs) {
    extern __shared__ float sm[];
    float* sW1 = sm;                 // 9216: W1p then W2a
    float* sW2 = sm + 9216;          // 9216: W1m then W2b
    float* sX  = sm + 18432;         // 45*96
    float* sY  = sX + MROWS*96;
    int b = blockIdx.x, tile = blockIdx.y;
    int t = threadIdx.x;
    int o = t % 96, rg = t / 96;     // rg 0..2
    for (int i = t; i < 9216; i += 288) {
        sW1[i] = g_W1p[loff + b*9216+i];
        sW2[i] = g_W1m[loff + b*9216+i];
    }
    int p0 = tile * MROWS;
    for (int pp = rg; pp < MROWS; pp += 3) {
        int p = p0 + pp;
        int h = p / 23, w = p % 23;
        int shh = (45 - h) % 45;
        int sww = (90 - w) % 90;
        sX[pp*96+o] = g_a[(size_t)p*EE + b*96 + o];
        sY[pp*96+o] = g_t[(size_t)(shh*90 + sww)*EE + b*96 + o];
    }
    __syncthreads();
    float bk = b1l[b*96+o], bn = b1l[NBB*BSS + b*96+o];
    float ok_[15], on_[15];
    {
        int c = 0;
        for (int pp = rg; pp < MROWS; pp += 3, c++) {
            float ak = bk, an = bn;
            #pragma unroll 8
            for (int i = 0; i < 96; i++) {
                float xv = sX[pp*96+i], yv = sY[pp*96+i];
                float wp = sW1[i*96+o], wm = sW2[i*96+o];
                ak += xv*wp + yv*wm;
                an += yv*wp + xv*wm;
            }
            ok_[c] = fmaxf(ak, 0.f);
            on_[c] = fmaxf(an, 0.f);
        }
    }
    __syncthreads();
    {
        int c = 0;
        for (int pp = rg; pp < MROWS; pp += 3, c++) {
            sX[pp*96+o] = ok_[c];
            sY[pp*96+o] = on_[c];
        }
    }
    for (int i = t; i < 9216; i += 288) {
        sW1[i] = g_W2a[loff + b*9216+i];
        sW2[i] = g_W2b[loff + b*9216+i];
    }
    __syncthreads();
    float bsv = g_bs[lbs + b*96+o];
    for (int pp = rg; pp < MROWS; pp += 3) {
        float acc = bsv;
        #pragma unroll 8
        for (int i = 0; i < 96; i++) {
            acc += sX[pp*96+i]*sW1[i*96+o] + sY[pp*96+i]*sW2[i*96+o];
        }
        float aab = fabsf(acc) - 0.01f;
        float v = (aab > 0.f) ? copysignf(aab, acc) : 0.f;
        __nv_bfloat16 h, l; bsplit(v, h, l);
        size_t idx = (size_t)(p0+pp)*EE + b*96 + o;
        g_sh[idx] = h; g_sl[idx] = l;
    }
}

// ---------------- host orchestration ----------------
extern "C" void kernel_launch(void* const* d_in, const int* in_sizes, int n_in,
                              void* d_out, int out_size)
{
    const float* x        = (const float*)d_in[0];
    const float* patch_w  = (const float*)d_in[1];
    const float* patch_b  = (const float*)d_in[2];
    const float* pos      = (const float*)d_in[3];
    const float* norm1_w  = (const float*)d_in[4];
    const float* norm1_b  = (const float*)d_in[5];
    const float* w1       = (const float*)d_in[6];
    const float* b1       = (const float*)d_in[7];
    const float* w2       = (const float*)d_in[8];
    const float* b2       = (const float*)d_in[9];
    const float* norm2_w  = (const float*)d_in[10];
    const float* norm2_b  = (const float*)d_in[11];
    const float* fc1_w    = (const float*)d_in[12];
    const float* fc1_b    = (const float*)d_in[13];
    const float* fc2_w    = (const float*)d_in[14];
    const float* fc2_b    = (const float*)d_in[15];
    const float* head_w   = (const float*)d_in[16];
    float* out = (float*)d_out;

    float *pPX,*pA,*pT,*pTT,*pa;
    cudaGetSymbolAddress((void**)&pPX, g_px);
    cudaGetSymbolAddress((void**)&pA,  g_A);
    cudaGetSymbolAddress((void**)&pT,  g_t);
    cudaGetSymbolAddress((void**)&pTT, g_T);
    cudaGetSymbolAddress((void**)&pa,  g_a);

    __nv_bfloat16 *pxh,*pxl,*th,*tl,*hbh,*hbl,*ah2,*al2,*q2h,*q2l,*sh,*sl;
    __nv_bfloat16 *pwh,*pwl,*fBh,*fBl,*iBh,*iBl,*f1h,*f1l,*f2h,*f2l,*hwh,*hwl;
    cudaGetSymbolAddress((void**)&pxh, g_pxh);  cudaGetSymbolAddress((void**)&pxl, g_pxl);
    cudaGetSymbolAddress((void**)&th,  g_th);   cudaGetSymbolAddress((void**)&tl,  g_tl);
    cudaGetSymbolAddress((void**)&hbh, g_hbh);  cudaGetSymbolAddress((void**)&hbl, g_hbl);
    cudaGetSymbolAddress((void**)&ah2, g_Ah2);  cudaGetSymbolAddress((void**)&al2, g_Al2);
    cudaGetSymbolAddress((void**)&q2h, g_q2h);  cudaGetSymbolAddress((void**)&q2l, g_q2l);
    cudaGetSymbolAddress((void**)&sh,  g_sh);   cudaGetSymbolAddress((void**)&sl,  g_sl);
    cudaGetSymbolAddress((void**)&pwh, g_pwh);  cudaGetSymbolAddress((void**)&pwl, g_pwl);
    cudaGetSymbolAddress((void**)&fBh, g_fBh);  cudaGetSymbolAddress((void**)&fBl, g_fBl);
    cudaGetSymbolAddress((void**)&iBh, g_iBh);  cudaGetSymbolAddress((void**)&iBl, g_iBl);
    cudaGetSymbolAddress((void**)&f1h, g_f1h);  cudaGetSymbolAddress((void**)&f1l, g_f1l);
    cudaGetSymbolAddress((void**)&f2h, g_f2h);  cudaGetSymbolAddress((void**)&f2l, g_f2l);
    cudaGetSymbolAddress((void**)&hwh, g_hwh);  cudaGetSymbolAddress((void**)&hwl, g_hwl);

    cudaFuncSetAttribute(k_wfwd,  cudaFuncAttributeMaxDynamicSharedMemorySize, 90*128*4);
    cudaFuncSetAttribute(k_hfwd,  cudaFuncAttributeMaxDynamicSharedMemorySize, 2*45*128*4);
    cudaFuncSetAttribute(k_hinv2, cudaFuncAttributeMaxDynamicSharedMemorySize, 2*45*128*4);
    cudaFuncSetAttribute(k_winv2, cudaFuncAttributeMaxDynamicSharedMemorySize, 2*23*128*4);
    cudaFuncSetAttribute(k_mixf,  cudaFuncAttributeMaxDynamicSharedMemorySize, MIXSM);
    cudaFuncSetAttribute(hgemm<0>, cudaFuncAttributeMaxDynamicSharedMemorySize, 2*BUF_B);
    cudaFuncSetAttribute(hgemm<2>, cudaFuncAttributeMaxDynamicSharedMemorySize, 2*BUF_B);
    cudaFuncSetAttribute(hgemm<3>, cudaFuncAttributeMaxDynamicSharedMemorySize, 2*BUF_B);
    cudaFuncSetAttribute(hgemm<4>, cudaFuncAttributeMaxDynamicSharedMemorySize, 2*BUF_B);
    cudaFuncSetAttribute(hgemm<5>, cudaFuncAttributeMaxDynamicSharedMemorySize, 2*BUF_B);

    // tables + weight splits + ALL-layer block-weight prep (once)
    tabC <<<(EE*EE + 255)/256, 256>>>();
    tab90<<<(GWw*GWw + 255)/256, 256>>>();
    tab45<<<(GHh*GHh + 255)/256, 256>>>();
    split_kernel<<<(EE*PKK + 255)/256, 256>>>(patch_w, pwh, pwl, EE*PKK);
    split_kernel<<<(HDD*EE + 255)/256, 256>>>(head_w, hwh, hwl, HDD*EE);
    split_kernel<<<(12*HID*EE + 255)/256, 256>>>(fc1_w, f1h, f1l, 12*HID*EE);
    split_kernel<<<(12*EE*HID + 255)/256, 256>>>(fc2_w, f2h, f2l, 12*EE*HID);
    prep_pm_all<<<(12*BLK + 255)/256, 256>>>(w1, w2);
    prep_ab_all<<<(12*BLK + 127)/128, 128>>>();
    prep_bs_all<<<(12*NBB*BSS + 127)/128, 128>>>(b2);

    const dim3 GB(256);
    const int SMB = 2*BUF_B;

    // patch embed (bias + pos fused)
    im2col_kernel<<<(NP*PKK + 255)/256, 256>>>(x);
    hgemm<4><<<dim3(EE/64, MPAD/128), GB, SMB>>>(pxh, pxl, pwh, pwl, pA, nullptr, nullptr,
                                                 NP, EE, PKK, patch_b, pos);

    for (int l = 0; l < 12; l++) {
        // ---- AFNO half ----
        ln_kernel<0><<<NP, 256>>>(pA, pT, nullptr, nullptr, norm1_w + l*EE, norm1_b + l*EE);
        k_wfwd<<<dim3(6, 45), 128, 90*128*4>>>();
        k_hfwd<<<dim3(6, 23), 128, 2*45*128*4>>>();
        hgemm<0><<<dim3(EE/64, FPAD/128), GB, SMB>>>(q2h, q2l, fBh, fBl, pa, nullptr, nullptr,
                                                     NFREQ, EE, 2*EE, nullptr, nullptr);
        k_mixf<<<dim3(8, 23), 288, MIXSM>>>(b1 + (size_t)l*2*NBB*BSS, l*BLK, l*NBB*BSS);
        hgemm<0><<<dim3((2*EE)/64, FPAD/128), GB, SMB>>>(sh, sl, iBh, iBl, pTT, nullptr, nullptr,
                                                         NFREQ, 2*EE, EE, nullptr, nullptr);
        k_hinv2<<<dim3(6, 23), 128, 2*45*128*4>>>();
        k_winv2<<<dim3(6, 45), 128, 2*23*128*4>>>();   // fused: A += y + t

        // ---- MLP half ----
        ln_kernel<1><<<NP, 256>>>(pA, nullptr, th, tl, norm2_w + l*EE, norm2_b + l*EE);
        hgemm<2><<<dim3(HID/64, MPAD/128), GB, SMB>>>(th, tl, f1h + (size_t)l*HID*EE, f1l + (size_t)l*HID*EE,
                                                      nullptr, hbh, hbl, NP, HID, EE, fc1_b + l*HID, nullptr);
        if (l < 11) {
            hgemm<3><<<dim3(EE/64, MPAD/128), GB, SMB>>>(hbh, hbl, f2h + (size_t)l*EE*HID, f2l + (size_t)l*EE*HID,
                                                         pA, nullptr, nullptr, NP, EE, HID, fc2_b + l*EE, nullptr);
        } else {
            hgemm<5><<<dim3(EE/64, MPAD/128), GB, SMB>>>(hbh, hbl, f2h + (size_t)l*EE*HID, f2l + (size_t)l*EE*HID,
                                                         pA, ah2, al2, NP, EE, HID, fc2_b + l*EE, nullptr);
        }
    }

    // head (A splits already emitted by last fc2)
    hgemm<0><<<dim3(HDD/64, MPAD/128), GB, SMB>>>(ah2, al2, hwh, hwl, pPX, nullptr, nullptr,
                                                  NP, HDD, EE, nullptr, nullptr);
    scatter_out<<<(20736000 + 255)/256, 256>>>(out);
}

// round 10
// speedup vs baseline: 2.3542x; 1.0174x over previous
#include <cuda_runtime.h>
#include <cuda_bf16.h>
#include <math.h>
#include <stdint.h>

// ---------------- constants ----------------
#define GHh 45
#define GWw 90
#define NP 4050          // tokens
#define MPAD 4096        // padded token rows
#define EE 768
#define KM 23
#define NFREQ (GHh*KM)   // 1035
#define FPAD 1152        // padded freq rows (9*128)
#define HID 3072
#define PKK 5120
#define HDD 5120
#define NBB 8
#define BSS 96
#define BLK (NBB*BSS*BSS)   // 73728 per layer
#define DHT_SIZE 3110400.0

// ---------------- fp32 scratch ----------------
__device__ __align__(128) float g_px[(size_t)NP*HDD];
__device__ __align__(128) float g_A [NP*EE];
__device__ __align__(128) float g_T [NP*EE];        // inverse C-stage out (1035 x 1536 view)
__device__ __align__(128) float g_Qr[NFREQ*EE];
__device__ __align__(128) float g_Qi[NFREQ*EE];
__device__ __align__(128) float g_Zr[NFREQ*EE];
__device__ __align__(128) float g_Zi[NFREQ*EE];
__device__ __align__(128) float g_a [NFREQ*EE];
__device__ __align__(128) float g_mu[NP];           // LN1 stats
__device__ __align__(128) float g_ri[NP];
// small DFT tables
__device__ __align__(128) float g_WC[GWw*GWw];
__device__ __align__(128) float g_WS[GWw*GWw];
__device__ __align__(128) float g_WCm[GWw*GWw];   // (cos-sin)/SIZE
__device__ __align__(128) float g_WCp[GWw*GWw];   // (cos+sin)/SIZE
__device__ __align__(128) float g_HC[GHh*GHh];
__device__ __align__(128) float g_HS[GHh*GHh];
// per-layer prepped block weights (ALL 12 layers, hoisted)
__device__ __align__(128) float g_W1p[12*BLK], g_W1m[12*BLK];
__device__ __align__(128) float g_W2p[12*BLK], g_W2m[12*BLK];
__device__ __align__(128) float g_W2a[12*BLK], g_W2b[12*BLK];
__device__ __align__(128) float g_bs [12*NBB*BSS];

// ---------------- bf16 split buffers (hi/lo) ----------------
__device__ __align__(128) __nv_bfloat16 g_pxh[(size_t)MPAD*PKK], g_pxl[(size_t)MPAD*PKK];
__device__ __align__(128) __nv_bfloat16 g_th [(size_t)MPAD*EE],  g_tl [(size_t)MPAD*EE];
__device__ __align__(128) __nv_bfloat16 g_hbh[(size_t)MPAD*HID], g_hbl[(size_t)MPAD*HID];
__device__ __align__(128) __nv_bfloat16 g_Ah2[(size_t)MPAD*EE],  g_Al2[(size_t)MPAD*EE];
__device__ __align__(128) __nv_bfloat16 g_q2h[(size_t)FPAD*2*EE], g_q2l[(size_t)FPAD*2*EE];
__device__ __align__(128) __nv_bfloat16 g_sh [(size_t)FPAD*EE],  g_sl [(size_t)FPAD*EE];
// weights / tables
__device__ __align__(128) __nv_bfloat16 g_pwh[EE*PKK],  g_pwl[EE*PKK];
__device__ __align__(128) __nv_bfloat16 g_fBh[EE*2*EE], g_fBl[EE*2*EE];   // fwd C B
__device__ __align__(128) __nv_bfloat16 g_iBh[2*EE*EE], g_iBl[2*EE*EE];   // inv C B
__device__ __align__(128) __nv_bfloat16 g_f1h[(size_t)12*HID*EE], g_f1l[(size_t)12*HID*EE];
__device__ __align__(128) __nv_bfloat16 g_f2h[(size_t)12*EE*HID], g_f2l[(size_t)12*EE*HID];
__device__ __align__(128) __nv_bfloat16 g_hwh[HDD*EE],  g_hwl[HDD*EE];

// ---------------- helpers ----------------
__device__ __forceinline__ void bsplit(float x, __nv_bfloat16& h, __nv_bfloat16& l) {
    h = __float2bfloat16(x);
    l = __float2bfloat16(x - __bfloat162float(h));
}
__device__ __forceinline__ uint32_t s2u32(const void* p) {
    uint32_t a;
    asm("{ .reg .u64 t; cvta.to.shared.u64 t, %1; cvt.u32.u64 %0, t; }" : "=r"(a) : "l"(p));
    return a;
}
__device__ __forceinline__ void mma_bf16(float* c, const uint32_t* a, const uint32_t* b) {
    asm volatile("mma.sync.aligned.m16n8k16.row.col.f32.bf16.bf16.f32 "
        "{%0,%1,%2,%3}, {%4,%5,%6,%7}, {%8,%9}, {%0,%1,%2,%3};"
        : "+f"(c[0]), "+f"(c[1]), "+f"(c[2]), "+f"(c[3])
        : "r"(a[0]), "r"(a[1]), "r"(a[2]), "r"(a[3]), "r"(b[0]), "r"(b[1]));
}
__device__ __forceinline__ void cpa16(uint32_t dst, const void* src) {
    asm volatile("cp.async.cg.shared.global [%0], [%1], 16;" :: "r"(dst), "l"(src));
}
__device__ __forceinline__ void ldsm4(uint32_t* r, uint32_t addr) {
    asm volatile("ldmatrix.sync.aligned.m8n8.x4.shared.b16 {%0,%1,%2,%3}, [%4];"
        : "=r"(r[0]), "=r"(r[1]), "=r"(r[2]), "=r"(r[3]) : "r"(addr));
}

// ---------------- table init ----------------
__global__ void tabC() {
    int idx = blockIdx.x*256 + threadIdx.x;
    if (idx >= EE*EE) return;
    int kc = idx / EE, c = idx % EE;
    long long m = ((long long)kc * c) % EE;
    double a = 2.0 * (double)m / (double)EE;
    double cs = cospi(a), sn = sinpi(a);
    __nv_bfloat16 h, l;
    bsplit((float)(cs - sn), h, l); g_fBh[kc*2*EE + c]      = h; g_fBl[kc*2*EE + c]      = l;
    bsplit((float)(cs + sn), h, l); g_fBh[kc*2*EE + EE + c] = h; g_fBl[kc*2*EE + EE + c] = l;
    bsplit((float)cs, h, l);        g_iBh[kc*EE + c]        = h; g_iBl[kc*EE + c]        = l;
    bsplit((float)(-sn), h, l);     g_iBh[(EE+kc)*EE + c]   = h; g_iBl[(EE+kc)*EE + c]   = l;
}
__global__ void tab90() {
    int idx = blockIdx.x*256 + threadIdx.x;
    if (idx >= GWw*GWw) return;
    int a = idx / GWw, b = idx % GWw;
    long long m = ((long long)a * b) % GWw;
    double ang = 2.0 * (double)m / (double)GWw;
    double cs = cospi(ang), sn = sinpi(ang);
    g_WC[idx]  = (float)cs;
    g_WS[idx]  = (float)sn;
    g_WCm[idx] = (float)((cs - sn) / DHT_SIZE);
    g_WCp[idx] = (float)((cs + sn) / DHT_SIZE);
}
__global__ void tab45() {
    int idx = blockIdx.x*256 + threadIdx.x;
    if (idx >= GHh*GHh) return;
    int a = idx / GHh, b = idx % GHh;
    long long m = ((long long)a * b) % GHh;
    double ang = 2.0 * (double)m / (double)GHh;
    g_HC[idx] = (float)cospi(ang);
    g_HS[idx] = (float)sinpi(ang);
}

__global__ void split_kernel(const float* __restrict__ in,
                             __nv_bfloat16* __restrict__ oh,
                             __nv_bfloat16* __restrict__ ol, int n) {
    int i = blockIdx.x*256 + threadIdx.x;
    if (i >= n) return;
    __nv_bfloat16 h, l;
    bsplit(in[i], h, l);
    oh[i] = h; ol[i] = l;
}

// ---------------- bf16x3 mma.sync GEMM, tile 128Mx64N, k-chunk 32 ----------------
// MODE: 0=store fp32, 2=bias+GELU->bf16 split, 3=accumulate(+bias) fp32,
//       4=store+bias+addmat, 5=accumulate(+bias) fp32 AND emit bf16 split of result
#define SMSTR 40
#define A_TB (128*SMSTR*2)
#define B_TB (64*SMSTR*2)
#define BUF_B (2*A_TB + 2*B_TB)

template<int MODE>
__global__ void __launch_bounds__(256, 3)
hgemm(const __nv_bfloat16* __restrict__ Ah, const __nv_bfloat16* __restrict__ Al,
      const __nv_bfloat16* __restrict__ Bh, const __nv_bfloat16* __restrict__ Bl,
      float* __restrict__ C,
      __nv_bfloat16* __restrict__ Csh, __nv_bfloat16* __restrict__ Csl,
      int Mtrue, int N, int K, const float* __restrict__ bias,
      const float* __restrict__ addm)
{
    extern __shared__ __align__(128) char smem[];
    const int t = threadIdx.x, warp = t >> 5, lane = t & 31;
    const int wm = warp >> 1, wn = warp & 1;
    const int bm = blockIdx.y * 128, bn = blockIdx.x * 64;
    const uint32_t sb = s2u32(smem);

    float acc[2][4][4];
    #pragma unroll
    for (int i = 0; i < 2; i++)
        #pragma unroll
        for (int j = 0; j < 4; j++)
            #pragma unroll
            for (int q = 0; q < 4; q++) acc[i][j][q] = 0.f;

    const int arow = t & 127, ahalf = t >> 7;
    const __nv_bfloat16* pAh = Ah + (size_t)(bm + arow) * K + ahalf * 16;
    const __nv_bfloat16* pAl = Al + (size_t)(bm + arow) * K + ahalf * 16;
    const uint32_t aoff = (uint32_t)(arow * SMSTR + ahalf * 16) * 2;
    const int brow = t >> 2, bseg = t & 3;
    const __nv_bfloat16* pBh = Bh + (size_t)(bn + brow) * K + bseg * 8;
    const __nv_bfloat16* pBl = Bl + (size_t)(bn + brow) * K + bseg * 8;
    const uint32_t boff = (uint32_t)(brow * SMSTR + bseg * 8) * 2;

    // precomputed LDSM base addresses (buffer 0); in-loop: + parity*BUF_B
    uint32_t adA[2][2], adB[2][2];
    {
        const int g = lane >> 3, r = lane & 7;
        #pragma unroll
        for (int step = 0; step < 2; step++) {
            const int ks = step * 16;
            const uint32_t a_off = (uint32_t)(((g & 1) * 8 + r) * SMSTR + ks + (g >> 1) * 8) * 2;
            const uint32_t b_off = (uint32_t)(((g >> 1) * 8 + r) * SMSTR + ks + (g & 1) * 8) * 2;
            #pragma unroll
            for (int mt = 0; mt < 2; mt++)
                adA[step][mt] = sb + (uint32_t)((wm*32 + mt*16) * SMSTR) * 2 + a_off;
            #pragma unroll
            for (int j2 = 0; j2 < 2; j2++)
                adB[step][j2] = sb + 2*A_TB + (uint32_t)((wn*32 + j2*16) * SMSTR) * 2 + b_off;
        }
    }

    const int nch = K >> 5;
    auto issue = [&](int ch) {
        const int k0 = ch << 5;
        const uint32_t dst = sb + (uint32_t)(ch & 1) * BUF_B;
        cpa16(dst + aoff,        pAh + k0); cpa16(dst + aoff + 16,        pAh + k0 + 8);
        cpa16(dst + A_TB + aoff, pAl + k0); cpa16(dst + A_TB + aoff + 16, pAl + k0 + 8);
        cpa16(dst + 2*A_TB + boff,        pBh + k0);
        cpa16(dst + 2*A_TB + B_TB + boff, pBl + k0);
        asm volatile("cp.async.commit_group;" ::: "memory");
    };

    issue(0);
    for (int ch = 0; ch < nch; ch++) {
        const bool more = (ch + 1) < nch;
        if (more) { issue(ch + 1); asm volatile("cp.async.wait_group 1;" ::: "memory"); }
        else      { asm volatile("cp.async.wait_group 0;" ::: "memory"); }
        __syncthreads();

        const uint32_t bsel = (uint32_t)(ch & 1) * BUF_B;

        #pragma unroll
        for (int step = 0; step < 2; step++) {
            uint32_t ah_[2][4], al_[2][4], bh_[4][2], bl_[4][2];
            #pragma unroll
            for (int mt = 0; mt < 2; mt++) {
                const uint32_t ad = adA[step][mt] + bsel;
                ldsm4(ah_[mt], ad);
                ldsm4(al_[mt], ad + A_TB);
            }
            #pragma unroll
            for (int j2 = 0; j2 < 2; j2++) {
                const uint32_t bd = adB[step][j2] + bsel;
                uint32_t tmp[4];
                ldsm4(tmp, bd);
                bh_[j2*2][0]=tmp[0]; bh_[j2*2][1]=tmp[1]; bh_[j2*2+1][0]=tmp[2]; bh_[j2*2+1][1]=tmp[3];
                ldsm4(tmp, bd + B_TB);
                bl_[j2*2][0]=tmp[0]; bl_[j2*2][1]=tmp[1]; bl_[j2*2+1][0]=tmp[2]; bl_[j2*2+1][1]=tmp[3];
            }
            #pragma unroll
            for (int mt = 0; mt < 2; mt++)
                #pragma unroll
                for (int nt = 0; nt < 4; nt++) mma_bf16(acc[mt][nt], ah_[mt], bh_[nt]);
            #pragma unroll
            for (int mt = 0; mt < 2; mt++)
                #pragma unroll
                for (int nt = 0; nt < 4; nt++) mma_bf16(acc[mt][nt], al_[mt], bh_[nt]);
            #pragma unroll
            for (int mt = 0; mt < 2; mt++)
                #pragma unroll
                for (int nt = 0; nt < 4; nt++) mma_bf16(acc[mt][nt], ah_[mt], bl_[nt]);
        }
        __syncthreads();
    }

    #pragma unroll
    for (int mt = 0; mt < 2; mt++) {
        const int r0 = bm + wm*32 + mt*16 + (lane >> 2);
        #pragma unroll
        for (int nt = 0; nt < 4; nt++) {
            const int c0 = bn + wn*32 + nt*8 + (lane & 3)*2;
            float b0 = 0.f, b1 = 0.f;
            if (MODE == 2 || MODE == 3 || MODE == 4 || MODE == 5) { b0 = bias[c0]; b1 = bias[c0+1]; }
            #pragma unroll
            for (int h = 0; h < 2; h++) {
                const int row = r0 + h*8;
                if (row >= Mtrue) continue;
                float v0 = acc[mt][nt][h*2+0] + b0;
                float v1 = acc[mt][nt][h*2+1] + b1;
                if (MODE == 2) {
                    v0 = 0.5f*v0*(1.0f + erff(v0*0.7071067811865475f));
                    v1 = 0.5f*v1*(1.0f + erff(v1*0.7071067811865475f));
                    __nv_bfloat16 h0, l0, h1, l1;
                    bsplit(v0, h0, l0); bsplit(v1, h1, l1);
                    __nv_bfloat162 hv; hv.x = h0; hv.y = h1;
                    __nv_bfloat162 lv; lv.x = l0; lv.y = l1;
                    *(__nv_bfloat162*)&Csh[(size_t)row*N + c0] = hv;
                    *(__nv_bfloat162*)&Csl[(size_t)row*N + c0] = lv;
                } else if (MODE == 3) {
                    float2* cp = (float2*)&C[(size_t)row*N + c0];
                    float2 old = *cp;
                    old.x += v0; old.y += v1;
                    *cp = old;
                } else if (MODE == 5) {
                    float2* cp = (float2*)&C[(size_t)row*N + c0];
                    float2 old = *cp;
                    old.x += v0; old.y += v1;
                    *cp = old;
                    __nv_bfloat16 h0, l0, h1, l1;
                    bsplit(old.x, h0, l0); bsplit(old.y, h1, l1);
                    __nv_bfloat162 hv; hv.x = h0; hv.y = h1;
                    __nv_bfloat162 lv; lv.x = l0; lv.y = l1;
                    *(__nv_bfloat162*)&Csh[(size_t)row*N + c0] = hv;
                    *(__nv_bfloat162*)&Csl[(size_t)row*N + c0] = lv;
                } else if (MODE == 4) {
                    const float2 am = *(const float2*)&addm[(size_t)row*N + c0];
                    float2 fv; fv.x = v0 + am.x; fv.y = v1 + am.y;
                    *(float2*)&C[(size_t)row*N + c0] = fv;
                } else {
                    float2 fv; fv.x = v0; fv.y = v1;
                    *(float2*)&C[(size_t)row*N + c0] = fv;
                }
            }
        }
    }
}

// ---------------- LN stats (mu, 1/sigma per token) ----------------
__global__ void ln_stats(const float* __restrict__ in) {
    int tok = blockIdx.x;
    int tid = threadIdx.x;
    const float* row = in + (size_t)tok*EE;
    float x0 = row[tid], x1 = row[tid+256], x2 = row[tid+512];
    float s  = x0+x1+x2;
    float sq = x0*x0 + x1*x1 + x2*x2;
    #pragma unroll
    for (int o = 16; o > 0; o >>= 1) {
        s  += __shfl_down_sync(0xffffffffu, s,  o);
        sq += __shfl_down_sync(0xffffffffu, sq, o);
    }
    __shared__ float ss[8], ssq[8];
    int warp = tid >> 5, lane = tid & 31;
    if (lane == 0) { ss[warp] = s; ssq[warp] = sq; }
    __syncthreads();
    if (tid == 0) {
        float ts = 0.f, tq = 0.f;
        #pragma unroll
        for (int i = 0; i < 8; i++) { ts += ss[i]; tq += ssq[i]; }
        float m = ts * (1.0f/768.0f);
        float v = tq * (1.0f/768.0f) - m*m;
        g_mu[tok] = m;
        g_ri[tok] = rsqrtf(v + 1e-5f);
    }
}

// ---------------- LN with bf16-split output (MLP half) ----------------
__global__ void ln_bf16(const float* __restrict__ in,
                        __nv_bfloat16* __restrict__ oh, __nv_bfloat16* __restrict__ ol,
                        const float* __restrict__ w, const float* __restrict__ b)
{
    int tok = blockIdx.x;
    int tid = threadIdx.x;
    const float* row = in + (size_t)tok*EE;
    float x0 = row[tid], x1 = row[tid+256], x2 = row[tid+512];
    float s  = x0+x1+x2;
    float sq = x0*x0 + x1*x1 + x2*x2;
    #pragma unroll
    for (int o = 16; o > 0; o >>= 1) {
        s  += __shfl_down_sync(0xffffffffu, s,  o);
        sq += __shfl_down_sync(0xffffffffu, sq, o);
    }
    __shared__ float ss[8], ssq[8];
    int warp = tid >> 5, lane = tid & 31;
    if (lane == 0) { ss[warp] = s; ssq[warp] = sq; }
    __syncthreads();
    if (tid == 0) {
        float ts = 0.f, tq = 0.f;
        #pragma unroll
        for (int i = 0; i < 8; i++) { ts += ss[i]; tq += ssq[i]; }
        float m = ts * (1.0f/768.0f);
        float v = tq * (1.0f/768.0f) - m*m;
        ss[0] = m; ssq[0] = rsqrtf(v + 1e-5f);
    }
    __syncthreads();
    float m = ss[0], inv = ssq[0];
    size_t base = (size_t)tok*EE;
    #pragma unroll
    for (int j = 0; j < 3; j++) {
        int o = tid + j*256;
        float y = (j==0?x0:(j==1?x1:x2));
        y = (y - m)*inv*w[o] + b[o];
        __nv_bfloat16 h, l; bsplit(y, h, l);
        oh[base + o] = h; ol[base + o] = l;
    }
}

// ---------------- DHT stage kernels (LN fused via stats) ----------------
__global__ void k_wfwd(const float* __restrict__ nw, const float* __restrict__ nb) {
    extern __shared__ float sm[];          // 90*128 + 180
    float* stat = sm + 90*128;
    int c0 = blockIdx.x*128, h = blockIdx.y, tid = threadIdx.x;
    if (tid < 90) {
        stat[tid]    = g_mu[h*90+tid];
        stat[90+tid] = g_ri[h*90+tid];
    }
    __syncthreads();
    float wv = nw[c0+tid], bv = nb[c0+tid];
    for (int w = 0; w < 90; w++) {
        float av = g_A[(h*90+w)*EE + c0+tid];
        sm[w*128+tid] = (av - stat[w]) * stat[90+w] * wv + bv;
    }
    __syncthreads();
    for (int kw = 0; kw < 23; kw++) {
        float ar = 0.f, ai = 0.f;
        #pragma unroll 6
        for (int w = 0; w < 90; w++) {
            float v = sm[w*128+tid];
            ar += v * g_WC[kw*90+w];
            ai -= v * g_WS[kw*90+w];
        }
        g_Qr[(h*23+kw)*EE + c0+tid] = ar;
        g_Qi[(h*23+kw)*EE + c0+tid] = ai;
    }
}
__global__ void k_hfwd() {
    extern __shared__ float sm[];
    float* sr = sm; float* si = sm + 45*128;
    int c0 = blockIdx.x*128, kw = blockIdx.y, tid = threadIdx.x;
    for (int h = 0; h < 45; h++) {
        sr[h*128+tid] = g_Qr[(h*23+kw)*EE + c0+tid];
        si[h*128+tid] = g_Qi[(h*23+kw)*EE + c0+tid];
    }
    __syncthreads();
    for (int kh = 0; kh < 45; kh++) {
        float qr = 0.f, qi = 0.f;
        #pragma unroll 5
        for (int h = 0; h < 45; h++) {
            float ch = g_HC[kh*45+h], sh = g_HS[kh*45+h];
            float ur = sr[h*128+tid], ui = si[h*128+tid];
            qr += ur*ch + ui*sh;
            qi += ui*ch - ur*sh;
        }
        size_t row = (size_t)(kh*23+kw) * (2*EE);
        __nv_bfloat16 h2, l2;
        bsplit(qr, h2, l2); g_q2h[row + c0+tid] = h2;      g_q2l[row + c0+tid] = l2;
        bsplit(qi, h2, l2); g_q2h[row + EE + c0+tid] = h2; g_q2l[row + EE + c0+tid] = l2;
    }
}
__global__ void k_hinv2() {
    extern __shared__ float sm[];
    float* tr = sm; float* ti = sm + 45*128;
    int c0 = blockIdx.x*128, wp = blockIdx.y, tid = threadIdx.x;
    for (int hp = 0; hp < 45; hp++) {
        size_t row = (size_t)(hp*23+wp) * (2*EE);
        tr[hp*128+tid] = g_T[row + c0+tid];
        ti[hp*128+tid] = g_T[row + EE + c0+tid];
    }
    __syncthreads();
    for (int a = 0; a < 45; a++) {
        float zr = 0.f, zi = 0.f;
        #pragma unroll 5
        for (int hp = 0; hp < 45; hp++) {
            float ch = g_HC[a*45+hp], sh = g_HS[a*45+hp];
            float xr = tr[hp*128+tid], xi = ti[hp*128+tid];
            zr += xr*ch + xi*sh;
            zi += xi*ch - xr*sh;
        }
        g_Zr[(a*23+wp)*EE + c0+tid] = zr;
        g_Zi[(a*23+wp)*EE + c0+tid] = zi;
    }
}
// inverse W-stage: A += y + LN1(A) (normalization recomputed from stats)
__global__ void k_winv2(const float* __restrict__ nw, const float* __restrict__ nb) {
    extern __shared__ float sm[];
    float* zr = sm; float* zi = sm + 23*128;
    int c0 = blockIdx.x*128, a = blockIdx.y, tid = threadIdx.x;
    for (int wp = 0; wp < 23; wp++) {
        zr[wp*128+tid] = g_Zr[(a*23+wp)*EE + c0+tid];
        zi[wp*128+tid] = g_Zi[(a*23+wp)*EE + c0+tid];
    }
    __syncthreads();
    float wv = nw[c0+tid], bv = nb[c0+tid];
    for (int b = 0; b < 90; b++) {
        float y = 0.f;
        #pragma unroll
        for (int wp = 0; wp < 23; wp++) {
            y += zr[wp*128+tid]*g_WCm[b*90+wp] + zi[wp*128+tid]*g_WCp[b*90+wp];
        }
        int tok = a*90 + b;
        size_t idx = (size_t)tok*EE + c0+tid;
        float av = g_A[idx];
        float tv = (av - g_mu[tok]) * g_ri[tok] * wv + bv;
        g_A[idx] = av + y + tv;
    }
}

// ---------------- misc elementwise ----------------
__global__ void im2col_kernel(const float* __restrict__ x) {
    int idx = blockIdx.x*256 + threadIdx.x;
    if (idx >= NP*PKK) return;
    int p = idx / PKK, k = idx % PKK;
    int c = k >> 8, r = k & 255;
    int ph = r >> 4, pw = r & 15;
    int gh = p / 90, gw = p % 90;
    float v = x[(size_t)c*1036800 + (size_t)(gh*16+ph)*1440 + (gw*16+pw)];
    __nv_bfloat16 h, l; bsplit(v, h, l);
    size_t o = (size_t)p*PKK + k;
    g_pxh[o] = h; g_pxl[o] = l;
}
__global__ void scatter_out(float* __restrict__ out) {
    int idx = blockIdx.x*256 + threadIdx.x;
    if (idx >= 20736000) return;
    int oc = idx / 1036800; int r = idx % 1036800;
    int hh = r / 1440, ww = r % 1440;
    int gh = hh >> 4, ph = hh & 15, gw = ww >> 4, pw = ww & 15;
    out[idx] = g_px[(size_t)(gh*90+gw)*HDD + ph*320 + pw*20 + oc];
}

// ---------------- block-weight prep, ALL layers hoisted ----------------
__global__ void prep_pm_all(const float* __restrict__ w1, const float* __restrict__ w2) {
    int idx = blockIdx.x*256 + threadIdx.x;
    if (idx >= 12*BLK) return;
    int l = idx / BLK, i = idx % BLK;
    const float* w1l = w1 + (size_t)l*2*BLK;
    const float* w2l = w2 + (size_t)l*2*BLK;
    g_W1p[idx] = 0.5f*(w1l[i] + w1l[BLK+i]);
    g_W1m[idx] = 0.5f*(w1l[i] - w1l[BLK+i]);
    g_W2p[idx] = 0.5f*(w2l[i] + w2l[BLK+i]);
    g_W2m[idx] = 0.5f*(w2l[i] - w2l[BLK+i]);
}
__global__ void prep_ab_all() {
    int idx = blockIdx.x*128 + threadIdx.x;
    if (idx >= 12*BLK) return;
    int l = idx / BLK, rr = idx % BLK;
    int o = rr % 96;
    int i = (rr / 96) % 96;
    int b = rr / 9216;
    const float* P = g_W2p + (size_t)l*BLK + b*9216;
    const float* M = g_W2m + (size_t)l*BLK + b*9216;
    float aa = g_W2p[idx];
    float bb = g_W2m[idx] + g_W2p[idx];
    #pragma unroll 8
    for (int j = 0; j < 96; j++) {
        aa += P[i*96+j] * M[j*96+o];
        bb += M[i*96+j] * M[j*96+o];
    }
    g_W2a[idx] = aa;
    g_W2b[idx] = bb;
}
__global__ void prep_bs_all(const float* __restrict__ b2) {
    int idx = blockIdx.x*128 + threadIdx.x;
    if (idx >= 12*NBB*BSS) return;
    int l = idx / (NBB*BSS), rr = idx % (NBB*BSS);
    int o = rr % 96, b = rr / 96;
    const float* b2l = b2 + (size_t)l*2*NBB*BSS;
    float v = b2l[rr] + b2l[NBB*BSS + rr];
    const float* M = g_W2m + (size_t)l*BLK;
    #pragma unroll 8
    for (int j = 0; j < 96; j++) v += b2l[b*96+j] * M[(b*96+j)*96+o];
    g_bs[idx] = v;
}

// ---------------- fused block mixing (LN-gather + mix1 + mix2 + soft-thresh + split) ----------------
#define MROWS 45
#define MIXSM ((9216*2 + MROWS*96*2)*4)
__global__ void k_mixf(const float* __restrict__ b1l,
                       const float* __restrict__ nw, const float* __restrict__ nb,
                       int loff, int lbs) {
    extern __shared__ float sm[];
    float* sW1 = sm;
    float* sW2 = sm + 9216;
    float* sX  = sm + 18432;
    float* sY  = sX + MROWS*96;
    int b = blockIdx.x, tile = blockIdx.y;
    int t = threadIdx.x;
    int o = t % 96, rg = t / 96;
    for (int i = t; i < 9216; i += 288) {
        sW1[i] = g_W1p[loff + b*9216+i];
        sW2[i] = g_W1m[loff + b*9216+i];
    }
    int p0 = tile * MROWS;
    float nwv = nw[b*96+o], nbv = nb[b*96+o];
    for (int pp = rg; pp < MROWS; pp += 3) {
        int p = p0 + pp;
        int h = p / 23, w = p % 23;
        int shh = (45 - h) % 45;
        int sww = (90 - w) % 90;
        int tok = shh*90 + sww;
        float av = g_A[(size_t)tok*EE + b*96 + o];
        sX[pp*96+o] = g_a[(size_t)p*EE + b*96 + o];
        sY[pp*96+o] = (av - g_mu[tok]) * g_ri[tok] * nwv + nbv;   // fused LN gather
    }
    __syncthreads();
    float bk = b1l[b*96+o], bn = b1l[NBB*BSS + b*96+o];
    float ok_[15], on_[15];
    {
        int c = 0;
        for (int pp = rg; pp < MROWS; pp += 3, c++) {
            float ak = bk, an = bn;
            #pragma unroll 8
            for (int i = 0; i < 96; i++) {
                float xv = sX[pp*96+i], yv = sY[pp*96+i];
                float wp = sW1[i*96+o], wm = sW2[i*96+o];
                ak += xv*wp + yv*wm;
                an += yv*wp + xv*wm;
            }
            ok_[c] = fmaxf(ak, 0.f);
            on_[c] = fmaxf(an, 0.f);
        }
    }
    __syncthreads();
    {
        int c = 0;
        for (int pp = rg; pp < MROWS; pp += 3, c++) {
            sX[pp*96+o] = ok_[c];
            sY[pp*96+o] = on_[c];
        }
    }
    for (int i = t; i < 9216; i += 288) {
        sW1[i] = g_W2a[loff + b*9216+i];
        sW2[i] = g_W2b[loff + b*9216+i];
    }
    __syncthreads();
    float bsv = g_bs[lbs + b*96+o];
    for (int pp = rg; pp < MROWS; pp += 3) {
        float acc = bsv;
        #pragma unroll 8
        for (int i = 0; i < 96; i++) {
            acc += sX[pp*96+i]*sW1[i*96+o] + sY[pp*96+i]*sW2[i*96+o];
        }
        float aab = fabsf(acc) - 0.01f;
        float v = (aab > 0.f) ? copysignf(aab, acc) : 0.f;
        __nv_bfloat16 h, l; bsplit(v, h, l);
        size_t idx = (size_t)(p0+pp)*EE + b*96 + o;
        g_sh[idx] = h; g_sl[idx] = l;
    }
}

// ---------------- host orchestration ----------------
extern "C" void kernel_launch(void* const* d_in, const int* in_sizes, int n_in,
                              void* d_out, int out_size)
{
    const float* x        = (const float*)d_in[0];
    const float* patch_w  = (const float*)d_in[1];
    const float* patch_b  = (const float*)d_in[2];
    const float* pos      = (const float*)d_in[3];
    const float* norm1_w  = (const float*)d_in[4];
    const float* norm1_b  = (const float*)d_in[5];
    const float* w1       = (const float*)d_in[6];
    const float* b1       = (const float*)d_in[7];
    const float* w2       = (const float*)d_in[8];
    const float* b2       = (const float*)d_in[9];
    const float* norm2_w  = (const float*)d_in[10];
    const float* norm2_b  = (const float*)d_in[11];
    const float* fc1_w    = (const float*)d_in[12];
    const float* fc1_b    = (const float*)d_in[13];
    const float* fc2_w    = (const float*)d_in[14];
    const float* fc2_b    = (const float*)d_in[15];
    const float* head_w   = (const float*)d_in[16];
    float* out = (float*)d_out;

    float *pPX,*pA,*pTT,*pa;
    cudaGetSymbolAddress((void**)&pPX, g_px);
    cudaGetSymbolAddress((void**)&pA,  g_A);
    cudaGetSymbolAddress((void**)&pTT, g_T);
    cudaGetSymbolAddress((void**)&pa,  g_a);

    __nv_bfloat16 *pxh,*pxl,*th,*tl,*hbh,*hbl,*ah2,*al2,*q2h,*q2l,*sh,*sl;
    __nv_bfloat16 *pwh,*pwl,*fBh,*fBl,*iBh,*iBl,*f1h,*f1l,*f2h,*f2l,*hwh,*hwl;
    cudaGetSymbolAddress((void**)&pxh, g_pxh);  cudaGetSymbolAddress((void**)&pxl, g_pxl);
    cudaGetSymbolAddress((void**)&th,  g_th);   cudaGetSymbolAddress((void**)&tl,  g_tl);
    cudaGetSymbolAddress((void**)&hbh, g_hbh);  cudaGetSymbolAddress((void**)&hbl, g_hbl);
    cudaGetSymbolAddress((void**)&ah2, g_Ah2);  cudaGetSymbolAddress((void**)&al2, g_Al2);
    cudaGetSymbolAddress((void**)&q2h, g_q2h);  cudaGetSymbolAddress((void**)&q2l, g_q2l);
    cudaGetSymbolAddress((void**)&sh,  g_sh);   cudaGetSymbolAddress((void**)&sl,  g_sl);
    cudaGetSymbolAddress((void**)&pwh, g_pwh);  cudaGetSymbolAddress((void**)&pwl, g_pwl);
    cudaGetSymbolAddress((void**)&fBh, g_fBh);  cudaGetSymbolAddress((void**)&fBl, g_fBl);
    cudaGetSymbolAddress((void**)&iBh, g_iBh);  cudaGetSymbolAddress((void**)&iBl, g_iBl);
    cudaGetSymbolAddress((void**)&f1h, g_f1h);  cudaGetSymbolAddress((void**)&f1l, g_f1l);
    cudaGetSymbolAddress((void**)&f2h, g_f2h);  cudaGetSymbolAddress((void**)&f2l, g_f2l);
    cudaGetSymbolAddress((void**)&hwh, g_hwh);  cudaGetSymbolAddress((void**)&hwl, g_hwl);

    cudaFuncSetAttribute(k_wfwd,  cudaFuncAttributeMaxDynamicSharedMemorySize, 90*128*4 + 180*4);
    cudaFuncSetAttribute(k_hfwd,  cudaFuncAttributeMaxDynamicSharedMemorySize, 2*45*128*4);
    cudaFuncSetAttribute(k_hinv2, cudaFuncAttributeMaxDynamicSharedMemorySize, 2*45*128*4);
    cudaFuncSetAttribute(k_winv2, cudaFuncAttributeMaxDynamicSharedMemorySize, 2*23*128*4);
    cudaFuncSetAttribute(k_mixf,  cudaFuncAttributeMaxDynamicSharedMemorySize, MIXSM);
    cudaFuncSetAttribute(hgemm<0>, cudaFuncAttributeMaxDynamicSharedMemorySize, 2*BUF_B);
    cudaFuncSetAttribute(hgemm<2>, cudaFuncAttributeMaxDynamicSharedMemorySize, 2*BUF_B);
    cudaFuncSetAttribute(hgemm<3>, cudaFuncAttributeMaxDynamicSharedMemorySize, 2*BUF_B);
    cudaFuncSetAttribute(hgemm<4>, cudaFuncAttributeMaxDynamicSharedMemorySize, 2*BUF_B);
    cudaFuncSetAttribute(hgemm<5>, cudaFuncAttributeMaxDynamicSharedMemorySize, 2*BUF_B);

    // tables + weight splits + ALL-layer block-weight prep (once)
    tabC <<<(EE*EE + 255)/256, 256>>>();
    tab90<<<(GWw*GWw + 255)/256, 256>>>();
    tab45<<<(GHh*GHh + 255)/256, 256>>>();
    split_kernel<<<(EE*PKK + 255)/256, 256>>>(patch_w, pwh, pwl, EE*PKK);
    split_kernel<<<(HDD*EE + 255)/256, 256>>>(head_w, hwh, hwl, HDD*EE);
    split_kernel<<<(12*HID*EE + 255)/256, 256>>>(fc1_w, f1h, f1l, 12*HID*EE);
    split_kernel<<<(12*EE*HID + 255)/256, 256>>>(fc2_w, f2h, f2l, 12*EE*HID);
    prep_pm_all<<<(12*BLK + 255)/256, 256>>>(w1, w2);
    prep_ab_all<<<(12*BLK + 127)/128, 128>>>();
    prep_bs_all<<<(12*NBB*BSS + 127)/128, 128>>>(b2);

    const dim3 GB(256);
    const int SMB = 2*BUF_B;

    // patch embed (bias + pos fused)
    im2col_kernel<<<(NP*PKK + 255)/256, 256>>>(x);
    hgemm<4><<<dim3(EE/64, MPAD/128), GB, SMB>>>(pxh, pxl, pwh, pwl, pA, nullptr, nullptr,
                                                 NP, EE, PKK, patch_b, pos);

    for (int l = 0; l < 12; l++) {
        // ---- AFNO half ----
        ln_stats<<<NP, 256>>>(pA);
        k_wfwd<<<dim3(6, 45), 128, 90*128*4 + 180*4>>>(norm1_w + l*EE, norm1_b + l*EE);
        k_hfwd<<<dim3(6, 23), 128, 2*45*128*4>>>();
        hgemm<0><<<dim3(EE/64, FPAD/128), GB, SMB>>>(q2h, q2l, fBh, fBl, pa, nullptr, nullptr,
                                                     NFREQ, EE, 2*EE, nullptr, nullptr);
        k_mixf<<<dim3(8, 23), 288, MIXSM>>>(b1 + (size_t)l*2*NBB*BSS,
                                            norm1_w + l*EE, norm1_b + l*EE, l*BLK, l*NBB*BSS);
        hgemm<0><<<dim3((2*EE)/64, FPAD/128), GB, SMB>>>(sh, sl, iBh, iBl, pTT, nullptr, nullptr,
                                                         NFREQ, 2*EE, EE, nullptr, nullptr);
        k_hinv2<<<dim3(6, 23), 128, 2*45*128*4>>>();
        k_winv2<<<dim3(6, 45), 128, 2*23*128*4>>>(norm1_w + l*EE, norm1_b + l*EE);

        // ---- MLP half ----
        ln_bf16<<<NP, 256>>>(pA, th, tl, norm2_w + l*EE, norm2_b + l*EE);
        hgemm<2><<<dim3(HID/64, MPAD/128), GB, SMB>>>(th, tl, f1h + (size_t)l*HID*EE, f1l + (size_t)l*HID*EE,
                                                      nullptr, hbh, hbl, NP, HID, EE, fc1_b + l*HID, nullptr);
        if (l < 11) {
            hgemm<3><<<dim3(EE/64, MPAD/128), GB, SMB>>>(hbh, hbl, f2h + (size_t)l*EE*HID, f2l + (size_t)l*EE*HID,
                                                         pA, nullptr, nullptr, NP, EE, HID, fc2_b + l*EE, nullptr);
        } else {
            hgemm<5><<<dim3(EE/64, MPAD/128), GB, SMB>>>(hbh, hbl, f2h + (size_t)l*EE*HID, f2l + (size_t)l*EE*HID,
                                                         pA, ah2, al2, NP, EE, HID, fc2_b + l*EE, nullptr);
        }
    }

    // head (A splits already emitted by last fc2)
    hgemm<0><<<dim3(HDD/64, MPAD/128), GB, SMB>>>(ah2, al2, hwh, hwl, pPX, nullptr, nullptr,
                                                  NP, HDD, EE, nullptr, nullptr);
    scatter_out<<<(20736000 + 255)/256, 256>>>(out);
}

// round 11
// speedup vs baseline: 2.3612x; 1.0030x over previous
#include <cuda_runtime.h>
#include <cuda_bf16.h>
#include <math.h>
#include <stdint.h>

// ---------------- constants ----------------
#define GHh 45
#define GWw 90
#define NP 4050          // tokens
#define MPAD 4096        // padded token rows
#define EE 768
#define KM 23
#define NFREQ (GHh*KM)   // 1035
#define FPAD 1152        // padded freq rows (9*128)
#define HID 3072
#define PKK 5120
#define HDD 5120
#define NBB 8
#define BSS 96
#define BLK (NBB*BSS*BSS)   // 73728 per layer
#define DHT_SIZE 3110400.0

// ---------------- fp32 scratch ----------------
__device__ __align__(128) float g_A [NP*EE];
__device__ __align__(128) float g_T [NP*EE];        // inverse C-stage out (1035 x 1536 view)
__device__ __align__(128) float g_Qr[NFREQ*EE];
__device__ __align__(128) float g_Qi[NFREQ*EE];
__device__ __align__(128) float g_Zr[NFREQ*EE];
__device__ __align__(128) float g_Zi[NFREQ*EE];
__device__ __align__(128) float g_a [NFREQ*EE];
__device__ __align__(128) float g_ssum[NP];         // LN1 running sums (produced by GEMM epilogues)
__device__ __align__(128) float g_ssq [NP];
// small DFT tables
__device__ __align__(128) float g_WC[GWw*GWw];
__device__ __align__(128) float g_WS[GWw*GWw];
__device__ __align__(128) float g_WCm[GWw*GWw];   // (cos-sin)/SIZE
__device__ __align__(128) float g_WCp[GWw*GWw];   // (cos+sin)/SIZE
__device__ __align__(128) float g_HC[GHh*GHh];
__device__ __align__(128) float g_HS[GHh*GHh];
// per-layer prepped block weights (ALL 12 layers, hoisted)
__device__ __align__(128) float g_W1p[12*BLK], g_W1m[12*BLK];
__device__ __align__(128) float g_W2p[12*BLK], g_W2m[12*BLK];
__device__ __align__(128) float g_W2a[12*BLK], g_W2b[12*BLK];
__device__ __align__(128) float g_bs [12*NBB*BSS];

// ---------------- bf16 split buffers (hi/lo) ----------------
__device__ __align__(128) __nv_bfloat16 g_pxh[(size_t)MPAD*PKK], g_pxl[(size_t)MPAD*PKK];
__device__ __align__(128) __nv_bfloat16 g_th [(size_t)MPAD*EE],  g_tl [(size_t)MPAD*EE];
__device__ __align__(128) __nv_bfloat16 g_hbh[(size_t)MPAD*HID], g_hbl[(size_t)MPAD*HID];
__device__ __align__(128) __nv_bfloat16 g_Ah2[(size_t)MPAD*EE],  g_Al2[(size_t)MPAD*EE];
__device__ __align__(128) __nv_bfloat16 g_q2h[(size_t)FPAD*2*EE], g_q2l[(size_t)FPAD*2*EE];
__device__ __align__(128) __nv_bfloat16 g_sh [(size_t)FPAD*EE],  g_sl [(size_t)FPAD*EE];
// weights / tables
__device__ __align__(128) __nv_bfloat16 g_pwh[EE*PKK],  g_pwl[EE*PKK];
__device__ __align__(128) __nv_bfloat16 g_fBh[EE*2*EE], g_fBl[EE*2*EE];   // fwd C B
__device__ __align__(128) __nv_bfloat16 g_iBh[2*EE*EE], g_iBl[2*EE*EE];   // inv C B
__device__ __align__(128) __nv_bfloat16 g_f1h[(size_t)12*HID*EE], g_f1l[(size_t)12*HID*EE];
__device__ __align__(128) __nv_bfloat16 g_f2h[(size_t)12*EE*HID], g_f2l[(size_t)12*EE*HID];
__device__ __align__(128) __nv_bfloat16 g_hwh[HDD*EE],  g_hwl[HDD*EE];

// ---------------- helpers ----------------
__device__ __forceinline__ void bsplit(float x, __nv_bfloat16& h, __nv_bfloat16& l) {
    h = __float2bfloat16(x);
    l = __float2bfloat16(x - __bfloat162float(h));
}
__device__ __forceinline__ uint32_t s2u32(const void* p) {
    uint32_t a;
    asm("{ .reg .u64 t; cvta.to.shared.u64 t, %1; cvt.u32.u64 %0, t; }" : "=r"(a) : "l"(p));
    return a;
}
__device__ __forceinline__ void mma_bf16(float* c, const uint32_t* a, const uint32_t* b) {
    asm volatile("mma.sync.aligned.m16n8k16.row.col.f32.bf16.bf16.f32 "
        "{%0,%1,%2,%3}, {%4,%5,%6,%7}, {%8,%9}, {%0,%1,%2,%3};"
        : "+f"(c[0]), "+f"(c[1]), "+f"(c[2]), "+f"(c[3])
        : "r"(a[0]), "r"(a[1]), "r"(a[2]), "r"(a[3]), "r"(b[0]), "r"(b[1]));
}
__device__ __forceinline__ void cpa16(uint32_t dst, const void* src) {
    asm volatile("cp.async.cg.shared.global [%0], [%1], 16;" :: "r"(dst), "l"(src));
}
__device__ __forceinline__ void ldsm4(uint32_t* r, uint32_t addr) {
    asm volatile("ldmatrix.sync.aligned.m8n8.x4.shared.b16 {%0,%1,%2,%3}, [%4];"
        : "=r"(r[0]), "=r"(r[1]), "=r"(r[2]), "=r"(r[3]) : "r"(addr));
}
__device__ __forceinline__ void ln_from_sums(int tok, float& mu, float& ri) {
    float s = g_ssum[tok], q = g_ssq[tok];
    mu = s * (1.0f/768.0f);
    float v = q * (1.0f/768.0f) - mu*mu;
    ri = rsqrtf(v + 1e-5f);
}

// ---------------- table init ----------------
__global__ void tabC() {
    int idx = blockIdx.x*256 + threadIdx.x;
    if (idx >= EE*EE) return;
    int kc = idx / EE, c = idx % EE;
    long long m = ((long long)kc * c) % EE;
    double a = 2.0 * (double)m / (double)EE;
    double cs = cospi(a), sn = sinpi(a);
    __nv_bfloat16 h, l;
    bsplit((float)(cs - sn), h, l); g_fBh[kc*2*EE + c]      = h; g_fBl[kc*2*EE + c]      = l;
    bsplit((float)(cs + sn), h, l); g_fBh[kc*2*EE + EE + c] = h; g_fBl[kc*2*EE + EE + c] = l;
    bsplit((float)cs, h, l);        g_iBh[kc*EE + c]        = h; g_iBl[kc*EE + c]        = l;
    bsplit((float)(-sn), h, l);     g_iBh[(EE+kc)*EE + c]   = h; g_iBl[(EE+kc)*EE + c]   = l;
}
__global__ void tab90() {
    int idx = blockIdx.x*256 + threadIdx.x;
    if (idx >= GWw*GWw) return;
    int a = idx / GWw, b = idx % GWw;
    long long m = ((long long)a * b) % GWw;
    double ang = 2.0 * (double)m / (double)GWw;
    double cs = cospi(ang), sn = sinpi(ang);
    g_WC[idx]  = (float)cs;
    g_WS[idx]  = (float)sn;
    g_WCm[idx] = (float)((cs - sn) / DHT_SIZE);
    g_WCp[idx] = (float)((cs + sn) / DHT_SIZE);
}
__global__ void tab45() {
    int idx = blockIdx.x*256 + threadIdx.x;
    if (idx >= GHh*GHh) return;
    int a = idx / GHh, b = idx % GHh;
    long long m = ((long long)a * b) % GHh;
    double ang = 2.0 * (double)m / (double)GHh;
    g_HC[idx] = (float)cospi(ang);
    g_HS[idx] = (float)sinpi(ang);
}

__global__ void split_kernel(const float* __restrict__ in,
                             __nv_bfloat16* __restrict__ oh,
                             __nv_bfloat16* __restrict__ ol, int n) {
    int i = blockIdx.x*256 + threadIdx.x;
    if (i >= n) return;
    __nv_bfloat16 h, l;
    bsplit(in[i], h, l);
    oh[i] = h; ol[i] = l;
}

// ---------------- bf16x3 mma.sync GEMM, tile 128Mx64N, k-chunk 32 ----------------
// MODE: 0=store fp32, 2=bias+GELU->bf16 split, 3=accumulate(+bias) fp32 + LN stats,
//       4=store+bias+addmat + LN stats, 5=accumulate(+bias) fp32 AND emit bf16 split,
//       6=head: scatter directly to output image
#define SMSTR 40
#define A_TB (128*SMSTR*2)
#define B_TB (64*SMSTR*2)
#define BUF_B (2*A_TB + 2*B_TB)

template<int MODE>
__global__ void __launch_bounds__(256, 3)
hgemm(const __nv_bfloat16* __restrict__ Ah, const __nv_bfloat16* __restrict__ Al,
      const __nv_bfloat16* __restrict__ Bh, const __nv_bfloat16* __restrict__ Bl,
      float* __restrict__ C,
      __nv_bfloat16* __restrict__ Csh, __nv_bfloat16* __restrict__ Csl,
      int Mtrue, int N, int K, const float* __restrict__ bias,
      const float* __restrict__ addm)
{
    extern __shared__ __align__(128) char smem[];
    const int t = threadIdx.x, warp = t >> 5, lane = t & 31;
    const int wm = warp >> 1, wn = warp & 1;
    const int bm = blockIdx.y * 128, bn = blockIdx.x * 64;
    const uint32_t sb = s2u32(smem);

    float acc[2][4][4];
    #pragma unroll
    for (int i = 0; i < 2; i++)
        #pragma unroll
        for (int j = 0; j < 4; j++)
            #pragma unroll
            for (int q = 0; q < 4; q++) acc[i][j][q] = 0.f;

    const int arow = t & 127, ahalf = t >> 7;
    const __nv_bfloat16* pAh = Ah + (size_t)(bm + arow) * K + ahalf * 16;
    const __nv_bfloat16* pAl = Al + (size_t)(bm + arow) * K + ahalf * 16;
    const uint32_t aoff = (uint32_t)(arow * SMSTR + ahalf * 16) * 2;
    const int brow = t >> 2, bseg = t & 3;
    const __nv_bfloat16* pBh = Bh + (size_t)(bn + brow) * K + bseg * 8;
    const __nv_bfloat16* pBl = Bl + (size_t)(bn + brow) * K + bseg * 8;
    const uint32_t boff = (uint32_t)(brow * SMSTR + bseg * 8) * 2;

    // precomputed LDSM base addresses (buffer 0); in-loop: + parity*BUF_B
    uint32_t adA[2][2], adB[2][2];
    {
        const int g = lane >> 3, r = lane & 7;
        #pragma unroll
        for (int step = 0; step < 2; step++) {
            const int ks = step * 16;
            const uint32_t a_off = (uint32_t)(((g & 1) * 8 + r) * SMSTR + ks + (g >> 1) * 8) * 2;
            const uint32_t b_off = (uint32_t)(((g >> 1) * 8 + r) * SMSTR + ks + (g & 1) * 8) * 2;
            #pragma unroll
            for (int mt = 0; mt < 2; mt++)
                adA[step][mt] = sb + (uint32_t)((wm*32 + mt*16) * SMSTR) * 2 + a_off;
            #pragma unroll
            for (int j2 = 0; j2 < 2; j2++)
                adB[step][j2] = sb + 2*A_TB + (uint32_t)((wn*32 + j2*16) * SMSTR) * 2 + b_off;
        }
    }

    const int nch = K >> 5;
    auto issue = [&](int ch) {
        const int k0 = ch << 5;
        const uint32_t dst = sb + (uint32_t)(ch & 1) * BUF_B;
        cpa16(dst + aoff,        pAh + k0); cpa16(dst + aoff + 16,        pAh + k0 + 8);
        cpa16(dst + A_TB + aoff, pAl + k0); cpa16(dst + A_TB + aoff + 16, pAl + k0 + 8);
        cpa16(dst + 2*A_TB + boff,        pBh + k0);
        cpa16(dst + 2*A_TB + B_TB + boff, pBl + k0);
        asm volatile("cp.async.commit_group;" ::: "memory");
    };

    issue(0);
    for (int ch = 0; ch < nch; ch++) {
        const bool more = (ch + 1) < nch;
        if (more) { issue(ch + 1); asm volatile("cp.async.wait_group 1;" ::: "memory"); }
        else      { asm volatile("cp.async.wait_group 0;" ::: "memory"); }
        __syncthreads();

        const uint32_t bsel = (uint32_t)(ch & 1) * BUF_B;

        #pragma unroll
        for (int step = 0; step < 2; step++) {
            uint32_t ah_[2][4], al_[2][4], bh_[4][2], bl_[4][2];
            #pragma unroll
            for (int mt = 0; mt < 2; mt++) {
                const uint32_t ad = adA[step][mt] + bsel;
                ldsm4(ah_[mt], ad);
                ldsm4(al_[mt], ad + A_TB);
            }
            #pragma unroll
            for (int j2 = 0; j2 < 2; j2++) {
                const uint32_t bd = adB[step][j2] + bsel;
                uint32_t tmp[4];
                ldsm4(tmp, bd);
                bh_[j2*2][0]=tmp[0]; bh_[j2*2][1]=tmp[1]; bh_[j2*2+1][0]=tmp[2]; bh_[j2*2+1][1]=tmp[3];
                ldsm4(tmp, bd + B_TB);
                bl_[j2*2][0]=tmp[0]; bl_[j2*2][1]=tmp[1]; bl_[j2*2+1][0]=tmp[2]; bl_[j2*2+1][1]=tmp[3];
            }
            #pragma unroll
            for (int mt = 0; mt < 2; mt++)
                #pragma unroll
                for (int nt = 0; nt < 4; nt++) mma_bf16(acc[mt][nt], ah_[mt], bh_[nt]);
            #pragma unroll
            for (int mt = 0; mt < 2; mt++)
                #pragma unroll
                for (int nt = 0; nt < 4; nt++) mma_bf16(acc[mt][nt], al_[mt], bh_[nt]);
            #pragma unroll
            for (int mt = 0; mt < 2; mt++)
                #pragma unroll
                for (int nt = 0; nt < 4; nt++) mma_bf16(acc[mt][nt], ah_[mt], bl_[nt]);
        }
        __syncthreads();
    }

    // epilogue
    float st_s[2][2], st_q[2][2];
    if (MODE == 3 || MODE == 4) {
        #pragma unroll
        for (int i = 0; i < 2; i++)
            #pragma unroll
            for (int j = 0; j < 2; j++) { st_s[i][j] = 0.f; st_q[i][j] = 0.f; }
    }
    #pragma unroll
    for (int mt = 0; mt < 2; mt++) {
        const int r0 = bm + wm*32 + mt*16 + (lane >> 2);
        #pragma unroll
        for (int nt = 0; nt < 4; nt++) {
            const int c0 = bn + wn*32 + nt*8 + (lane & 3)*2;
            float b0 = 0.f, b1 = 0.f;
            if (MODE == 2 || MODE == 3 || MODE == 4 || MODE == 5) { b0 = bias[c0]; b1 = bias[c0+1]; }
            #pragma unroll
            for (int h = 0; h < 2; h++) {
                const int row = r0 + h*8;
                if (row >= Mtrue) continue;
                float v0 = acc[mt][nt][h*2+0] + b0;
                float v1 = acc[mt][nt][h*2+1] + b1;
                if (MODE == 2) {
                    v0 = 0.5f*v0*(1.0f + erff(v0*0.7071067811865475f));
                    v1 = 0.5f*v1*(1.0f + erff(v1*0.7071067811865475f));
                    __nv_bfloat16 h0, l0, h1, l1;
                    bsplit(v0, h0, l0); bsplit(v1, h1, l1);
                    __nv_bfloat162 hv; hv.x = h0; hv.y = h1;
                    __nv_bfloat162 lv; lv.x = l0; lv.y = l1;
                    *(__nv_bfloat162*)&Csh[(size_t)row*N + c0] = hv;
                    *(__nv_bfloat162*)&Csl[(size_t)row*N + c0] = lv;
                } else if (MODE == 3) {
                    float2* cp = (float2*)&C[(size_t)row*N + c0];
                    float2 old = *cp;
                    old.x += v0; old.y += v1;
                    *cp = old;
                    st_s[mt][h] += old.x + old.y;
                    st_q[mt][h] += old.x*old.x + old.y*old.y;
                } else if (MODE == 5) {
                    float2* cp = (float2*)&C[(size_t)row*N + c0];
                    float2 old = *cp;
                    old.x += v0; old.y += v1;
                    *cp = old;
                    __nv_bfloat16 h0, l0, h1, l1;
                    bsplit(old.x, h0, l0); bsplit(old.y, h1, l1);
                    __nv_bfloat162 hv; hv.x = h0; hv.y = h1;
                    __nv_bfloat162 lv; lv.x = l0; lv.y = l1;
                    *(__nv_bfloat162*)&Csh[(size_t)row*N + c0] = hv;
                    *(__nv_bfloat162*)&Csl[(size_t)row*N + c0] = lv;
                } else if (MODE == 4) {
                    const float2 am = *(const float2*)&addm[(size_t)row*N + c0];
                    float2 fv; fv.x = v0 + am.x; fv.y = v1 + am.y;
                    *(float2*)&C[(size_t)row*N + c0] = fv;
                    st_s[mt][h] += fv.x + fv.y;
                    st_q[mt][h] += fv.x*fv.x + fv.y*fv.y;
                } else if (MODE == 6) {
                    // head: scatter to output image. row = gh*90+gw, col n -> (ph,pw,oc)
                    const int gh = row / 90, gw = row % 90;
                    #pragma unroll
                    for (int e = 0; e < 2; e++) {
                        const int n = c0 + e;
                        const int ph = n / 320;
                        const int rem = n - ph*320;
                        const int pw = rem / 20;
                        const int oc = rem - pw*20;
                        C[(size_t)oc*1036800 + (size_t)(gh*16 + ph)*1440 + (gw*16 + pw)]
                            = (e == 0 ? v0 : v1);
                    }
                } else {
                    float2 fv; fv.x = v0; fv.y = v1;
                    *(float2*)&C[(size_t)row*N + c0] = fv;
                }
            }
        }
    }
    if (MODE == 3 || MODE == 4) {
        // lanes 4k..4k+3 share the same row: reduce across the 4-lane group, one atomic pair per group
        #pragma unroll
        for (int mt = 0; mt < 2; mt++) {
            #pragma unroll
            for (int h = 0; h < 2; h++) {
                float s = st_s[mt][h], q = st_q[mt][h];
                s += __shfl_xor_sync(0xffffffffu, s, 1);
                q += __shfl_xor_sync(0xffffffffu, q, 1);
                s += __shfl_xor_sync(0xffffffffu, s, 2);
                q += __shfl_xor_sync(0xffffffffu, q, 2);
                const int row = bm + wm*32 + mt*16 + (lane >> 2) + h*8;
                if ((lane & 3) == 0 && row < Mtrue) {
                    atomicAdd(&g_ssum[row], s);
                    atomicAdd(&g_ssq[row],  q);
                }
            }
        }
    }
}

// ---------------- LN2 with bf16-split output (MLP half); also zeroes LN1 accumulators --------
__global__ void ln_bf16(const float* __restrict__ in,
                        __nv_bfloat16* __restrict__ oh, __nv_bfloat16* __restrict__ ol,
                        const float* __restrict__ w, const float* __restrict__ b)
{
    int tok = blockIdx.x;
    int tid = threadIdx.x;
    const float* row = in + (size_t)tok*EE;
    float x0 = row[tid], x1 = row[tid+256], x2 = row[tid+512];
    float s  = x0+x1+x2;
    float sq = x0*x0 + x1*x1 + x2*x2;
    #pragma unroll
    for (int o = 16; o > 0; o >>= 1) {
        s  += __shfl_down_sync(0xffffffffu, s,  o);
        sq += __shfl_down_sync(0xffffffffu, sq, o);
    }
    __shared__ float ss[8], ssq[8];
    int warp = tid >> 5, lane = tid & 31;
    if (lane == 0) { ss[warp] = s; ssq[warp] = sq; }
    __syncthreads();
    if (tid == 0) {
        float ts = 0.f, tq = 0.f;
        #pragma unroll
        for (int i = 0; i < 8; i++) { ts += ss[i]; tq += ssq[i]; }
        float m = ts * (1.0f/768.0f);
        float v = tq * (1.0f/768.0f) - m*m;
        ss[0] = m; ssq[0] = rsqrtf(v + 1e-5f);
        g_ssum[tok] = 0.f;   // reset LN1 accumulators for next layer's producer
        g_ssq[tok]  = 0.f;
    }
    __syncthreads();
    float m = ss[0], inv = ssq[0];
    size_t base = (size_t)tok*EE;
    #pragma unroll
    for (int j = 0; j < 3; j++) {
        int o = tid + j*256;
        float y = (j==0?x0:(j==1?x1:x2));
        y = (y - m)*inv*w[o] + b[o];
        __nv_bfloat16 h, l; bsplit(y, h, l);
        oh[base + o] = h; ol[base + o] = l;
    }
}

// ---------------- DHT stage kernels (LN fused via sums) ----------------
__global__ void k_wfwd(const float* __restrict__ nw, const float* __restrict__ nb) {
    extern __shared__ float sm[];          // 90*128 + 180
    float* stat = sm + 90*128;
    int c0 = blockIdx.x*128, h = blockIdx.y, tid = threadIdx.x;
    if (tid < 90) {
        float mu, ri;
        ln_from_sums(h*90+tid, mu, ri);
        stat[tid]    = mu;
        stat[90+tid] = ri;
    }
    __syncthreads();
    float wv = nw[c0+tid], bv = nb[c0+tid];
    for (int w = 0; w < 90; w++) {
        float av = g_A[(h*90+w)*EE + c0+tid];
        sm[w*128+tid] = (av - stat[w]) * stat[90+w] * wv + bv;
    }
    __syncthreads();
    for (int kw = 0; kw < 23; kw++) {
        float ar = 0.f, ai = 0.f;
        #pragma unroll 6
        for (int w = 0; w < 90; w++) {
            float v = sm[w*128+tid];
            ar += v * g_WC[kw*90+w];
            ai -= v * g_WS[kw*90+w];
        }
        g_Qr[(h*23+kw)*EE + c0+tid] = ar;
        g_Qi[(h*23+kw)*EE + c0+tid] = ai;
    }
}
__global__ void k_hfwd() {
    extern __shared__ float sm[];
    float* sr = sm; float* si = sm + 45*128;
    int c0 = blockIdx.x*128, kw = blockIdx.y, tid = threadIdx.x;
    for (int h = 0; h < 45; h++) {
        sr[h*128+tid] = g_Qr[(h*23+kw)*EE + c0+tid];
        si[h*128+tid] = g_Qi[(h*23+kw)*EE + c0+tid];
    }
    __syncthreads();
    for (int kh = 0; kh < 45; kh++) {
        float qr = 0.f, qi = 0.f;
        #pragma unroll 5
        for (int h = 0; h < 45; h++) {
            float ch = g_HC[kh*45+h], sh = g_HS[kh*45+h];
            float ur = sr[h*128+tid], ui = si[h*128+tid];
            qr += ur*ch + ui*sh;
            qi += ui*ch - ur*sh;
        }
        size_t row = (size_t)(kh*23+kw) * (2*EE);
        __nv_bfloat16 h2, l2;
        bsplit(qr, h2, l2); g_q2h[row + c0+tid] = h2;      g_q2l[row + c0+tid] = l2;
        bsplit(qi, h2, l2); g_q2h[row + EE + c0+tid] = h2; g_q2l[row + EE + c0+tid] = l2;
    }
}
__global__ void k_hinv2() {
    extern __shared__ float sm[];
    float* tr = sm; float* ti = sm + 45*128;
    int c0 = blockIdx.x*128, wp = blockIdx.y, tid = threadIdx.x;
    for (int hp = 0; hp < 45; hp++) {
        size_t row = (size_t)(hp*23+wp) * (2*EE);
        tr[hp*128+tid] = g_T[row + c0+tid];
        ti[hp*128+tid] = g_T[row + EE + c0+tid];
    }
    __syncthreads();
    for (int a = 0; a < 45; a++) {
        float zr = 0.f, zi = 0.f;
        #pragma unroll 5
        for (int hp = 0; hp < 45; hp++) {
            float ch = g_HC[a*45+hp], sh = g_HS[a*45+hp];
            float xr = tr[hp*128+tid], xi = ti[hp*128+tid];
            zr += xr*ch + xi*sh;
            zi += xi*ch - xr*sh;
        }
        g_Zr[(a*23+wp)*EE + c0+tid] = zr;
        g_Zi[(a*23+wp)*EE + c0+tid] = zi;
    }
}
// inverse W-stage: A += y + LN1(A) (normalization recomputed from sums)
__global__ void k_winv2(const float* __restrict__ nw, const float* __restrict__ nb) {
    extern __shared__ float sm[];
    float* zr = sm; float* zi = sm + 23*128;
    int c0 = blockIdx.x*128, a = blockIdx.y, tid = threadIdx.x;
    for (int wp = 0; wp < 23; wp++) {
        zr[wp*128+tid] = g_Zr[(a*23+wp)*EE + c0+tid];
        zi[wp*128+tid] = g_Zi[(a*23+wp)*EE + c0+tid];
    }
    __syncthreads();
    float wv = nw[c0+tid], bv = nb[c0+tid];
    for (int b = 0; b < 90; b++) {
        float y = 0.f;
        #pragma unroll
        for (int wp = 0; wp < 23; wp++) {
            y += zr[wp*128+tid]*g_WCm[b*90+wp] + zi[wp*128+tid]*g_WCp[b*90+wp];
        }
        int tok = a*90 + b;
        size_t idx = (size_t)tok*EE + c0+tid;
        float mu, ri;
        ln_from_sums(tok, mu, ri);
        float av = g_A[idx];
        float tv = (av - mu) * ri * wv + bv;
        g_A[idx] = av + y + tv;
    }
}

// ---------------- misc elementwise ----------------
__global__ void im2col_kernel(const float* __restrict__ x) {
    int idx = blockIdx.x*256 + threadIdx.x;
    if (idx >= NP*PKK) return;
    int p = idx / PKK, k = idx % PKK;
    int c = k >> 8, r = k & 255;
    int ph = r >> 4, pw = r & 15;
    int gh = p / 90, gw = p % 90;
    float v = x[(size_t)c*1036800 + (size_t)(gh*16+ph)*1440 + (gw*16+pw)];
    __nv_bfloat16 h, l; bsplit(v, h, l);
    size_t o = (size_t)p*PKK + k;
    g_pxh[o] = h; g_pxl[o] = l;
}

// ---------------- block-weight prep, ALL layers hoisted ----------------
__global__ void prep_pm_all(const float* __restrict__ w1, const float* __restrict__ w2) {
    int idx = blockIdx.x*256 + threadIdx.x;
    if (idx >= 12*BLK) return;
    int l = idx / BLK, i = idx % BLK;
    const float* w1l = w1 + (size_t)l*2*BLK;
    const float* w2l = w2 + (size_t)l*2*BLK;
    g_W1p[idx] = 0.5f*(w1l[i] + w1l[BLK+i]);
    g_W1m[idx] = 0.5f*(w1l[i] - w1l[BLK+i]);
    g_W2p[idx] = 0.5f*(w2l[i] + w2l[BLK+i]);
    g_W2m[idx] = 0.5f*(w2l[i] - w2l[BLK+i]);
}
__global__ void prep_ab_all() {
    int idx = blockIdx.x*128 + threadIdx.x;
    if (idx >= 12*BLK) return;
    int l = idx / BLK, rr = idx % BLK;
    int o = rr % 96;
    int i = (rr / 96) % 96;
    int b = rr / 9216;
    const float* P = g_W2p + (size_t)l*BLK + b*9216;
    const float* M = g_W2m + (size_t)l*BLK + b*9216;
    float aa = g_W2p[idx];
    float bb = g_W2m[idx] + g_W2p[idx];
    #pragma unroll 8
    for (int j = 0; j < 96; j++) {
        aa += P[i*96+j] * M[j*96+o];
        bb += M[i*96+j] * M[j*96+o];
    }
    g_W2a[idx] = aa;
    g_W2b[idx] = bb;
}
__global__ void prep_bs_all(const float* __restrict__ b2) {
    int idx = blockIdx.x*128 + threadIdx.x;
    if (idx >= 12*NBB*BSS) return;
    int l = idx / (NBB*BSS), rr = idx % (NBB*BSS);
    int o = rr % 96, b = rr / 96;
    const float* b2l = b2 + (size_t)l*2*NBB*BSS;
    float v = b2l[rr] + b2l[NBB*BSS + rr];
    const float* M = g_W2m + (size_t)l*BLK;
    #pragma unroll 8
    for (int j = 0; j < 96; j++) v += b2l[b*96+j] * M[(b*96+j)*96+o];
    g_bs[idx] = v;
}

// ---------------- fused block mixing (LN-gather + mix1 + mix2 + soft-thresh + split) ----------------
#define MROWS 45
#define MIXSM ((9216*2 + MROWS*96*2)*4)
__global__ void k_mixf(const float* __restrict__ b1l,
                       const float* __restrict__ nw, const float* __restrict__ nb,
                       int loff, int lbs) {
    extern __shared__ float sm[];
    float* sW1 = sm;
    float* sW2 = sm + 9216;
    float* sX  = sm + 18432;
    float* sY  = sX + MROWS*96;
    int b = blockIdx.x, tile = blockIdx.y;
    int t = threadIdx.x;
    int o = t % 96, rg = t / 96;
    for (int i = t; i < 9216; i += 288) {
        sW1[i] = g_W1p[loff + b*9216+i];
        sW2[i] = g_W1m[loff + b*9216+i];
    }
    int p0 = tile * MROWS;
    float nwv = nw[b*96+o], nbv = nb[b*96+o];
    for (int pp = rg; pp < MROWS; pp += 3) {
        int p = p0 + pp;
        int h = p / 23, w = p % 23;
        int shh = (45 - h) % 45;
        int sww = (90 - w) % 90;
        int tok = shh*90 + sww;
        float mu, ri;
        ln_from_sums(tok, mu, ri);
        float av = g_A[(size_t)tok*EE + b*96 + o];
        sX[pp*96+o] = g_a[(size_t)p*EE + b*96 + o];
        sY[pp*96+o] = (av - mu) * ri * nwv + nbv;   // fused LN gather
    }
    __syncthreads();
    float bk = b1l[b*96+o], bn = b1l[NBB*BSS + b*96+o];
    float ok_[15], on_[15];
    {
        int c = 0;
        for (int pp = rg; pp < MROWS; pp += 3, c++) {
            float ak = bk, an = bn;
            #pragma unroll 8
            for (int i = 0; i < 96; i++) {
                float xv = sX[pp*96+i], yv = sY[pp*96+i];
                float wp = sW1[i*96+o], wm = sW2[i*96+o];
                ak += xv*wp + yv*wm;
                an += yv*wp + xv*wm;
            }
            ok_[c] = fmaxf(ak, 0.f);
            on_[c] = fmaxf(an, 0.f);
        }
    }
    __syncthreads();
    {
        int c = 0;
        for (int pp = rg; pp < MROWS; pp += 3, c++) {
            sX[pp*96+o] = ok_[c];
            sY[pp*96+o] = on_[c];
        }
    }
    for (int i = t; i < 9216; i += 288) {
        sW1[i] = g_W2a[loff + b*9216+i];
        sW2[i] = g_W2b[loff + b*9216+i];
    }
    __syncthreads();
    float bsv = g_bs[lbs + b*96+o];
    for (int pp = rg; pp < MROWS; pp += 3) {
        float acc = bsv;
        #pragma unroll 8
        for (int i = 0; i < 96; i++) {
            acc += sX[pp*96+i]*sW1[i*96+o] + sY[pp*96+i]*sW2[i*96+o];
        }
        float aab = fabsf(acc) - 0.01f;
        float v = (aab > 0.f) ? copysignf(aab, acc) : 0.f;
        __nv_bfloat16 h, l; bsplit(v, h, l);
        size_t idx = (size_t)(p0+pp)*EE + b*96 + o;
        g_sh[idx] = h; g_sl[idx] = l;
    }
}

// ---------------- host orchestration ----------------
extern "C" void kernel_launch(void* const* d_in, const int* in_sizes, int n_in,
                              void* d_out, int out_size)
{
    const float* x        = (const float*)d_in[0];
    const float* patch_w  = (const float*)d_in[1];
    const float* patch_b  = (const float*)d_in[2];
    const float* pos      = (const float*)d_in[3];
    const float* norm1_w  = (const float*)d_in[4];
    const float* norm1_b  = (const float*)d_in[5];
    const float* w1       = (const float*)d_in[6];
    const float* b1       = (const float*)d_in[7];
    const float* w2       = (const float*)d_in[8];
    const float* b2       = (const float*)d_in[9];
    const float* norm2_w  = (const float*)d_in[10];
    const float* norm2_b  = (const float*)d_in[11];
    const float* fc1_w    = (const float*)d_in[12];
    const float* fc1_b    = (const float*)d_in[13];
    const float* fc2_w    = (const float*)d_in[14];
    const float* fc2_b    = (const float*)d_in[15];
    const float* head_w   = (const float*)d_in[16];
    float* out = (float*)d_out;

    float *pA,*pTT,*pa;
    cudaGetSymbolAddress((void**)&pA,  g_A);
    cudaGetSymbolAddress((void**)&pTT, g_T);
    cudaGetSymbolAddress((void**)&pa,  g_a);

    __nv_bfloat16 *pxh,*pxl,*th,*tl,*hbh,*hbl,*ah2,*al2,*q2h,*q2l,*sh,*sl;
    __nv_bfloat16 *pwh,*pwl,*fBh,*fBl,*iBh,*iBl,*f1h,*f1l,*f2h,*f2l,*hwh,*hwl;
    cudaGetSymbolAddress((void**)&pxh, g_pxh);  cudaGetSymbolAddress((void**)&pxl, g_pxl);
    cudaGetSymbolAddress((void**)&th,  g_th);   cudaGetSymbolAddress((void**)&tl,  g_tl);
    cudaGetSymbolAddress((void**)&hbh, g_hbh);  cudaGetSymbolAddress((void**)&hbl, g_hbl);
    cudaGetSymbolAddress((void**)&ah2, g_Ah2);  cudaGetSymbolAddress((void**)&al2, g_Al2);
    cudaGetSymbolAddress((void**)&q2h, g_q2h);  cudaGetSymbolAddress((void**)&q2l, g_q2l);
    cudaGetSymbolAddress((void**)&sh,  g_sh);   cudaGetSymbolAddress((void**)&sl,  g_sl);
    cudaGetSymbolAddress((void**)&pwh, g_pwh);  cudaGetSymbolAddress((void**)&pwl, g_pwl);
    cudaGetSymbolAddress((void**)&fBh, g_fBh);  cudaGetSymbolAddress((void**)&fBl, g_fBl);
    cudaGetSymbolAddress((void**)&iBh, g_iBh);  cudaGetSymbolAddress((void**)&iBl, g_iBl);
    cudaGetSymbolAddress((void**)&f1h, g_f1h);  cudaGetSymbolAddress((void**)&f1l, g_f1l);
    cudaGetSymbolAddress((void**)&f2h, g_f2h);  cudaGetSymbolAddress((void**)&f2l, g_f2l);
    cudaGetSymbolAddress((void**)&hwh, g_hwh);  cudaGetSymbolAddress((void**)&hwl, g_hwl);

    cudaFuncSetAttribute(k_wfwd,  cudaFuncAttributeMaxDynamicSharedMemorySize, 90*128*4 + 180*4);
    cudaFuncSetAttribute(k_hfwd,  cudaFuncAttributeMaxDynamicSharedMemorySize, 2*45*128*4);
    cudaFuncSetAttribute(k_hinv2, cudaFuncAttributeMaxDynamicSharedMemorySize, 2*45*128*4);
    cudaFuncSetAttribute(k_winv2, cudaFuncAttributeMaxDynamicSharedMemorySize, 2*23*128*4);
    cudaFuncSetAttribute(k_mixf,  cudaFuncAttributeMaxDynamicSharedMemorySize, MIXSM);
    cudaFuncSetAttribute(hgemm<0>, cudaFuncAttributeMaxDynamicSharedMemorySize, 2*BUF_B);
    cudaFuncSetAttribute(hgemm<2>, cudaFuncAttributeMaxDynamicSharedMemorySize, 2*BUF_B);
    cudaFuncSetAttribute(hgemm<3>, cudaFuncAttributeMaxDynamicSharedMemorySize, 2*BUF_B);
    cudaFuncSetAttribute(hgemm<4>, cudaFuncAttributeMaxDynamicSharedMemorySize, 2*BUF_B);
    cudaFuncSetAttribute(hgemm<5>, cudaFuncAttributeMaxDynamicSharedMemorySize, 2*BUF_B);
    cudaFuncSetAttribute(hgemm<6>, cudaFuncAttributeMaxDynamicSharedMemorySize, 2*BUF_B);

    // tables + weight splits + ALL-layer block-weight prep (once)
    tabC <<<(EE*EE + 255)/256, 256>>>();
    tab90<<<(GWw*GWw + 255)/256, 256>>>();
    tab45<<<(GHh*GHh + 255)/256, 256>>>();
    split_kernel<<<(EE*PKK + 255)/256, 256>>>(patch_w, pwh, pwl, EE*PKK);
    split_kernel<<<(HDD*EE + 255)/256, 256>>>(head_w, hwh, hwl, HDD*EE);
    split_kernel<<<(12*HID*EE + 255)/256, 256>>>(fc1_w, f1h, f1l, 12*HID*EE);
    split_kernel<<<(12*EE*HID + 255)/256, 256>>>(fc2_w, f2h, f2l, 12*EE*HID);
    prep_pm_all<<<(12*BLK + 255)/256, 256>>>(w1, w2);
    prep_ab_all<<<(12*BLK + 127)/128, 128>>>();
    prep_bs_all<<<(12*NBB*BSS + 127)/128, 128>>>(b2);

    const dim3 GB(256);
    const int SMB = 2*BUF_B;

    // patch embed (bias + pos fused; emits LN1 stats for layer 0)
    im2col_kernel<<<(NP*PKK + 255)/256, 256>>>(x);
    hgemm<4><<<dim3(EE/64, MPAD/128), GB, SMB>>>(pxh, pxl, pwh, pwl, pA, nullptr, nullptr,
                                                 NP, EE, PKK, patch_b, pos);

    for (int l = 0; l < 12; l++) {
        // ---- AFNO half ----
        k_wfwd<<<dim3(6, 45), 128, 90*128*4 + 180*4>>>(norm1_w + l*EE, norm1_b + l*EE);
        k_hfwd<<<dim3(6, 23), 128, 2*45*128*4>>>();
        hgemm<0><<<dim3(EE/64, FPAD/128), GB, SMB>>>(q2h, q2l, fBh, fBl, pa, nullptr, nullptr,
                                                     NFREQ, EE, 2*EE, nullptr, nullptr);
        k_mixf<<<dim3(8, 23), 288, MIXSM>>>(b1 + (size_t)l*2*NBB*BSS,
                                            norm1_w + l*EE, norm1_b + l*EE, l*BLK, l*NBB*BSS);
        hgemm<0><<<dim3((2*EE)/64, FPAD/128), GB, SMB>>>(sh, sl, iBh, iBl, pTT, nullptr, nullptr,
                                                         NFREQ, 2*EE, EE, nullptr, nullptr);
        k_hinv2<<<dim3(6, 23), 128, 2*45*128*4>>>();
        k_winv2<<<dim3(6, 45), 128, 2*23*128*4>>>(norm1_w + l*EE, norm1_b + l*EE);

        // ---- MLP half ----
        ln_bf16<<<NP, 256>>>(pA, th, tl, norm2_w + l*EE, norm2_b + l*EE);
        hgemm<2><<<dim3(HID/64, MPAD/128), GB, SMB>>>(th, tl, f1h + (size_t)l*HID*EE, f1l + (size_t)l*HID*EE,
                                                      nullptr, hbh, hbl, NP, HID, EE, fc1_b + l*HID, nullptr);
        if (l < 11) {
            hgemm<3><<<dim3(EE/64, MPAD/128), GB, SMB>>>(hbh, hbl, f2h + (size_t)l*EE*HID, f2l + (size_t)l*EE*HID,
                                                         pA, nullptr, nullptr, NP, EE, HID, fc2_b + l*EE, nullptr);
        } else {
            hgemm<5><<<dim3(EE/64, MPAD/128), GB, SMB>>>(hbh, hbl, f2h + (size_t)l*EE*HID, f2l + (size_t)l*EE*HID,
                                                         pA, ah2, al2, NP, EE, HID, fc2_b + l*EE, nullptr);
        }
    }

    // head: GEMM scatters directly into the output image (no scatter pass)
    hgemm<6><<<dim3(HDD/64, MPAD/128), GB, SMB>>>(ah2, al2, hwh, hwl, out, nullptr, nullptr,
                                                  NP, HDD, EE, nullptr, nullptr);
}

// round 12
// speedup vs baseline: 2.3776x; 1.0069x over previous
#include <cuda_runtime.h>
#include <cuda_bf16.h>
#include <math.h>
#include <stdint.h>

// ---------------- constants ----------------
#define GHh 45
#define GWw 90
#define NP 4050          // tokens
#define MPAD 4096        // padded token rows
#define EE 768
#define KM 23
#define NFREQ (GHh*KM)   // 1035
#define FPAD 1152        // padded freq rows (9*128)
#define HID 3072
#define PKK 5120
#define HDD 5120
#define NBB 8
#define BSS 96
#define BLK (NBB*BSS*BSS)   // 73728 per layer
#define DHT_SIZE 3110400.0

// ---------------- fp32 scratch ----------------
__device__ __align__(128) float g_A [NP*EE];
__device__ __align__(128) float g_T [2*(size_t)NP*EE];     // inverse C-stage out, 2 split-K partials
__device__ __align__(128) float g_Qr[NFREQ*EE];
__device__ __align__(128) float g_Qi[NFREQ*EE];
__device__ __align__(128) float g_Zr[NFREQ*EE];
__device__ __align__(128) float g_Zi[NFREQ*EE];
__device__ __align__(128) float g_a [2*(size_t)NFREQ*EE];  // fwd C-stage out, 2 split-K partials
__device__ __align__(128) float g_ssum[NP];
__device__ __align__(128) float g_ssq [NP];
// small DFT tables
__device__ __align__(128) float g_WC[GWw*GWw];
__device__ __align__(128) float g_WS[GWw*GWw];
__device__ __align__(128) float g_WCm[GWw*GWw];   // (cos-sin)/SIZE
__device__ __align__(128) float g_WCp[GWw*GWw];   // (cos+sin)/SIZE
__device__ __align__(128) float g_HC[GHh*GHh];
__device__ __align__(128) float g_HS[GHh*GHh];
// per-layer prepped block weights (ALL 12 layers, hoisted)
__device__ __align__(128) float g_W1p[12*BLK], g_W1m[12*BLK];
__device__ __align__(128) float g_W2p[12*BLK], g_W2m[12*BLK];
__device__ __align__(128) float g_W2a[12*BLK], g_W2b[12*BLK];
__device__ __align__(128) float g_bs [12*NBB*BSS];

// ---------------- bf16 split buffers (hi/lo) ----------------
__device__ __align__(128) __nv_bfloat16 g_pxh[(size_t)MPAD*PKK], g_pxl[(size_t)MPAD*PKK];
__device__ __align__(128) __nv_bfloat16 g_th [(size_t)MPAD*EE],  g_tl [(size_t)MPAD*EE];
__device__ __align__(128) __nv_bfloat16 g_hbh[(size_t)MPAD*HID], g_hbl[(size_t)MPAD*HID];
__device__ __align__(128) __nv_bfloat16 g_Ah2[(size_t)MPAD*EE],  g_Al2[(size_t)MPAD*EE];
__device__ __align__(128) __nv_bfloat16 g_q2h[(size_t)FPAD*2*EE], g_q2l[(size_t)FPAD*2*EE];
__device__ __align__(128) __nv_bfloat16 g_sh [(size_t)FPAD*EE],  g_sl [(size_t)FPAD*EE];
// weights / tables
__device__ __align__(128) __nv_bfloat16 g_pwh[EE*PKK],  g_pwl[EE*PKK];
__device__ __align__(128) __nv_bfloat16 g_fBh[EE*2*EE], g_fBl[EE*2*EE];   // fwd C B
__device__ __align__(128) __nv_bfloat16 g_iBh[2*EE*EE], g_iBl[2*EE*EE];   // inv C B
__device__ __align__(128) __nv_bfloat16 g_f1h[(size_t)12*HID*EE], g_f1l[(size_t)12*HID*EE];
__device__ __align__(128) __nv_bfloat16 g_f2h[(size_t)12*EE*HID], g_f2l[(size_t)12*EE*HID];
__device__ __align__(128) __nv_bfloat16 g_hwh[HDD*EE],  g_hwl[HDD*EE];

// ---------------- helpers ----------------
__device__ __forceinline__ void bsplit(float x, __nv_bfloat16& h, __nv_bfloat16& l) {
    h = __float2bfloat16(x);
    l = __float2bfloat16(x - __bfloat162float(h));
}
__device__ __forceinline__ uint32_t s2u32(const void* p) {
    uint32_t a;
    asm("{ .reg .u64 t; cvta.to.shared.u64 t, %1; cvt.u32.u64 %0, t; }" : "=r"(a) : "l"(p));
    return a;
}
__device__ __forceinline__ void mma_bf16(float* c, const uint32_t* a, const uint32_t* b) {
    asm volatile("mma.sync.aligned.m16n8k16.row.col.f32.bf16.bf16.f32 "
        "{%0,%1,%2,%3}, {%4,%5,%6,%7}, {%8,%9}, {%0,%1,%2,%3};"
        : "+f"(c[0]), "+f"(c[1]), "+f"(c[2]), "+f"(c[3])
        : "r"(a[0]), "r"(a[1]), "r"(a[2]), "r"(a[3]), "r"(b[0]), "r"(b[1]));
}
__device__ __forceinline__ void cpa16(uint32_t dst, const void* src) {
    asm volatile("cp.async.cg.shared.global [%0], [%1], 16;" :: "r"(dst), "l"(src));
}
__device__ __forceinline__ void ldsm4(uint32_t* r, uint32_t addr) {
    asm volatile("ldmatrix.sync.aligned.m8n8.x4.shared.b16 {%0,%1,%2,%3}, [%4];"
        : "=r"(r[0]), "=r"(r[1]), "=r"(r[2]), "=r"(r[3]) : "r"(addr));
}
__device__ __forceinline__ void ln_from_sums(int tok, float& mu, float& ri) {
    float s = g_ssum[tok], q = g_ssq[tok];
    mu = s * (1.0f/768.0f);
    float v = q * (1.0f/768.0f) - mu*mu;
    ri = rsqrtf(v + 1e-5f);
}

// ---------------- table init ----------------
__global__ void tabC() {
    int idx = blockIdx.x*256 + threadIdx.x;
    if (idx >= EE*EE) return;
    int kc = idx / EE, c = idx % EE;
    long long m = ((long long)kc * c) % EE;
    double a = 2.0 * (double)m / (double)EE;
    double cs = cospi(a), sn = sinpi(a);
    __nv_bfloat16 h, l;
    bsplit((float)(cs - sn), h, l); g_fBh[kc*2*EE + c]      = h; g_fBl[kc*2*EE + c]      = l;
    bsplit((float)(cs + sn), h, l); g_fBh[kc*2*EE + EE + c] = h; g_fBl[kc*2*EE + EE + c] = l;
    bsplit((float)cs, h, l);        g_iBh[kc*EE + c]        = h; g_iBl[kc*EE + c]        = l;
    bsplit((float)(-sn), h, l);     g_iBh[(EE+kc)*EE + c]   = h; g_iBl[(EE+kc)*EE + c]   = l;
}
__global__ void tab90() {
    int idx = blockIdx.x*256 + threadIdx.x;
    if (idx >= GWw*GWw) return;
    int a = idx / GWw, b = idx % GWw;
    long long m = ((long long)a * b) % GWw;
    double ang = 2.0 * (double)m / (double)GWw;
    double cs = cospi(ang), sn = sinpi(ang);
    g_WC[idx]  = (float)cs;
    g_WS[idx]  = (float)sn;
    g_WCm[idx] = (float)((cs - sn) / DHT_SIZE);
    g_WCp[idx] = (float)((cs + sn) / DHT_SIZE);
}
__global__ void tab45() {
    int idx = blockIdx.x*256 + threadIdx.x;
    if (idx >= GHh*GHh) return;
    int a = idx / GHh, b = idx % GHh;
    long long m = ((long long)a * b) % GHh;
    double ang = 2.0 * (double)m / (double)GHh;
    g_HC[idx] = (float)cospi(ang);
    g_HS[idx] = (float)sinpi(ang);
}

__global__ void split_kernel(const float* __restrict__ in,
                             __nv_bfloat16* __restrict__ oh,
                             __nv_bfloat16* __restrict__ ol, int n) {
    int i = blockIdx.x*256 + threadIdx.x;
    if (i >= n) return;
    __nv_bfloat16 h, l;
    bsplit(in[i], h, l);
    oh[i] = h; ol[i] = l;
}

// ---------------- bf16x3 mma.sync GEMM, tile 128Mx64N, k-chunk 32, optional split-K ----
// MODE: 0=store fp32 (+split-K via blockIdx.z -> C+z*zoff), 2=bias+GELU->bf16 split,
//       3=accumulate(+bias) fp32 + LN stats, 4=store+bias+addmat + LN stats,
//       5=accumulate(+bias) fp32 AND emit bf16 split, 6=head scatter to output image
#define SMSTR 40
#define A_TB (128*SMSTR*2)
#define B_TB (64*SMSTR*2)
#define BUF_B (2*A_TB + 2*B_TB)

template<int MODE>
__global__ void __launch_bounds__(256, 3)
hgemm(const __nv_bfloat16* __restrict__ Ah, const __nv_bfloat16* __restrict__ Al,
      const __nv_bfloat16* __restrict__ Bh, const __nv_bfloat16* __restrict__ Bl,
      float* __restrict__ C,
      __nv_bfloat16* __restrict__ Csh, __nv_bfloat16* __restrict__ Csl,
      int Mtrue, int N, int K, const float* __restrict__ bias,
      const float* __restrict__ addm, int ld, long zoff)
{
    extern __shared__ __align__(128) char smem[];
    const int t = threadIdx.x, warp = t >> 5, lane = t & 31;
    const int wm = warp >> 1, wn = warp & 1;
    const int bm = blockIdx.y * 128, bn = blockIdx.x * 64;
    const int kz = blockIdx.z;
    const size_t kbase = (size_t)kz * K;
    if (MODE == 0) C += (size_t)kz * zoff;
    const uint32_t sb = s2u32(smem);

    float acc[2][4][4];
    #pragma unroll
    for (int i = 0; i < 2; i++)
        #pragma unroll
        for (int j = 0; j < 4; j++)
            #pragma unroll
            for (int q = 0; q < 4; q++) acc[i][j][q] = 0.f;

    const int arow = t & 127, ahalf = t >> 7;
    const __nv_bfloat16* pAh = Ah + (size_t)(bm + arow) * ld + kbase + ahalf * 16;
    const __nv_bfloat16* pAl = Al + (size_t)(bm + arow) * ld + kbase + ahalf * 16;
    const uint32_t aoff = (uint32_t)(arow * SMSTR + ahalf * 16) * 2;
    const int brow = t >> 2, bseg = t & 3;
    const __nv_bfloat16* pBh = Bh + (size_t)(bn + brow) * ld + kbase + bseg * 8;
    const __nv_bfloat16* pBl = Bl + (size_t)(bn + brow) * ld + kbase + bseg * 8;
    const uint32_t boff = (uint32_t)(brow * SMSTR + bseg * 8) * 2;

    // precomputed LDSM base addresses (buffer 0); in-loop: + parity*BUF_B
    uint32_t adA[2][2], adB[2][2];
    {
        const int g = lane >> 3, r = lane & 7;
        #pragma unroll
        for (int step = 0; step < 2; step++) {
            const int ks = step * 16;
            const uint32_t a_off = (uint32_t)(((g & 1) * 8 + r) * SMSTR + ks + (g >> 1) * 8) * 2;
            const uint32_t b_off = (uint32_t)(((g >> 1) * 8 + r) * SMSTR + ks + (g & 1) * 8) * 2;
            #pragma unroll
            for (int mt = 0; mt < 2; mt++)
                adA[step][mt] = sb + (uint32_t)((wm*32 + mt*16) * SMSTR) * 2 + a_off;
            #pragma unroll
            for (int j2 = 0; j2 < 2; j2++)
                adB[step][j2] = sb + 2*A_TB + (uint32_t)((wn*32 + j2*16) * SMSTR) * 2 + b_off;
        }
    }

    const int nch = K >> 5;
    auto issue = [&](int ch) {
        const int k0 = ch << 5;
        const uint32_t dst = sb + (uint32_t)(ch & 1) * BUF_B;
        cpa16(dst + aoff,        pAh + k0); cpa16(dst + aoff + 16,        pAh + k0 + 8);
        cpa16(dst + A_TB + aoff, pAl + k0); cpa16(dst + A_TB + aoff + 16, pAl + k0 + 8);
        cpa16(dst + 2*A_TB + boff,        pBh + k0);
        cpa16(dst + 2*A_TB + B_TB + boff, pBl + k0);
        asm volatile("cp.async.commit_group;" ::: "memory");
    };

    issue(0);
    for (int ch = 0; ch < nch; ch++) {
        const bool more = (ch + 1) < nch;
        if (more) { issue(ch + 1); asm volatile("cp.async.wait_group 1;" ::: "memory"); }
        else      { asm volatile("cp.async.wait_group 0;" ::: "memory"); }
        __syncthreads();

        const uint32_t bsel = (uint32_t)(ch & 1) * BUF_B;

        #pragma unroll
        for (int step = 0; step < 2; step++) {
            uint32_t ah_[2][4], al_[2][4], bh_[4][2], bl_[4][2];
            #pragma unroll
            for (int mt = 0; mt < 2; mt++) {
                const uint32_t ad = adA[step][mt] + bsel;
                ldsm4(ah_[mt], ad);
                ldsm4(al_[mt], ad + A_TB);
            }
            #pragma unroll
            for (int j2 = 0; j2 < 2; j2++) {
                const uint32_t bd = adB[step][j2] + bsel;
                uint32_t tmp[4];
                ldsm4(tmp, bd);
                bh_[j2*2][0]=tmp[0]; bh_[j2*2][1]=tmp[1]; bh_[j2*2+1][0]=tmp[2]; bh_[j2*2+1][1]=tmp[3];
                ldsm4(tmp, bd + B_TB);
                bl_[j2*2][0]=tmp[0]; bl_[j2*2][1]=tmp[1]; bl_[j2*2+1][0]=tmp[2]; bl_[j2*2+1][1]=tmp[3];
            }
            #pragma unroll
            for (int mt = 0; mt < 2; mt++)
                #pragma unroll
                for (int nt = 0; nt < 4; nt++) mma_bf16(acc[mt][nt], ah_[mt], bh_[nt]);
            #pragma unroll
            for (int mt = 0; mt < 2; mt++)
                #pragma unroll
                for (int nt = 0; nt < 4; nt++) mma_bf16(acc[mt][nt], al_[mt], bh_[nt]);
            #pragma unroll
            for (int mt = 0; mt < 2; mt++)
                #pragma unroll
                for (int nt = 0; nt < 4; nt++) mma_bf16(acc[mt][nt], ah_[mt], bl_[nt]);
        }
        __syncthreads();
    }

    // epilogue
    float st_s[2][2], st_q[2][2];
    if (MODE == 3 || MODE == 4) {
        #pragma unroll
        for (int i = 0; i < 2; i++)
            #pragma unroll
            for (int j = 0; j < 2; j++) { st_s[i][j] = 0.f; st_q[i][j] = 0.f; }
    }
    #pragma unroll
    for (int mt = 0; mt < 2; mt++) {
        const int r0 = bm + wm*32 + mt*16 + (lane >> 2);
        #pragma unroll
        for (int nt = 0; nt < 4; nt++) {
            const int c0 = bn + wn*32 + nt*8 + (lane & 3)*2;
            float b0 = 0.f, b1 = 0.f;
            if (MODE == 2 || MODE == 3 || MODE == 4 || MODE == 5) { b0 = bias[c0]; b1 = bias[c0+1]; }
            #pragma unroll
            for (int h = 0; h < 2; h++) {
                const int row = r0 + h*8;
                if (row >= Mtrue) continue;
                float v0 = acc[mt][nt][h*2+0] + b0;
                float v1 = acc[mt][nt][h*2+1] + b1;
                if (MODE == 2) {
                    v0 = 0.5f*v0*(1.0f + erff(v0*0.7071067811865475f));
                    v1 = 0.5f*v1*(1.0f + erff(v1*0.7071067811865475f));
                    __nv_bfloat16 h0, l0, h1, l1;
                    bsplit(v0, h0, l0); bsplit(v1, h1, l1);
                    __nv_bfloat162 hv; hv.x = h0; hv.y = h1;
                    __nv_bfloat162 lv; lv.x = l0; lv.y = l1;
                    *(__nv_bfloat162*)&Csh[(size_t)row*N + c0] = hv;
                    *(__nv_bfloat162*)&Csl[(size_t)row*N + c0] = lv;
                } else if (MODE == 3) {
                    float2* cp = (float2*)&C[(size_t)row*N + c0];
                    float2 old = *cp;
                    old.x += v0; old.y += v1;
                    *cp = old;
                    st_s[mt][h] += old.x + old.y;
                    st_q[mt][h] += old.x*old.x + old.y*old.y;
                } else if (MODE == 5) {
                    float2* cp = (float2*)&C[(size_t)row*N + c0];
                    float2 old = *cp;
                    old.x += v0; old.y += v1;
                    *cp = old;
                    __nv_bfloat16 h0, l0, h1, l1;
                    bsplit(old.x, h0, l0); bsplit(old.y, h1, l1);
                    __nv_bfloat162 hv; hv.x = h0; hv.y = h1;
                    __nv_bfloat162 lv; lv.x = l0; lv.y = l1;
                    *(__nv_bfloat162*)&Csh[(size_t)row*N + c0] = hv;
                    *(__nv_bfloat162*)&Csl[(size_t)row*N + c0] = lv;
                } else if (MODE == 4) {
                    const float2 am = *(const float2*)&addm[(size_t)row*N + c0];
                    float2 fv; fv.x = v0 + am.x; fv.y = v1 + am.y;
                    *(float2*)&C[(size_t)row*N + c0] = fv;
                    st_s[mt][h] += fv.x + fv.y;
                    st_q[mt][h] += fv.x*fv.x + fv.y*fv.y;
                } else if (MODE == 6) {
                    const int gh = row / 90, gw = row % 90;
                    #pragma unroll
                    for (int e = 0; e < 2; e++) {
                        const int n = c0 + e;
                        const int ph = n / 320;
                        const int rem = n - ph*320;
                        const int pw = rem / 20;
                        const int oc = rem - pw*20;
                        C[(size_t)oc*1036800 + (size_t)(gh*16 + ph)*1440 + (gw*16 + pw)]
                            = (e == 0 ? v0 : v1);
                    }
                } else {
                    float2 fv; fv.x = v0; fv.y = v1;
                    *(float2*)&C[(size_t)row*N + c0] = fv;
                }
            }
        }
    }
    if (MODE == 3 || MODE == 4) {
        #pragma unroll
        for (int mt = 0; mt < 2; mt++) {
            #pragma unroll
            for (int h = 0; h < 2; h++) {
                float s = st_s[mt][h], q = st_q[mt][h];
                s += __shfl_xor_sync(0xffffffffu, s, 1);
                q += __shfl_xor_sync(0xffffffffu, q, 1);
                s += __shfl_xor_sync(0xffffffffu, s, 2);
                q += __shfl_xor_sync(0xffffffffu, q, 2);
                const int row = bm + wm*32 + mt*16 + (lane >> 2) + h*8;
                if ((lane & 3) == 0 && row < Mtrue) {
                    atomicAdd(&g_ssum[row], s);
                    atomicAdd(&g_ssq[row],  q);
                }
            }
        }
    }
}

// ---------------- LN2 with bf16-split output (MLP half); also zeroes LN1 accumulators --------
__global__ void ln_bf16(const float* __restrict__ in,
                        __nv_bfloat16* __restrict__ oh, __nv_bfloat16* __restrict__ ol,
                        const float* __restrict__ w, const float* __restrict__ b)
{
    int tok = blockIdx.x;
    int tid = threadIdx.x;
    const float* row = in + (size_t)tok*EE;
    float x0 = row[tid], x1 = row[tid+256], x2 = row[tid+512];
    float s  = x0+x1+x2;
    float sq = x0*x0 + x1*x1 + x2*x2;
    #pragma unroll
    for (int o = 16; o > 0; o >>= 1) {
        s  += __shfl_down_sync(0xffffffffu, s,  o);
        sq += __shfl_down_sync(0xffffffffu, sq, o);
    }
    __shared__ float ss[8], ssq[8];
    int warp = tid >> 5, lane = tid & 31;
    if (lane == 0) { ss[warp] = s; ssq[warp] = sq; }
    __syncthreads();
    if (tid == 0) {
        float ts = 0.f, tq = 0.f;
        #pragma unroll
        for (int i = 0; i < 8; i++) { ts += ss[i]; tq += ssq[i]; }
        float m = ts * (1.0f/768.0f);
        float v = tq * (1.0f/768.0f) - m*m;
        ss[0] = m; ssq[0] = rsqrtf(v + 1e-5f);
        g_ssum[tok] = 0.f;
        g_ssq[tok]  = 0.f;
    }
    __syncthreads();
    float m = ss[0], inv = ssq[0];
    size_t base = (size_t)tok*EE;
    #pragma unroll
    for (int j = 0; j < 3; j++) {
        int o = tid + j*256;
        float y = (j==0?x0:(j==1?x1:x2));
        y = (y - m)*inv*w[o] + b[o];
        __nv_bfloat16 h, l; bsplit(y, h, l);
        oh[base + o] = h; ol[base + o] = l;
    }
}

// ---------------- DHT stage kernels (LN fused via sums) ----------------
__global__ void k_wfwd(const float* __restrict__ nw, const float* __restrict__ nb) {
    extern __shared__ float sm[];          // 90*128 + 180
    float* stat = sm + 90*128;
    int c0 = blockIdx.x*128, h = blockIdx.y, tid = threadIdx.x;
    if (tid < 90) {
        float mu, ri;
        ln_from_sums(h*90+tid, mu, ri);
        stat[tid]    = mu;
        stat[90+tid] = ri;
    }
    __syncthreads();
    float wv = nw[c0+tid], bv = nb[c0+tid];
    for (int w = 0; w < 90; w++) {
        float av = g_A[(h*90+w)*EE + c0+tid];
        sm[w*128+tid] = (av - stat[w]) * stat[90+w] * wv + bv;
    }
    __syncthreads();
    for (int kw = 0; kw < 23; kw++) {
        float ar = 0.f, ai = 0.f;
        #pragma unroll 6
        for (int w = 0; w < 90; w++) {
            float v = sm[w*128+tid];
            ar += v * g_WC[kw*90+w];
            ai -= v * g_WS[kw*90+w];
        }
        g_Qr[(h*23+kw)*EE + c0+tid] = ar;
        g_Qi[(h*23+kw)*EE + c0+tid] = ai;
    }
}
__global__ void k_hfwd() {
    extern __shared__ float sm[];
    float* sr = sm; float* si = sm + 45*128;
    int c0 = blockIdx.x*128, kw = blockIdx.y, tid = threadIdx.x;
    for (int h = 0; h < 45; h++) {
        sr[h*128+tid] = g_Qr[(h*23+kw)*EE + c0+tid];
        si[h*128+tid] = g_Qi[(h*23+kw)*EE + c0+tid];
    }
    __syncthreads();
    for (int kh = 0; kh < 45; kh++) {
        float qr = 0.f, qi = 0.f;
        #pragma unroll 5
        for (int h = 0; h < 45; h++) {
            float ch = g_HC[kh*45+h], sh = g_HS[kh*45+h];
            float ur = sr[h*128+tid], ui = si[h*128+tid];
            qr += ur*ch + ui*sh;
            qi += ui*ch - ur*sh;
        }
        size_t row = (size_t)(kh*23+kw) * (2*EE);
        __nv_bfloat16 h2, l2;
        bsplit(qr, h2, l2); g_q2h[row + c0+tid] = h2;      g_q2l[row + c0+tid] = l2;
        bsplit(qi, h2, l2); g_q2h[row + EE + c0+tid] = h2; g_q2l[row + EE + c0+tid] = l2;
    }
}
__global__ void k_hinv2() {
    extern __shared__ float sm[];
    float* tr = sm; float* ti = sm + 45*128;
    int c0 = blockIdx.x*128, wp = blockIdx.y, tid = threadIdx.x;
    for (int hp = 0; hp < 45; hp++) {
        size_t row = (size_t)(hp*23+wp) * (2*EE);
        tr[hp*128+tid] = g_T[row + c0+tid]      + g_T[(size_t)NP*EE + row + c0+tid];
        ti[hp*128+tid] = g_T[row + EE + c0+tid] + g_T[(size_t)NP*EE + row + EE + c0+tid];
    }
    __syncthreads();
    for (int a = 0; a < 45; a++) {
        float zr = 0.f, zi = 0.f;
        #pragma unroll 5
        for (int hp = 0; hp < 45; hp++) {
            float ch = g_HC[a*45+hp], sh = g_HS[a*45+hp];
            float xr = tr[hp*128+tid], xi = ti[hp*128+tid];
            zr += xr*ch + xi*sh;
            zi += xi*ch - xr*sh;
        }
        g_Zr[(a*23+wp)*EE + c0+tid] = zr;
        g_Zi[(a*23+wp)*EE + c0+tid] = zi;
    }
}
// inverse W-stage: A += y + LN1(A) (normalization recomputed from sums)
__global__ void k_winv2(const float* __restrict__ nw, const float* __restrict__ nb) {
    extern __shared__ float sm[];
    float* zr = sm; float* zi = sm + 23*128;
    int c0 = blockIdx.x*128, a = blockIdx.y, tid = threadIdx.x;
    for (int wp = 0; wp < 23; wp++) {
        zr[wp*128+tid] = g_Zr[(a*23+wp)*EE + c0+tid];
        zi[wp*128+tid] = g_Zi[(a*23+wp)*EE + c0+tid];
    }
    __syncthreads();
    float wv = nw[c0+tid], bv = nb[c0+tid];
    for (int b = 0; b < 90; b++) {
        float y = 0.f;
        #pragma unroll
        for (int wp = 0; wp < 23; wp++) {
            y += zr[wp*128+tid]*g_WCm[b*90+wp] + zi[wp*128+tid]*g_WCp[b*90+wp];
        }
        int tok = a*90 + b;
        size_t idx = (size_t)tok*EE + c0+tid;
        float mu, ri;
        ln_from_sums(tok, mu, ri);
        float av = g_A[idx];
        float tv = (av - mu) * ri * wv + bv;
        g_A[idx] = av + y + tv;
    }
}

// ---------------- misc elementwise ----------------
__global__ void im2col_kernel(const float* __restrict__ x) {
    int idx = blockIdx.x*256 + threadIdx.x;
    if (idx >= NP*PKK) return;
    int p = idx / PKK, k = idx % PKK;
    int c = k >> 8, r = k & 255;
    int ph = r >> 4, pw = r & 15;
    int gh = p / 90, gw = p % 90;
    float v = x[(size_t)c*1036800 + (size_t)(gh*16+ph)*1440 + (gw*16+pw)];
    __nv_bfloat16 h, l; bsplit(v, h, l);
    size_t o = (size_t)p*PKK + k;
    g_pxh[o] = h; g_pxl[o] = l;
}

// ---------------- block-weight prep, ALL layers hoisted ----------------
__global__ void prep_pm_all(const float* __restrict__ w1, const float* __restrict__ w2) {
    int idx = blockIdx.x*256 + threadIdx.x;
    if (idx >= 12*BLK) return;
    int l = idx / BLK, i = idx % BLK;
    const float* w1l = w1 + (size_t)l*2*BLK;
    const float* w2l = w2 + (size_t)l*2*BLK;
    g_W1p[idx] = 0.5f*(w1l[i] + w1l[BLK+i]);
    g_W1m[idx] = 0.5f*(w1l[i] - w1l[BLK+i]);
    g_W2p[idx] = 0.5f*(w2l[i] + w2l[BLK+i]);
    g_W2m[idx] = 0.5f*(w2l[i] - w2l[BLK+i]);
}
__global__ void prep_ab_all() {
    int idx = blockIdx.x*128 + threadIdx.x;
    if (idx >= 12*BLK) return;
    int l = idx / BLK, rr = idx % BLK;
    int o = rr % 96;
    int i = (rr / 96) % 96;
    int b = rr / 9216;
    const float* P = g_W2p + (size_t)l*BLK + b*9216;
    const float* M = g_W2m + (size_t)l*BLK + b*9216;
    float aa = g_W2p[idx];
    float bb = g_W2m[idx] + g_W2p[idx];
    #pragma unroll 8
    for (int j = 0; j < 96; j++) {
        aa += P[i*96+j] * M[j*96+o];
        bb += M[i*96+j] * M[j*96+o];
    }
    g_W2a[idx] = aa;
    g_W2b[idx] = bb;
}
__global__ void prep_bs_all(const float* __restrict__ b2) {
    int idx = blockIdx.x*128 + threadIdx.x;
    if (idx >= 12*NBB*BSS) return;
    int l = idx / (NBB*BSS), rr = idx % (NBB*BSS);
    int o = rr % 96, b = rr / 96;
    const float* b2l = b2 + (size_t)l*2*NBB*BSS;
    float v = b2l[rr] + b2l[NBB*BSS + rr];
    const float* M = g_W2m + (size_t)l*BLK;
    #pragma unroll 8
    for (int j = 0; j < 96; j++) v += b2l[b*96+j] * M[(b*96+j)*96+o];
    g_bs[idx] = v;
}

// ---------------- fused block mixing (LN-gather + mix1 + mix2 + soft-thresh + split) ----------------
#define MROWS 45
#define MIXSM ((9216*2 + MROWS*96*2)*4)
__global__ void k_mixf(const float* __restrict__ b1l,
                       const float* __restrict__ nw, const float* __restrict__ nb,
                       int loff, int lbs) {
    extern __shared__ float sm[];
    float* sW1 = sm;
    float* sW2 = sm + 9216;
    float* sX  = sm + 18432;
    float* sY  = sX + MROWS*96;
    int b = blockIdx.x, tile = blockIdx.y;
    int t = threadIdx.x;
    int o = t % 96, rg = t / 96;
    for (int i = t; i < 9216; i += 288) {
        sW1[i] = g_W1p[loff + b*9216+i];
        sW2[i] = g_W1m[loff + b*9216+i];
    }
    int p0 = tile * MROWS;
    float nwv = nw[b*96+o], nbv = nb[b*96+o];
    for (int pp = rg; pp < MROWS; pp += 3) {
        int p = p0 + pp;
        int h = p / 23, w = p % 23;
        int shh = (45 - h) % 45;
        int sww = (90 - w) % 90;
        int tok = shh*90 + sww;
        float mu, ri;
        ln_from_sums(tok, mu, ri);
        float av = g_A[(size_t)tok*EE + b*96 + o];
        // fwd C-stage split-K partial sum
        sX[pp*96+o] = g_a[(size_t)p*EE + b*96 + o] + g_a[(size_t)NFREQ*EE + (size_t)p*EE + b*96 + o];
        sY[pp*96+o] = (av - mu) * ri * nwv + nbv;
    }
    __syncthreads();
    float bk = b1l[b*96+o], bn = b1l[NBB*BSS + b*96+o];
    float ok_[15], on_[15];
    {
        int c = 0;
        for (int pp = rg; pp < MROWS; pp += 3, c++) {
            float ak = bk, an = bn;
            #pragma unroll 8
            for (int i = 0; i < 96; i++) {
                float xv = sX[pp*96+i], yv = sY[pp*96+i];
                float wp = sW1[i*96+o], wm = sW2[i*96+o];
                ak += xv*wp + yv*wm;
                an += yv*wp + xv*wm;
            }
            ok_[c] = fmaxf(ak, 0.f);
            on_[c] = fmaxf(an, 0.f);
        }
    }
    __syncthreads();
    {
        int c = 0;
        for (int pp = rg; pp < MROWS; pp += 3, c++) {
            sX[pp*96+o] = ok_[c];
            sY[pp*96+o] = on_[c];
        }
    }
    for (int i = t; i < 9216; i += 288) {
        sW1[i] = g_W2a[loff + b*9216+i];
        sW2[i] = g_W2b[loff + b*9216+i];
    }
    __syncthreads();
    float bsv = g_bs[lbs + b*96+o];
    for (int pp = rg; pp < MROWS; pp += 3) {
        float acc = bsv;
        #pragma unroll 8
        for (int i = 0; i < 96; i++) {
            acc += sX[pp*96+i]*sW1[i*96+o] + sY[pp*96+i]*sW2[i*96+o];
        }
        float aab = fabsf(acc) - 0.01f;
        float v = (aab > 0.f) ? copysignf(aab, acc) : 0.f;
        __nv_bfloat16 h, l; bsplit(v, h, l);
        size_t idx = (size_t)(p0+pp)*EE + b*96 + o;
        g_sh[idx] = h; g_sl[idx] = l;
    }
}

// ---------------- host orchestration ----------------
extern "C" void kernel_launch(void* const* d_in, const int* in_sizes, int n_in,
                              void* d_out, int out_size)
{
    const float* x        = (const float*)d_in[0];
    const float* patch_w  = (const float*)d_in[1];
    const float* patch_b  = (const float*)d_in[2];
    const float* pos      = (const float*)d_in[3];
    const float* norm1_w  = (const float*)d_in[4];
    const float* norm1_b  = (const float*)d_in[5];
    const float* w1       = (const float*)d_in[6];
    const float* b1       = (const float*)d_in[7];
    const float* w2       = (const float*)d_in[8];
    const float* b2       = (const float*)d_in[9];
    const float* norm2_w  = (const float*)d_in[10];
    const float* norm2_b  = (const float*)d_in[11];
    const float* fc1_w    = (const float*)d_in[12];
    const float* fc1_b    = (const float*)d_in[13];
    const float* fc2_w    = (const float*)d_in[14];
    const float* fc2_b    = (const float*)d_in[15];
    const float* head_w   = (const float*)d_in[16];
    float* out = (float*)d_out;

    float *pA,*pTT,*pa;
    cudaGetSymbolAddress((void**)&pA,  g_A);
    cudaGetSymbolAddress((void**)&pTT, g_T);
    cudaGetSymbolAddress((void**)&pa,  g_a);

    __nv_bfloat16 *pxh,*pxl,*th,*tl,*hbh,*hbl,*ah2,*al2,*q2h,*q2l,*sh,*sl;
    __nv_bfloat16 *pwh,*pwl,*fBh,*fBl,*iBh,*iBl,*f1h,*f1l,*f2h,*f2l,*hwh,*hwl;
    cudaGetSymbolAddress((void**)&pxh, g_pxh);  cudaGetSymbolAddress((void**)&pxl, g_pxl);
    cudaGetSymbolAddress((void**)&th,  g_th);   cudaGetSymbolAddress((void**)&tl,  g_tl);
    cudaGetSymbolAddress((void**)&hbh, g_hbh);  cudaGetSymbolAddress((void**)&hbl, g_hbl);
    cudaGetSymbolAddress((void**)&ah2, g_Ah2);  cudaGetSymbolAddress((void**)&al2, g_Al2);
    cudaGetSymbolAddress((void**)&q2h, g_q2h);  cudaGetSymbolAddress((void**)&q2l, g_q2l);
    cudaGetSymbolAddress((void**)&sh,  g_sh);   cudaGetSymbolAddress((void**)&sl,  g_sl);
    cudaGetSymbolAddress((void**)&pwh, g_pwh);  cudaGetSymbolAddress((void**)&pwl, g_pwl);
    cudaGetSymbolAddress((void**)&fBh, g_fBh);  cudaGetSymbolAddress((void**)&fBl, g_fBl);
    cudaGetSymbolAddress((void**)&iBh, g_iBh);  cudaGetSymbolAddress((void**)&iBl, g_iBl);
    cudaGetSymbolAddress((void**)&f1h, g_f1h);  cudaGetSymbolAddress((void**)&f1l, g_f1l);
    cudaGetSymbolAddress((void**)&f2h, g_f2h);  cudaGetSymbolAddress((void**)&f2l, g_f2l);
    cudaGetSymbolAddress((void**)&hwh, g_hwh);  cudaGetSymbolAddress((void**)&hwl, g_hwl);

    cudaFuncSetAttribute(k_wfwd,  cudaFuncAttributeMaxDynamicSharedMemorySize, 90*128*4 + 180*4);
    cudaFuncSetAttribute(k_hfwd,  cudaFuncAttributeMaxDynamicSharedMemorySize, 2*45*128*4);
    cudaFuncSetAttribute(k_hinv2, cudaFuncAttributeMaxDynamicSharedMemorySize, 2*45*128*4);
    cudaFuncSetAttribute(k_winv2, cudaFuncAttributeMaxDynamicSharedMemorySize, 2*23*128*4);
    cudaFuncSetAttribute(k_mixf,  cudaFuncAttributeMaxDynamicSharedMemorySize, MIXSM);
    cudaFuncSetAttribute(hgemm<0>, cudaFuncAttributeMaxDynamicSharedMemorySize, 2*BUF_B);
    cudaFuncSetAttribute(hgemm<2>, cudaFuncAttributeMaxDynamicSharedMemorySize, 2*BUF_B);
    cudaFuncSetAttribute(hgemm<3>, cudaFuncAttributeMaxDynamicSharedMemorySize, 2*BUF_B);
    cudaFuncSetAttribute(hgemm<4>, cudaFuncAttributeMaxDynamicSharedMemorySize, 2*BUF_B);
    cudaFuncSetAttribute(hgemm<5>, cudaFuncAttributeMaxDynamicSharedMemorySize, 2*BUF_B);
    cudaFuncSetAttribute(hgemm<6>, cudaFuncAttributeMaxDynamicSharedMemorySize, 2*BUF_B);

    // tables + weight splits + ALL-layer block-weight prep (once)
    tabC <<<(EE*EE + 255)/256, 256>>>();
    tab90<<<(GWw*GWw + 255)/256, 256>>>();
    tab45<<<(GHh*GHh + 255)/256, 256>>>();
    split_kernel<<<(EE*PKK + 255)/256, 256>>>(patch_w, pwh, pwl, EE*PKK);
    split_kernel<<<(HDD*EE + 255)/256, 256>>>(head_w, hwh, hwl, HDD*EE);
    split_kernel<<<(12*HID*EE + 255)/256, 256>>>(fc1_w, f1h, f1l, 12*HID*EE);
    split_kernel<<<(12*EE*HID + 255)/256, 256>>>(fc2_w, f2h, f2l, 12*EE*HID);
    prep_pm_all<<<(12*BLK + 255)/256, 256>>>(w1, w2);
    prep_ab_all<<<(12*BLK + 127)/128, 128>>>();
    prep_bs_all<<<(12*NBB*BSS + 127)/128, 128>>>(b2);

    const dim3 GB(256);
    const int SMB = 2*BUF_B;

    // patch embed (bias + pos fused; emits LN1 stats for layer 0)
    im2col_kernel<<<(NP*PKK + 255)/256, 256>>>(x);
    hgemm<4><<<dim3(EE/64, MPAD/128), GB, SMB>>>(pxh, pxl, pwh, pwl, pA, nullptr, nullptr,
                                                 NP, EE, PKK, patch_b, pos, PKK, 0);

    for (int l = 0; l < 12; l++) {
        // ---- AFNO half ----
        k_wfwd<<<dim3(6, 45), 128, 90*128*4 + 180*4>>>(norm1_w + l*EE, norm1_b + l*EE);
        k_hfwd<<<dim3(6, 23), 128, 2*45*128*4>>>();
        // fwd C-stage GEMM: split-K2 (z=0: Q2r x (cos-sin); z=1: Q2i x (cos+sin))
        hgemm<0><<<dim3(EE/64, FPAD/128, 2), GB, SMB>>>(q2h, q2l, fBh, fBl, pa, nullptr, nullptr,
                                                        NFREQ, EE, EE, nullptr, nullptr,
                                                        2*EE, (long)NFREQ*EE);
        k_mixf<<<dim3(8, 23), 288, MIXSM>>>(b1 + (size_t)l*2*NBB*BSS,
                                            norm1_w + l*EE, norm1_b + l*EE, l*BLK, l*NBB*BSS);
        // inv C-stage GEMM: split-K2 over the 768 c-dimension
        hgemm<0><<<dim3((2*EE)/64, FPAD/128, 2), GB, SMB>>>(sh, sl, iBh, iBl, pTT, nullptr, nullptr,
                                                            NFREQ, 2*EE, EE/2, nullptr, nullptr,
                                                            EE, (long)NP*EE);
        k_hinv2<<<dim3(6, 23), 128, 2*45*128*4>>>();
        k_winv2<<<dim3(6, 45), 128, 2*23*128*4>>>(norm1_w + l*EE, norm1_b + l*EE);

        // ---- MLP half ----
        ln_bf16<<<NP, 256>>>(pA, th, tl, norm2_w + l*EE, norm2_b + l*EE);
        hgemm<2><<<dim3(HID/64, MPAD/128), GB, SMB>>>(th, tl, f1h + (size_t)l*HID*EE, f1l + (size_t)l*HID*EE,
                                                      nullptr, hbh, hbl, NP, HID, EE, fc1_b + l*HID, nullptr,
                                                      EE, 0);
        if (l < 11) {
            hgemm<3><<<dim3(EE/64, MPAD/128), GB, SMB>>>(hbh, hbl, f2h + (size_t)l*EE*HID, f2l + (size_t)l*EE*HID,
                                                         pA, nullptr, nullptr, NP, EE, HID, fc2_b + l*EE, nullptr,
                                                         HID, 0);
        } else {
            hgemm<5><<<dim3(EE/64, MPAD/128), GB, SMB>>>(hbh, hbl, f2h + (size_t)l*EE*HID, f2l + (size_t)l*EE*HID,
                                                         pA, ah2, al2, NP, EE, HID, fc2_b + l*EE, nullptr,
                                                         HID, 0);
        }
    }

    // head: GEMM scatters directly into the output image
    hgemm<6><<<dim3(HDD/64, MPAD/128), GB, SMB>>>(ah2, al2, hwh, hwl, out, nullptr, nullptr,
                                                  NP, HDD, EE, nullptr, nullptr, EE, 0);
}

// round 13
// speedup vs baseline: 2.6785x; 1.1266x over previous
#include <cuda_runtime.h>
#include <cuda_fp16.h>
#include <math.h>
#include <stdint.h>

// ---------------- constants ----------------
#define GHh 45
#define GWw 90
#define NP 4050          // tokens
#define MPAD 4096        // padded token rows
#define EE 768
#define KM 23
#define NFREQ (GHh*KM)   // 1035
#define FPAD 1152        // padded freq rows (9*128)
#define HID 3072
#define PKK 5120
#define HDD 5120
#define NBB 8
#define BSS 96
#define BLK (NBB*BSS*BSS)   // 73728 per layer
#define DHT_SIZE 3110400.0

// ---------------- fp32 scratch ----------------
__device__ __align__(128) float g_A [NP*EE];
__device__ __align__(128) float g_T [2*(size_t)NP*EE];     // inverse C-stage out, 2 split-K partials
__device__ __align__(128) float g_Qr[NFREQ*EE];
__device__ __align__(128) float g_Qi[NFREQ*EE];
__device__ __align__(128) float g_Zr[NFREQ*EE];
__device__ __align__(128) float g_Zi[NFREQ*EE];
__device__ __align__(128) float g_a [2*(size_t)NFREQ*EE];  // fwd C-stage out, 2 split-K partials
__device__ __align__(128) float g_ssum[NP];
__device__ __align__(128) float g_ssq [NP];
// small DFT tables
__device__ __align__(128) float g_WC[GWw*GWw];
__device__ __align__(128) float g_WS[GWw*GWw];
__device__ __align__(128) float g_WCm[GWw*GWw];   // (cos-sin)/SIZE
__device__ __align__(128) float g_WCp[GWw*GWw];   // (cos+sin)/SIZE
__device__ __align__(128) float g_HC[GHh*GHh];
__device__ __align__(128) float g_HS[GHh*GHh];
// per-layer prepped block weights (ALL 12 layers, hoisted)
__device__ __align__(128) float g_W1p[12*BLK], g_W1m[12*BLK];
__device__ __align__(128) float g_W2p[12*BLK], g_W2m[12*BLK];
__device__ __align__(128) float g_W2a[12*BLK], g_W2b[12*BLK];
__device__ __align__(128) float g_bs [12*NBB*BSS];

// ---------------- fp16 buffers: activations as hi/lo pairs, weights single ----------------
__device__ __align__(128) __half g_pxh[(size_t)MPAD*PKK], g_pxl[(size_t)MPAD*PKK];
__device__ __align__(128) __half g_th [(size_t)MPAD*EE],  g_tl [(size_t)MPAD*EE];
__device__ __align__(128) __half g_hbh[(size_t)MPAD*HID], g_hbl[(size_t)MPAD*HID];
__device__ __align__(128) __half g_Ah2[(size_t)MPAD*EE],  g_Al2[(size_t)MPAD*EE];
__device__ __align__(128) __half g_q2h[(size_t)FPAD*2*EE], g_q2l[(size_t)FPAD*2*EE];
__device__ __align__(128) __half g_sh [(size_t)FPAD*EE],  g_sl [(size_t)FPAD*EE];
// weights / tables (single fp16)
__device__ __align__(128) __half g_pw [EE*PKK];
__device__ __align__(128) __half g_fB [EE*2*EE];   // fwd C B
__device__ __align__(128) __half g_iB [2*EE*EE];   // inv C B
__device__ __align__(128) __half g_f1 [(size_t)12*HID*EE];
__device__ __align__(128) __half g_f2 [(size_t)12*EE*HID];
__device__ __align__(128) __half g_hw [HDD*EE];

// ---------------- helpers ----------------
__device__ __forceinline__ void hsplit(float x, __half& h, __half& l) {
    h = __float2half(x);
    l = __float2half(x - __half2float(h));
}
__device__ __forceinline__ uint32_t s2u32(const void* p) {
    uint32_t a;
    asm("{ .reg .u64 t; cvta.to.shared.u64 t, %1; cvt.u32.u64 %0, t; }" : "=r"(a) : "l"(p));
    return a;
}
__device__ __forceinline__ void mma_f16(float* c, const uint32_t* a, const uint32_t* b) {
    asm volatile("mma.sync.aligned.m16n8k16.row.col.f32.f16.f16.f32 "
        "{%0,%1,%2,%3}, {%4,%5,%6,%7}, {%8,%9}, {%0,%1,%2,%3};"
        : "+f"(c[0]), "+f"(c[1]), "+f"(c[2]), "+f"(c[3])
        : "r"(a[0]), "r"(a[1]), "r"(a[2]), "r"(a[3]), "r"(b[0]), "r"(b[1]));
}
__device__ __forceinline__ void cpa16(uint32_t dst, const void* src) {
    asm volatile("cp.async.cg.shared.global [%0], [%1], 16;" :: "r"(dst), "l"(src));
}
__device__ __forceinline__ void ldsm4(uint32_t* r, uint32_t addr) {
    asm volatile("ldmatrix.sync.aligned.m8n8.x4.shared.b16 {%0,%1,%2,%3}, [%4];"
        : "=r"(r[0]), "=r"(r[1]), "=r"(r[2]), "=r"(r[3]) : "r"(addr));
}
__device__ __forceinline__ void ln_from_sums(int tok, float& mu, float& ri) {
    float s = g_ssum[tok], q = g_ssq[tok];
    mu = s * (1.0f/768.0f);
    float v = q * (1.0f/768.0f) - mu*mu;
    ri = rsqrtf(v + 1e-5f);
}

// ---------------- table init ----------------
__global__ void tabC() {
    int idx = blockIdx.x*256 + threadIdx.x;
    if (idx >= EE*EE) return;
    int kc = idx / EE, c = idx % EE;
    long long m = ((long long)kc * c) % EE;
    double a = 2.0 * (double)m / (double)EE;
    double cs = cospi(a), sn = sinpi(a);
    g_fB[kc*2*EE + c]      = __float2half((float)(cs - sn));
    g_fB[kc*2*EE + EE + c] = __float2half((float)(cs + sn));
    g_iB[kc*EE + c]        = __float2half((float)cs);
    g_iB[(EE+kc)*EE + c]   = __float2half((float)(-sn));
}
__global__ void tab90() {
    int idx = blockIdx.x*256 + threadIdx.x;
    if (idx >= GWw*GWw) return;
    int a = idx / GWw, b = idx % GWw;
    long long m = ((long long)a * b) % GWw;
    double ang = 2.0 * (double)m / (double)GWw;
    double cs = cospi(ang), sn = sinpi(ang);
    g_WC[idx]  = (float)cs;
    g_WS[idx]  = (float)sn;
    g_WCm[idx] = (float)((cs - sn) / DHT_SIZE);
    g_WCp[idx] = (float)((cs + sn) / DHT_SIZE);
}
__global__ void tab45() {
    int idx = blockIdx.x*256 + threadIdx.x;
    if (idx >= GHh*GHh) return;
    int a = idx / GHh, b = idx % GHh;
    long long m = ((long long)a * b) % GHh;
    double ang = 2.0 * (double)m / (double)GHh;
    g_HC[idx] = (float)cospi(ang);
    g_HS[idx] = (float)sinpi(ang);
}

__global__ void conv_kernel(const float* __restrict__ in, __half* __restrict__ o, int n) {
    int i = blockIdx.x*256 + threadIdx.x;
    if (i >= n) return;
    o[i] = __float2half(in[i]);
}

// ---------------- fp16x2 mma.sync GEMM, tile 128Mx64N, k-chunk 32, optional split-K ----
// A = (Ah + Al) fp16 pair, B single fp16. D = Ah*B + Al*B.
// MODE: 0=store fp32 (+split-K via blockIdx.z), 2=bias+GELU->fp16 pair,
//       3=accumulate(+bias) fp32 + LN stats, 4=store+bias+addmat + LN stats,
//       5=accumulate(+bias) fp32 AND emit fp16 pair, 6=head scatter to output image
#define SMSTR 40
#define A_TB (128*SMSTR*2)
#define B_TB (64*SMSTR*2)
#define BUF_B (2*A_TB + B_TB)

template<int MODE>
__global__ void __launch_bounds__(256, 3)
hgemm(const __half* __restrict__ Ah, const __half* __restrict__ Al,
      const __half* __restrict__ B,
      float* __restrict__ C,
      __half* __restrict__ Csh, __half* __restrict__ Csl,
      int Mtrue, int N, int K, const float* __restrict__ bias,
      const float* __restrict__ addm, int ld, long zoff)
{
    extern __shared__ __align__(128) char smem[];
    const int t = threadIdx.x, warp = t >> 5, lane = t & 31;
    const int wm = warp >> 1, wn = warp & 1;
    const int bm = blockIdx.y * 128, bn = blockIdx.x * 64;
    const int kz = blockIdx.z;
    const size_t kbase = (size_t)kz * K;
    if (MODE == 0) C += (size_t)kz * zoff;
    const uint32_t sb = s2u32(smem);

    float acc[2][4][4];
    #pragma unroll
    for (int i = 0; i < 2; i++)
        #pragma unroll
        for (int j = 0; j < 4; j++)
            #pragma unroll
            for (int q = 0; q < 4; q++) acc[i][j][q] = 0.f;

    const int arow = t & 127, ahalf = t >> 7;
    const __half* pAh = Ah + (size_t)(bm + arow) * ld + kbase + ahalf * 16;
    const __half* pAl = Al + (size_t)(bm + arow) * ld + kbase + ahalf * 16;
    const uint32_t aoff = (uint32_t)(arow * SMSTR + ahalf * 16) * 2;
    const int brow = t >> 2, bseg = t & 3;
    const __half* pB = B + (size_t)(bn + brow) * ld + kbase + bseg * 8;
    const uint32_t boff = (uint32_t)(brow * SMSTR + bseg * 8) * 2;

    // precomputed LDSM base addresses (buffer 0); in-loop: + parity*BUF_B
    uint32_t adA[2][2], adB[2][2];
    {
        const int g = lane >> 3, r = lane & 7;
        #pragma unroll
        for (int step = 0; step < 2; step++) {
            const int ks = step * 16;
            const uint32_t a_off = (uint32_t)(((g & 1) * 8 + r) * SMSTR + ks + (g >> 1) * 8) * 2;
            const uint32_t b_off = (uint32_t)(((g >> 1) * 8 + r) * SMSTR + ks + (g & 1) * 8) * 2;
            #pragma unroll
            for (int mt = 0; mt < 2; mt++)
                adA[step][mt] = sb + (uint32_t)((wm*32 + mt*16) * SMSTR) * 2 + a_off;
            #pragma unroll
            for (int j2 = 0; j2 < 2; j2++)
                adB[step][j2] = sb + 2*A_TB + (uint32_t)((wn*32 + j2*16) * SMSTR) * 2 + b_off;
        }
    }

    const int nch = K >> 5;
    auto issue = [&](int ch) {
        const int k0 = ch << 5;
        const uint32_t dst = sb + (uint32_t)(ch & 1) * BUF_B;
        cpa16(dst + aoff,        pAh + k0); cpa16(dst + aoff + 16,        pAh + k0 + 8);
        cpa16(dst + A_TB + aoff, pAl + k0); cpa16(dst + A_TB + aoff + 16, pAl + k0 + 8);
        cpa16(dst + 2*A_TB + boff, pB + k0);
        asm volatile("cp.async.commit_group;" ::: "memory");
    };

    issue(0);
    for (int ch = 0; ch < nch; ch++) {
        const bool more = (ch + 1) < nch;
        if (more) { issue(ch + 1); asm volatile("cp.async.wait_group 1;" ::: "memory"); }
        else      { asm volatile("cp.async.wait_group 0;" ::: "memory"); }
        __syncthreads();

        const uint32_t bsel = (uint32_t)(ch & 1) * BUF_B;

        #pragma unroll
        for (int step = 0; step < 2; step++) {
            uint32_t ah_[2][4], al_[2][4], bh_[4][2];
            #pragma unroll
            for (int mt = 0; mt < 2; mt++) {
                const uint32_t ad = adA[step][mt] + bsel;
                ldsm4(ah_[mt], ad);
                ldsm4(al_[mt], ad + A_TB);
            }
            #pragma unroll
            for (int j2 = 0; j2 < 2; j2++) {
                const uint32_t bd = adB[step][j2] + bsel;
                uint32_t tmp[4];
                ldsm4(tmp, bd);
                bh_[j2*2][0]=tmp[0]; bh_[j2*2][1]=tmp[1]; bh_[j2*2+1][0]=tmp[2]; bh_[j2*2+1][1]=tmp[3];
            }
            #pragma unroll
            for (int mt = 0; mt < 2; mt++)
                #pragma unroll
                for (int nt = 0; nt < 4; nt++) mma_f16(acc[mt][nt], ah_[mt], bh_[nt]);
            #pragma unroll
            for (int mt = 0; mt < 2; mt++)
                #pragma unroll
                for (int nt = 0; nt < 4; nt++) mma_f16(acc[mt][nt], al_[mt], bh_[nt]);
        }
        __syncthreads();
    }

    // epilogue
    float st_s[2][2], st_q[2][2];
    if (MODE == 3 || MODE == 4) {
        #pragma unroll
        for (int i = 0; i < 2; i++)
            #pragma unroll
            for (int j = 0; j < 2; j++) { st_s[i][j] = 0.f; st_q[i][j] = 0.f; }
    }
    #pragma unroll
    for (int mt = 0; mt < 2; mt++) {
        const int r0 = bm + wm*32 + mt*16 + (lane >> 2);
        #pragma unroll
        for (int nt = 0; nt < 4; nt++) {
            const int c0 = bn + wn*32 + nt*8 + (lane & 3)*2;
            float b0 = 0.f, b1 = 0.f;
            if (MODE == 2 || MODE == 3 || MODE == 4 || MODE == 5) { b0 = bias[c0]; b1 = bias[c0+1]; }
            #pragma unroll
            for (int h = 0; h < 2; h++) {
                const int row = r0 + h*8;
                if (row >= Mtrue) continue;
                float v0 = acc[mt][nt][h*2+0] + b0;
                float v1 = acc[mt][nt][h*2+1] + b1;
                if (MODE == 2) {
                    v0 = 0.5f*v0*(1.0f + erff(v0*0.7071067811865475f));
                    v1 = 0.5f*v1*(1.0f + erff(v1*0.7071067811865475f));
                    __half h0, l0, h1, l1;
                    hsplit(v0, h0, l0); hsplit(v1, h1, l1);
                    __half2 hv; hv.x = h0; hv.y = h1;
                    __half2 lv; lv.x = l0; lv.y = l1;
                    *(__half2*)&Csh[(size_t)row*N + c0] = hv;
                    *(__half2*)&Csl[(size_t)row*N + c0] = lv;
                } else if (MODE == 3) {
                    float2* cp = (float2*)&C[(size_t)row*N + c0];
                    float2 old = *cp;
                    old.x += v0; old.y += v1;
                    *cp = old;
                    st_s[mt][h] += old.x + old.y;
                    st_q[mt][h] += old.x*old.x + old.y*old.y;
                } else if (MODE == 5) {
                    float2* cp = (float2*)&C[(size_t)row*N + c0];
                    float2 old = *cp;
                    old.x += v0; old.y += v1;
                    *cp = old;
                    __half h0, l0, h1, l1;
                    hsplit(old.x, h0, l0); hsplit(old.y, h1, l1);
                    __half2 hv; hv.x = h0; hv.y = h1;
                    __half2 lv; lv.x = l0; lv.y = l1;
                    *(__half2*)&Csh[(size_t)row*N + c0] = hv;
                    *(__half2*)&Csl[(size_t)row*N + c0] = lv;
                } else if (MODE == 4) {
                    const float2 am = *(const float2*)&addm[(size_t)row*N + c0];
                    float2 fv; fv.x = v0 + am.x; fv.y = v1 + am.y;
                    *(float2*)&C[(size_t)row*N + c0] = fv;
                    st_s[mt][h] += fv.x + fv.y;
                    st_q[mt][h] += fv.x*fv.x + fv.y*fv.y;
                } else if (MODE == 6) {
                    const int gh = row / 90, gw = row % 90;
                    #pragma unroll
                    for (int e = 0; e < 2; e++) {
                        const int n = c0 + e;
                        const int ph = n / 320;
                        const int rem = n - ph*320;
                        const int pw = rem / 20;
                        const int oc = rem - pw*20;
                        C[(size_t)oc*1036800 + (size_t)(gh*16 + ph)*1440 + (gw*16 + pw)]
                            = (e == 0 ? v0 : v1);
                    }
                } else {
                    float2 fv; fv.x = v0; fv.y = v1;
                    *(float2*)&C[(size_t)row*N + c0] = fv;
                }
            }
        }
    }
    if (MODE == 3 || MODE == 4) {
        #pragma unroll
        for (int mt = 0; mt < 2; mt++) {
            #pragma unroll
            for (int h = 0; h < 2; h++) {
                float s = st_s[mt][h], q = st_q[mt][h];
                s += __shfl_xor_sync(0xffffffffu, s, 1);
                q += __shfl_xor_sync(0xffffffffu, q, 1);
                s += __shfl_xor_sync(0xffffffffu, s, 2);
                q += __shfl_xor_sync(0xffffffffu, q, 2);
                const int row = bm + wm*32 + mt*16 + (lane >> 2) + h*8;
                if ((lane & 3) == 0 && row < Mtrue) {
                    atomicAdd(&g_ssum[row], s);
                    atomicAdd(&g_ssq[row],  q);
                }
            }
        }
    }
}

// ---------------- LN2 with fp16-pair output (MLP half); also zeroes LN1 accumulators --------
__global__ void ln_h(const float* __restrict__ in,
                     __half* __restrict__ oh, __half* __restrict__ ol,
                     const float* __restrict__ w, const float* __restrict__ b)
{
    int tok = blockIdx.x;
    int tid = threadIdx.x;
    const float* row = in + (size_t)tok*EE;
    float x0 = row[tid], x1 = row[tid+256], x2 = row[tid+512];
    float s  = x0+x1+x2;
    float sq = x0*x0 + x1*x1 + x2*x2;
    #pragma unroll
    for (int o = 16; o > 0; o >>= 1) {
        s  += __shfl_down_sync(0xffffffffu, s,  o);
        sq += __shfl_down_sync(0xffffffffu, sq, o);
    }
    __shared__ float ss[8], ssq[8];
    int warp = tid >> 5, lane = tid & 31;
    if (lane == 0) { ss[warp] = s; ssq[warp] = sq; }
    __syncthreads();
    if (tid == 0) {
        float ts = 0.f, tq = 0.f;
        #pragma unroll
        for (int i = 0; i < 8; i++) { ts += ss[i]; tq += ssq[i]; }
        float m = ts * (1.0f/768.0f);
        float v = tq * (1.0f/768.0f) - m*m;
        ss[0] = m; ssq[0] = rsqrtf(v + 1e-5f);
        g_ssum[tok] = 0.f;
        g_ssq[tok]  = 0.f;
    }
    __syncthreads();
    float m = ss[0], inv = ssq[0];
    size_t base = (size_t)tok*EE;
    #pragma unroll
    for (int j = 0; j < 3; j++) {
        int o = tid + j*256;
        float y = (j==0?x0:(j==1?x1:x2));
        y = (y - m)*inv*w[o] + b[o];
        __half h, l; hsplit(y, h, l);
        oh[base + o] = h; ol[base + o] = l;
    }
}

// ---------------- DHT stage kernels (LN fused via sums) ----------------
__global__ void k_wfwd(const float* __restrict__ nw, const float* __restrict__ nb) {
    extern __shared__ float sm[];          // 90*128 + 180
    float* stat = sm + 90*128;
    int c0 = blockIdx.x*128, h = blockIdx.y, tid = threadIdx.x;
    if (tid < 90) {
        float mu, ri;
        ln_from_sums(h*90+tid, mu, ri);
        stat[tid]    = mu;
        stat[90+tid] = ri;
    }
    __syncthreads();
    float wv = nw[c0+tid], bv = nb[c0+tid];
    for (int w = 0; w < 90; w++) {
        float av = g_A[(h*90+w)*EE + c0+tid];
        sm[w*128+tid] = (av - stat[w]) * stat[90+w] * wv + bv;
    }
    __syncthreads();
    for (int kw = 0; kw < 23; kw++) {
        float ar = 0.f, ai = 0.f;
        #pragma unroll 6
        for (int w = 0; w < 90; w++) {
            float v = sm[w*128+tid];
            ar += v * g_WC[kw*90+w];
            ai -= v * g_WS[kw*90+w];
        }
        g_Qr[(h*23+kw)*EE + c0+tid] = ar;
        g_Qi[(h*23+kw)*EE + c0+tid] = ai;
    }
}
__global__ void k_hfwd() {
    extern __shared__ float sm[];
    float* sr = sm; float* si = sm + 45*128;
    int c0 = blockIdx.x*128, kw = blockIdx.y, tid = threadIdx.x;
    for (int h = 0; h < 45; h++) {
        sr[h*128+tid] = g_Qr[(h*23+kw)*EE + c0+tid];
        si[h*128+tid] = g_Qi[(h*23+kw)*EE + c0+tid];
    }
    __syncthreads();
    for (int kh = 0; kh < 45; kh++) {
        float qr = 0.f, qi = 0.f;
        #pragma unroll 5
        for (int h = 0; h < 45; h++) {
            float ch = g_HC[kh*45+h], sh = g_HS[kh*45+h];
            float ur = sr[h*128+tid], ui = si[h*128+tid];
            qr += ur*ch + ui*sh;
            qi += ui*ch - ur*sh;
        }
        size_t row = (size_t)(kh*23+kw) * (2*EE);
        __half h2, l2;
        hsplit(qr, h2, l2); g_q2h[row + c0+tid] = h2;      g_q2l[row + c0+tid] = l2;
        hsplit(qi, h2, l2); g_q2h[row + EE + c0+tid] = h2; g_q2l[row + EE + c0+tid] = l2;
    }
}
__global__ void k_hinv2() {
    extern __shared__ float sm[];
    float* tr = sm; float* ti = sm + 45*128;
    int c0 = blockIdx.x*128, wp = blockIdx.y, tid = threadIdx.x;
    for (int hp = 0; hp < 45; hp++) {
        size_t row = (size_t)(hp*23+wp) * (2*EE);
        tr[hp*128+tid] = g_T[row + c0+tid]      + g_T[(size_t)NP*EE + row + c0+tid];
        ti[hp*128+tid] = g_T[row + EE + c0+tid] + g_T[(size_t)NP*EE + row + EE + c0+tid];
    }
    __syncthreads();
    for (int a = 0; a < 45; a++) {
        float zr = 0.f, zi = 0.f;
        #pragma unroll 5
        for (int hp = 0; hp < 45; hp++) {
            float ch = g_HC[a*45+hp], sh = g_HS[a*45+hp];
            float xr = tr[hp*128+tid], xi = ti[hp*128+tid];
            zr += xr*ch + xi*sh;
            zi += xi*ch - xr*sh;
        }
        g_Zr[(a*23+wp)*EE + c0+tid] = zr;
        g_Zi[(a*23+wp)*EE + c0+tid] = zi;
    }
}
// inverse W-stage: A += y + LN1(A) (normalization recomputed from sums)
__global__ void k_winv2(const float* __restrict__ nw, const float* __restrict__ nb) {
    extern __shared__ float sm[];
    float* zr = sm; float* zi = sm + 23*128;
    int c0 = blockIdx.x*128, a = blockIdx.y, tid = threadIdx.x;
    for (int wp = 0; wp < 23; wp++) {
        zr[wp*128+tid] = g_Zr[(a*23+wp)*EE + c0+tid];
        zi[wp*128+tid] = g_Zi[(a*23+wp)*EE + c0+tid];
    }
    __syncthreads();
    float wv = nw[c0+tid], bv = nb[c0+tid];
    for (int b = 0; b < 90; b++) {
        float y = 0.f;
        #pragma unroll
        for (int wp = 0; wp < 23; wp++) {
            y += zr[wp*128+tid]*g_WCm[b*90+wp] + zi[wp*128+tid]*g_WCp[b*90+wp];
        }
        int tok = a*90 + b;
        size_t idx = (size_t)tok*EE + c0+tid;
        float mu, ri;
        ln_from_sums(tok, mu, ri);
        float av = g_A[idx];
        float tv = (av - mu) * ri * wv + bv;
        g_A[idx] = av + y + tv;
    }
}

// ---------------- misc elementwise ----------------
__global__ void im2col_kernel(const float* __restrict__ x) {
    int idx = blockIdx.x*256 + threadIdx.x;
    if (idx >= NP*PKK) return;
    int p = idx / PKK, k = idx % PKK;
    int c = k >> 8, r = k & 255;
    int ph = r >> 4, pw = r & 15;
    int gh = p / 90, gw = p % 90;
    float v = x[(size_t)c*1036800 + (size_t)(gh*16+ph)*1440 + (gw*16+pw)];
    __half h, l; hsplit(v, h, l);
    size_t o = (size_t)p*PKK + k;
    g_pxh[o] = h; g_pxl[o] = l;
}

// ---------------- block-weight prep, ALL layers hoisted ----------------
__global__ void prep_pm_all(const float* __restrict__ w1, const float* __restrict__ w2) {
    int idx = blockIdx.x*256 + threadIdx.x;
    if (idx >= 12*BLK) return;
    int l = idx / BLK, i = idx % BLK;
    const float* w1l = w1 + (size_t)l*2*BLK;
    const float* w2l = w2 + (size_t)l*2*BLK;
    g_W1p[idx] = 0.5f*(w1l[i] + w1l[BLK+i]);
    g_W1m[idx] = 0.5f*(w1l[i] - w1l[BLK+i]);
    g_W2p[idx] = 0.5f*(w2l[i] + w2l[BLK+i]);
    g_W2m[idx] = 0.5f*(w2l[i] - w2l[BLK+i]);
}
__global__ void prep_ab_all() {
    int idx = blockIdx.x*128 + threadIdx.x;
    if (idx >= 12*BLK) return;
    int l = idx / BLK, rr = idx % BLK;
    int o = rr % 96;
    int i = (rr / 96) % 96;
    int b = rr / 9216;
    const float* P = g_W2p + (size_t)l*BLK + b*9216;
    const float* M = g_W2m + (size_t)l*BLK + b*9216;
    float aa = g_W2p[idx];
    float bb = g_W2m[idx] + g_W2p[idx];
    #pragma unroll 8
    for (int j = 0; j < 96; j++) {
        aa += P[i*96+j] * M[j*96+o];
        bb += M[i*96+j] * M[j*96+o];
    }
    g_W2a[idx] = aa;
    g_W2b[idx] = bb;
}
__global__ void prep_bs_all(const float* __restrict__ b2) {
    int idx = blockIdx.x*128 + threadIdx.x;
    if (idx >= 12*NBB*BSS) return;
    int l = idx / (NBB*BSS), rr = idx % (NBB*BSS);
    int o = rr % 96, b = rr / 96;
    const float* b2l = b2 + (size_t)l*2*NBB*BSS;
    float v = b2l[rr] + b2l[NBB*BSS + rr];
    const float* M = g_W2m + (size_t)l*BLK;
    #pragma unroll 8
    for (int j = 0; j < 96; j++) v += b2l[b*96+j] * M[(b*96+j)*96+o];
    g_bs[idx] = v;
}

// ---------------- fused block mixing (LN-gather + mix1 + mix2 + soft-thresh + split) ----------------
#define MROWS 45
#define MIXSM ((9216*2 + MROWS*96*2)*4)
__global__ void k_mixf(const float* __restrict__ b1l,
                       const float* __restrict__ nw, const float* __restrict__ nb,
                       int loff, int lbs) {
    extern __shared__ float sm[];
    float* sW1 = sm;
    float* sW2 = sm + 9216;
    float* sX  = sm + 18432;
    float* sY  = sX + MROWS*96;
    int b = blockIdx.x, tile = blockIdx.y;
    int t = threadIdx.x;
    int o = t % 96, rg = t / 96;
    for (int i = t; i < 9216; i += 288) {
        sW1[i] = g_W1p[loff + b*9216+i];
        sW2[i] = g_W1m[loff + b*9216+i];
    }
    int p0 = tile * MROWS;
    float nwv = nw[b*96+o], nbv = nb[b*96+o];
    for (int pp = rg; pp < MROWS; pp += 3) {
        int p = p0 + pp;
        int h = p / 23, w = p % 23;
        int shh = (45 - h) % 45;
        int sww = (90 - w) % 90;
        int tok = shh*90 + sww;
        float mu, ri;
        ln_from_sums(tok, mu, ri);
        float av = g_A[(size_t)tok*EE + b*96 + o];
        sX[pp*96+o] = g_a[(size_t)p*EE + b*96 + o] + g_a[(size_t)NFREQ*EE + (size_t)p*EE + b*96 + o];
        sY[pp*96+o] = (av - mu) * ri * nwv + nbv;
    }
    __syncthreads();
    float bk = b1l[b*96+o], bn = b1l[NBB*BSS + b*96+o];
    float ok_[15], on_[15];
    {
        int c = 0;
        for (int pp = rg; pp < MROWS; pp += 3, c++) {
            float ak = bk, an = bn;
            #pragma unroll 8
            for (int i = 0; i < 96; i++) {
                float xv = sX[pp*96+i], yv = sY[pp*96+i];
                float wp = sW1[i*96+o], wm = sW2[i*96+o];
                ak += xv*wp + yv*wm;
                an += yv*wp + xv*wm;
            }
            ok_[c] = fmaxf(ak, 0.f);
            on_[c] = fmaxf(an, 0.f);
        }
    }
    __syncthreads();
    {
        int c = 0;
        for (int pp = rg; pp < MROWS; pp += 3, c++) {
            sX[pp*96+o] = ok_[c];
            sY[pp*96+o] = on_[c];
        }
    }
    for (int i = t; i < 9216; i += 288) {
        sW1[i] = g_W2a[loff + b*9216+i];
        sW2[i] = g_W2b[loff + b*9216+i];
    }
    __syncthreads();
    float bsv = g_bs[lbs + b*96+o];
    for (int pp = rg; pp < MROWS; pp += 3) {
        float acc = bsv;
        #pragma unroll 8
        for (int i = 0; i < 96; i++) {
            acc += sX[pp*96+i]*sW1[i*96+o] + sY[pp*96+i]*sW2[i*96+o];
        }
        float aab = fabsf(acc) - 0.01f;
        float v = (aab > 0.f) ? copysignf(aab, acc) : 0.f;
        __half h, l; hsplit(v, h, l);
        size_t idx = (size_t)(p0+pp)*EE + b*96 + o;
        g_sh[idx] = h; g_sl[idx] = l;
    }
}

// ---------------- host orchestration ----------------
extern "C" void kernel_launch(void* const* d_in, const int* in_sizes, int n_in,
                              void* d_out, int out_size)
{
    const float* x        = (const float*)d_in[0];
    const float* patch_w  = (const float*)d_in[1];
    const float* patch_b  = (const float*)d_in[2];
    const float* pos      = (const float*)d_in[3];
    const float* norm1_w  = (const float*)d_in[4];
    const float* norm1_b  = (const float*)d_in[5];
    const float* w1       = (const float*)d_in[6];
    const float* b1       = (const float*)d_in[7];
    const float* w2       = (const float*)d_in[8];
    const float* b2       = (const float*)d_in[9];
    const float* norm2_w  = (const float*)d_in[10];
    const float* norm2_b  = (const float*)d_in[11];
    const float* fc1_w    = (const float*)d_in[12];
    const float* fc1_b    = (const float*)d_in[13];
    const float* fc2_w    = (const float*)d_in[14];
    const float* fc2_b    = (const float*)d_in[15];
    const float* head_w   = (const float*)d_in[16];
    float* out = (float*)d_out;

    float *pA,*pTT,*pa;
    cudaGetSymbolAddress((void**)&pA,  g_A);
    cudaGetSymbolAddress((void**)&pTT, g_T);
    cudaGetSymbolAddress((void**)&pa,  g_a);

    __half *pxh,*pxl,*th,*tl,*hbh,*hbl,*ah2,*al2,*q2h,*q2l,*sh,*sl;
    __half *pw,*fB,*iB,*f1,*f2,*hw;
    cudaGetSymbolAddress((void**)&pxh, g_pxh);  cudaGetSymbolAddress((void**)&pxl, g_pxl);
    cudaGetSymbolAddress((void**)&th,  g_th);   cudaGetSymbolAddress((void**)&tl,  g_tl);
    cudaGetSymbolAddress((void**)&hbh, g_hbh);  cudaGetSymbolAddress((void**)&hbl, g_hbl);
    cudaGetSymbolAddress((void**)&ah2, g_Ah2);  cudaGetSymbolAddress((void**)&al2, g_Al2);
    cudaGetSymbolAddress((void**)&q2h, g_q2h);  cudaGetSymbolAddress((void**)&q2l, g_q2l);
    cudaGetSymbolAddress((void**)&sh,  g_sh);   cudaGetSymbolAddress((void**)&sl,  g_sl);
    cudaGetSymbolAddress((void**)&pw,  g_pw);
    cudaGetSymbolAddress((void**)&fB,  g_fB);
    cudaGetSymbolAddress((void**)&iB,  g_iB);
    cudaGetSymbolAddress((void**)&f1,  g_f1);
    cudaGetSymbolAddress((void**)&f2,  g_f2);
    cudaGetSymbolAddress((void**)&hw,  g_hw);

    cudaFuncSetAttribute(k_wfwd,  cudaFuncAttributeMaxDynamicSharedMemorySize, 90*128*4 + 180*4);
    cudaFuncSetAttribute(k_hfwd,  cudaFuncAttributeMaxDynamicSharedMemorySize, 2*45*128*4);
    cudaFuncSetAttribute(k_hinv2, cudaFuncAttributeMaxDynamicSharedMemorySize, 2*45*128*4);
    cudaFuncSetAttribute(k_winv2, cudaFuncAttributeMaxDynamicSharedMemorySize, 2*23*128*4);
    cudaFuncSetAttribute(k_mixf,  cudaFuncAttributeMaxDynamicSharedMemorySize, MIXSM);
    cudaFuncSetAttribute(hgemm<0>, cudaFuncAttributeMaxDynamicSharedMemorySize, 2*BUF_B);
    cudaFuncSetAttribute(hgemm<2>, cudaFuncAttributeMaxDynamicSharedMemorySize, 2*BUF_B);
    cudaFuncSetAttribute(hgemm<3>, cudaFuncAttributeMaxDynamicSharedMemorySize, 2*BUF_B);
    cudaFuncSetAttribute(hgemm<4>, cudaFuncAttributeMaxDynamicSharedMemorySize, 2*BUF_B);
    cudaFuncSetAttribute(hgemm<5>, cudaFuncAttributeMaxDynamicSharedMemorySize, 2*BUF_B);
    cudaFuncSetAttribute(hgemm<6>, cudaFuncAttributeMaxDynamicSharedMemorySize, 2*BUF_B);

    // tables + weight converts + ALL-layer block-weight prep (once)
    tabC <<<(EE*EE + 255)/256, 256>>>();
    tab90<<<(GWw*GWw + 255)/256, 256>>>();
    tab45<<<(GHh*GHh + 255)/256, 256>>>();
    conv_kernel<<<(EE*PKK + 255)/256, 256>>>(patch_w, pw, EE*PKK);
    conv_kernel<<<(HDD*EE + 255)/256, 256>>>(head_w, hw, HDD*EE);
    conv_kernel<<<(12*HID*EE + 255)/256, 256>>>(fc1_w, f1, 12*HID*EE);
    conv_kernel<<<(12*EE*HID + 255)/256, 256>>>(fc2_w, f2, 12*EE*HID);
    prep_pm_all<<<(12*BLK + 255)/256, 256>>>(w1, w2);
    prep_ab_all<<<(12*BLK + 127)/128, 128>>>();
    prep_bs_all<<<(12*NBB*BSS + 127)/128, 128>>>(b2);

    const dim3 GB(256);
    const int SMB = 2*BUF_B;

    // patch embed (bias + pos fused; emits LN1 stats for layer 0)
    im2col_kernel<<<(NP*PKK + 255)/256, 256>>>(x);
    hgemm<4><<<dim3(EE/64, MPAD/128), GB, SMB>>>(pxh, pxl, pw, pA, nullptr, nullptr,
                                                 NP, EE, PKK, patch_b, pos, PKK, 0);

    for (int l = 0; l < 12; l++) {
        // ---- AFNO half ----
        k_wfwd<<<dim3(6, 45), 128, 90*128*4 + 180*4>>>(norm1_w + l*EE, norm1_b + l*EE);
        k_hfwd<<<dim3(6, 23), 128, 2*45*128*4>>>();
        // fwd C-stage GEMM: split-K2 (z=0: Q2r x (cos-sin); z=1: Q2i x (cos+sin))
        hgemm<0><<<dim3(EE/64, FPAD/128, 2), GB, SMB>>>(q2h, q2l, fB, pa, nullptr, nullptr,
                                                        NFREQ, EE, EE, nullptr, nullptr,
                                                        2*EE, (long)NFREQ*EE);
        k_mixf<<<dim3(8, 23), 288, MIXSM>>>(b1 + (size_t)l*2*NBB*BSS,
                                            norm1_w + l*EE, norm1_b + l*EE, l*BLK, l*NBB*BSS);
        // inv C-stage GEMM: split-K2 over the 768 c-dimension
        hgemm<0><<<dim3((2*EE)/64, FPAD/128, 2), GB, SMB>>>(sh, sl, iB, pTT, nullptr, nullptr,
                                                            NFREQ, 2*EE, EE/2, nullptr, nullptr,
                                                            EE, (long)NP*EE);
        k_hinv2<<<dim3(6, 23), 128, 2*45*128*4>>>();
        k_winv2<<<dim3(6, 45), 128, 2*23*128*4>>>(norm1_w + l*EE, norm1_b + l*EE);

        // ---- MLP half ----
        ln_h<<<NP, 256>>>(pA, th, tl, norm2_w + l*EE, norm2_b + l*EE);
        hgemm<2><<<dim3(HID/64, MPAD/128), GB, SMB>>>(th, tl, f1 + (size_t)l*HID*EE,
                                                      nullptr, hbh, hbl, NP, HID, EE, fc1_b + l*HID, nullptr,
                                                      EE, 0);
        if (l < 11) {
            hgemm<3><<<dim3(EE/64, MPAD/128), GB, SMB>>>(hbh, hbl, f2 + (size_t)l*EE*HID,
                                                         pA, nullptr, nullptr, NP, EE, HID, fc2_b + l*EE, nullptr,
                                                         HID, 0);
        } else {
            hgemm<5><<<dim3(EE/64, MPAD/128), GB, SMB>>>(hbh, hbl, f2 + (size_t)l*EE*HID,
                                                         pA, ah2, al2, NP, EE, HID, fc2_b + l*EE, nullptr,
                                                         HID, 0);
        }
    }

    // head: GEMM scatters directly into the output image
    hgemm<6><<<dim3(HDD/64, MPAD/128), GB, SMB>>>(ah2, al2, hw, out, nullptr, nullptr,
                                                  NP, HDD, EE, nullptr, nullptr, EE, 0);
}